// round 13
// baseline (speedup 1.0000x reference)
#include <cuda_runtime.h>
#include <cuda_bf16.h>
#include <math.h>
#include <stdint.h>

#define N_NODES 2000
#define NUM_KP 500
#define DESC 256
#define NVK 64
#define VLAD_DIM (DESC*NVK)        // 16384
#define H0D (NUM_KP*2)             // 1000
#define H1D NUM_KP                 // 500
#define NODE_D 128
#define EDGE_D 32
#define N_EDGES 64000
#define E_EXT (N_EDGES + N_NODES)  // 66000
#define DEPTH 3

#define M_PAD 2048
#define N_PAD 1024
#define K2PAD 1024
#define N2PAD 512

typedef unsigned long long u64;

// ---------------- scratch (device globals; no runtime allocation) ----------
__device__ float    g_h1[N_NODES * H1D];
__device__ float    g_x[N_NODES * NODE_D];
__device__ float    g_h[N_NODES * NODE_D];
__device__ float    g_es[N_NODES];
__device__ float    g_ed[N_NODES];
__device__ float    g_ef2[N_EDGES * EDGE_D];
// CSR by destination (rebuilt each launch; edge_index is an input)
__device__ int      g_cnt[N_NODES];
__device__ int      g_ofs[N_NODES + 1];
__device__ int      g_pos[N_NODES];
__device__ int      g_eidx[E_EXT];
// split-bf16 operands (pad regions stay zero: static zero-init, never written)
__device__ __nv_bfloat16 g_Ah[(size_t)M_PAD * VLAD_DIM];
__device__ __nv_bfloat16 g_Al[(size_t)M_PAD * VLAD_DIM];
__device__ __nv_bfloat16 g_Bh[(size_t)N_PAD * VLAD_DIM];
__device__ __nv_bfloat16 g_Bl[(size_t)N_PAD * VLAD_DIM];
__device__ __nv_bfloat16 g_Ah2[(size_t)M_PAD * K2PAD];
__device__ __nv_bfloat16 g_Al2[(size_t)M_PAD * K2PAD];
__device__ __nv_bfloat16 g_Bh2[(size_t)N2PAD * K2PAD];
__device__ __nv_bfloat16 g_Bl2[(size_t)N2PAD * K2PAD];
__device__ __nv_bfloat16 g_cwTh[NVK * DESC];
__device__ __nv_bfloat16 g_cwTl[NVK * DESC];

// ---------------- helpers ---------------------------------------------------
__device__ __forceinline__ uint32_t smem_u32(const void* p) {
    uint32_t a;
    asm("{ .reg .u64 t; cvta.to.shared.u64 t, %1; cvt.u32.u64 %0, t; }" : "=r"(a) : "l"(p));
    return a;
}
__device__ __forceinline__ uint32_t lds32(uint32_t addr) {
    uint32_t v;
    asm volatile("ld.shared.b32 %0, [%1];" : "=r"(v) : "r"(addr));
    return v;
}
__device__ __forceinline__ void ldm_x4(uint32_t* r, uint32_t addr) {
    asm volatile("ldmatrix.sync.aligned.m8n8.x4.shared.b16 {%0,%1,%2,%3}, [%4];"
        : "=r"(r[0]), "=r"(r[1]), "=r"(r[2]), "=r"(r[3]) : "r"(addr));
}
__device__ __forceinline__ void ldm_x4_t(uint32_t* r, uint32_t addr) {
    asm volatile("ldmatrix.sync.aligned.m8n8.x4.trans.shared.b16 {%0,%1,%2,%3}, [%4];"
        : "=r"(r[0]), "=r"(r[1]), "=r"(r[2]), "=r"(r[3]) : "r"(addr));
}
__device__ __forceinline__ void mma16816(float* c, const uint32_t* a, const uint32_t* b) {
    asm volatile(
        "mma.sync.aligned.m16n8k16.row.col.f32.bf16.bf16.f32 "
        "{%0,%1,%2,%3}, {%4,%5,%6,%7}, {%8,%9}, {%0,%1,%2,%3};"
        : "+f"(c[0]), "+f"(c[1]), "+f"(c[2]), "+f"(c[3])
        : "r"(a[0]), "r"(a[1]), "r"(a[2]), "r"(a[3]), "r"(b[0]), "r"(b[1]));
}
#define CP_ASYNC16(dst, src) \
    asm volatile("cp.async.cg.shared.global [%0], [%1], 16;" :: "r"(dst), "l"(src) : "memory")
#define CP_COMMIT()  asm volatile("cp.async.commit_group;" ::: "memory")
#define CP_WAIT0()   asm volatile("cp.async.wait_group 0;" ::: "memory")

__device__ __forceinline__ float sanit(float v) {
    if (!isfinite(v)) v = (v != v) ? 0.f : (v > 0.f ? 3.402823466e38f : -3.402823466e38f);
    return v;
}

// ---------------------------------------------------------------------------
// Prep: cw [256][64] fp32 -> cw^T split-bf16 [64][256]
// ---------------------------------------------------------------------------
__global__ void k_prep_cw(const float* __restrict__ cw)
{
    int i = blockIdx.x * 256 + threadIdx.x;    // 0..16383
    int k = i >> 8, d = i & 255;
    float v = cw[d * 64 + k];
    __nv_bfloat16 h = __float2bfloat16(v);
    g_cwTh[k * 256 + d] = h;
    g_cwTl[k * 256 + d] = __float2bfloat16(v - __bfloat162float(h));
}

// ---------------------------------------------------------------------------
// CSR build (on stream2, hidden under k_nv). edge e's dst: e<N_EDGES ?
// ei[N_EDGES+e] : e-N_EDGES (self loop).
// ---------------------------------------------------------------------------
__global__ void k_csr_zero()
{
    int i = blockIdx.x * blockDim.x + threadIdx.x;
    if (i < N_NODES) g_cnt[i] = 0;
}
__global__ void k_csr_hist(const int* __restrict__ ei)
{
    int e = blockIdx.x * blockDim.x + threadIdx.x;
    if (e >= E_EXT) return;
    int d = (e < N_EDGES) ? ei[N_EDGES + e] : (e - N_EDGES);
    atomicAdd(&g_cnt[d], 1);
}
__global__ void k_csr_scan()     // 1 thread; fully hidden under k_nv
{
    int acc = 0;
    g_ofs[0] = 0;
    for (int i = 0; i < N_NODES; i++) {
        g_pos[i] = acc;
        acc += g_cnt[i];
        g_ofs[i + 1] = acc;
    }
}
__global__ void k_csr_scatter(const int* __restrict__ ei)
{
    int e = blockIdx.x * blockDim.x + threadIdx.x;
    if (e >= E_EXT) return;
    int d = (e < N_EDGES) ? ei[N_EDGES + e] : (e - N_EDGES);
    int p = atomicAdd(&g_pos[d], 1);
    g_eidx[p] = e;
}

// ---------------------------------------------------------------------------
// FUSED NetVLAD (R12, passing).
// ---------------------------------------------------------------------------
#define O_CWH 0
#define O_CWL 33792
#define O_XH  67584
#define O_XL  101376
#define O_LOG 135168
#define O_ACTH 135168
#define O_ACTL 144384
#define O_RED 153600
#define O_ASUM 155648
#define O_REDK 155904
#define O_INVK 156928
#define O_INVT 157184
#define O_XF  157200
#define NV_SMEM 222736

__global__ void __launch_bounds__(256, 1) k_nv(
    const float* __restrict__ feats, const float* __restrict__ cb,
    const float* __restrict__ cw2)
{
    extern __shared__ __align__(16) char sm[];
    int b = blockIdx.x;
    int tid = threadIdx.x, lane = tid & 31, wid = tid >> 5;
    int wm = wid & 3, wn = wid >> 2;
    int lr = lane >> 2, lc = (lane & 3) * 2;

    uint32_t cwh_s = smem_u32(sm + O_CWH), cwl_s = smem_u32(sm + O_CWL);
    uint32_t xh_s  = smem_u32(sm + O_XH),  xl_s  = smem_u32(sm + O_XL);
    uint32_t ah_s  = smem_u32(sm + O_ACTH), al_s = smem_u32(sm + O_ACTL);
    uint32_t xf_s  = smem_u32(sm + O_XF);
    float* logit = (float*)(sm + O_LOG);
    float* red   = (float*)(sm + O_RED);
    float* asums = (float*)(sm + O_ASUM);
    float* redk  = (float*)(sm + O_REDK);
    float* invk  = (float*)(sm + O_INVK);
    float* invts = (float*)(sm + O_INVT);
    const float* xf = (const float*)(sm + O_XF);

    int l7  = lane & 7;
    int s8  = (lane & 8) ? 8 : 0;
    int s16 = (lane & 16) ? 8 : 0;
    int rowA_log = wm * 16 + l7 + s8;
    int rowB_nt  = l7 + s16;
    int rowX_n   = l7 + s16;

    auto issue_xf = [&](int kbi) {
        int n0 = kbi * 64;
#pragma unroll
        for (int p = 0; p < 16; p++) {
            int idx = tid + p * 256;
            int row = idx >> 6;
            int c16 = idx & 63;
            int gn = n0 + row;
            if (gn < NUM_KP) {
                uint32_t d = xf_s + (uint32_t)(row * 1024 + c16 * 16);
                const char* src = (const char*)(feats + ((size_t)b * NUM_KP + gn) * DESC) + c16 * 16;
                CP_ASYNC16(d, src);
            }
        }
        CP_COMMIT();
    };
    auto issue_cw2 = [&]() {
#pragma unroll
        for (int p = 0; p < 16; p++) {
            int idx = tid + p * 256;
            CP_ASYNC16(xf_s + (uint32_t)idx * 16, (const char*)cw2 + (size_t)idx * 16);
        }
        CP_COMMIT();
    };

    for (int i = tid; i < 2048; i += 256) {
        int k = i >> 5, c = i & 31;
        *(uint4*)(sm + O_CWH + k * 528 + c * 16) = ((const uint4*)g_cwTh)[i];
        *(uint4*)(sm + O_CWL + k * 528 + c * 16) = ((const uint4*)g_cwTl)[i];
    }
    issue_xf(0);

    float accv[4][4][4];
#pragma unroll
    for (int mt = 0; mt < 4; mt++)
#pragma unroll
        for (int nt = 0; nt < 4; nt++)
#pragma unroll
            for (int q = 0; q < 4; q++) accv[mt][nt][q] = 0.f;
    float s0 = 0.f, s1 = 0.f;
    float cb0 = cb[lane], cb1 = cb[lane + 32];

    for (int kb = 0; kb < 8; kb++) {
        CP_WAIT0();
        __syncthreads();
        int n0 = kb * 64;
        for (int i = tid; i < 4096; i += 256) {
            int row = i >> 6, c4 = i & 63;
            int gn = n0 + row;
            float4 v = make_float4(0.f, 0.f, 0.f, 0.f);
            if (gn < NUM_KP) v = *(const float4*)(xf + row * 256 + c4 * 4);
            float vv[4] = { sanit(v.x), sanit(v.y), sanit(v.z), sanit(v.w) };
            __nv_bfloat16 hh[4], ll[4];
#pragma unroll
            for (int j = 0; j < 4; j++) {
                hh[j] = __float2bfloat16(vv[j]);
                ll[j] = __float2bfloat16(vv[j] - __bfloat162float(hh[j]));
            }
            char* pxh = sm + O_XH + row * 528 + c4 * 8;
            char* pxl = sm + O_XL + row * 528 + c4 * 8;
            *(__nv_bfloat162*)pxh       = __nv_bfloat162(hh[0], hh[1]);
            *(__nv_bfloat162*)(pxh + 4) = __nv_bfloat162(hh[2], hh[3]);
            *(__nv_bfloat162*)pxl       = __nv_bfloat162(ll[0], ll[1]);
            *(__nv_bfloat162*)(pxl + 4) = __nv_bfloat162(ll[2], ll[3]);
        }
        __syncthreads();
        if (kb + 1 < 8) issue_xf(kb + 1);
        else            issue_cw2();

        // ---- logits GEMM ----
        float acc[4][4];
#pragma unroll
        for (int nt = 0; nt < 4; nt++)
#pragma unroll
            for (int q = 0; q < 4; q++) acc[nt][q] = 0.f;
#pragma unroll
        for (int ks = 0; ks < 16; ks++) {
            int kl = ks * 16;
            uint32_t aoff = (uint32_t)(rowA_log * 528 + (kl + s16) * 2);
            uint32_t a[4], al_[4];
            ldm_x4(a,  xh_s + aoff);
            ldm_x4(al_, xl_s + aoff);
#pragma unroll
            for (int ntp = 0; ntp < 2; ntp++) {
                uint32_t boff = (uint32_t)((wn * 32 + ntp * 16 + rowB_nt) * 528 + (kl + s8) * 2);
                uint32_t bh4[4], bl4[4];
                ldm_x4(bh4, cwh_s + boff);
                ldm_x4(bl4, cwl_s + boff);
                mma16816(acc[2 * ntp],     a,   bh4);
                mma16816(acc[2 * ntp],     a,   bl4);
                mma16816(acc[2 * ntp],     al_, bh4);
                mma16816(acc[2 * ntp + 1], a,   bh4 + 2);
                mma16816(acc[2 * ntp + 1], a,   bl4 + 2);
                mma16816(acc[2 * ntp + 1], al_, bh4 + 2);
            }
        }
#pragma unroll
        for (int nt = 0; nt < 4; nt++)
#pragma unroll
            for (int q = 0; q < 4; q++) {
                int row = wm * 16 + lr + ((q >> 1) * 8);
                int col = wn * 32 + nt * 8 + lc + (q & 1);
                logit[row * 68 + col] = acc[nt][q];
            }
        __syncthreads();

        // ---- softmax ----
        float l0r[8], l1r[8];
#pragma unroll
        for (int rr = 0; rr < 8; rr++) {
            int row = wid * 8 + rr;
            l0r[rr] = logit[row * 68 + lane] + cb0;
            l1r[rr] = logit[row * 68 + lane + 32] + cb1;
        }
        __syncthreads();
#pragma unroll
        for (int rr = 0; rr < 8; rr++) {
            int row = wid * 8 + rr;
            int gn = n0 + row;
            float e0 = __expf(l0r[rr]), e1 = __expf(l1r[rr]);
            float ss = e0 + e1;
#pragma unroll
            for (int off = 16; off; off >>= 1) ss += __shfl_xor_sync(0xFFFFFFFFu, ss, off);
            float inv = 1.f / ss;
            if (gn < NUM_KP) { e0 *= inv; e1 *= inv; s0 += e0; s1 += e1; }
            else             { e0 = 0.f;  e1 = 0.f; }
            __nv_bfloat16 h0 = __float2bfloat16(e0);
            __nv_bfloat16 h1 = __float2bfloat16(e1);
            *(__nv_bfloat16*)(sm + O_ACTH + lane * 144 + row * 2)        = h0;
            *(__nv_bfloat16*)(sm + O_ACTH + (lane + 32) * 144 + row * 2) = h1;
            *(__nv_bfloat16*)(sm + O_ACTL + lane * 144 + row * 2) =
                __float2bfloat16(e0 - __bfloat162float(h0));
            *(__nv_bfloat16*)(sm + O_ACTL + (lane + 32) * 144 + row * 2) =
                __float2bfloat16(e1 - __bfloat162float(h1));
        }
        __syncthreads();

        // ---- vlad GEMM ----
#pragma unroll
        for (int ks = 0; ks < 4; ks++) {
            int kl = ks * 16;
            uint32_t bh4[2][4], bl4[2][4];
#pragma unroll
            for (int ntp = 0; ntp < 2; ntp++) {
                uint32_t boff = (uint32_t)((wn * 32 + ntp * 16 + rowB_nt) * 144 + (kl + s8) * 2);
                ldm_x4(bh4[ntp], ah_s + boff);
                ldm_x4(bl4[ntp], al_s + boff);
            }
#pragma unroll
            for (int mt = 0; mt < 4; mt++) {
                uint32_t aoff = (uint32_t)((kl + rowX_n) * 528 + (wm * 64 + mt * 16 + s8) * 2);
                uint32_t a[4], al2[4];
                ldm_x4_t(a,   xh_s + aoff);
                ldm_x4_t(al2, xl_s + aoff);
#pragma unroll
                for (int ntp = 0; ntp < 2; ntp++) {
                    mma16816(accv[mt][2 * ntp],     a,   bh4[ntp]);
                    mma16816(accv[mt][2 * ntp],     a,   bl4[ntp]);
                    mma16816(accv[mt][2 * ntp],     al2, bh4[ntp]);
                    mma16816(accv[mt][2 * ntp + 1], a,   bh4[ntp] + 2);
                    mma16816(accv[mt][2 * ntp + 1], a,   bl4[ntp] + 2);
                    mma16816(accv[mt][2 * ntp + 1], al2, bh4[ntp] + 2);
                }
            }
        }
    }

    // ---- asum reduce; cw2 already streaming into XF ----
    red[wid * 64 + lane]      = s0;
    red[wid * 64 + lane + 32] = s1;
    CP_WAIT0();
    __syncthreads();
    if (tid < 32) {
        float t0 = 0.f, t1 = 0.f;
#pragma unroll
        for (int w = 0; w < 8; w++) { t0 += red[w * 64 + lane]; t1 += red[w * 64 + lane + 32]; }
        asums[lane] = t0; asums[lane + 32] = t1;
    }
    __syncthreads();
    const float* cw2s = xf;

#pragma unroll
    for (int mt = 0; mt < 4; mt++)
#pragma unroll
        for (int nt = 0; nt < 4; nt++)
#pragma unroll
            for (int q = 0; q < 4; q++) {
                int d = wm * 64 + mt * 16 + lr + ((q >> 1) * 8);
                int k = wn * 32 + nt * 8 + lc + (q & 1);
                accv[mt][nt][q] -= asums[k] * cw2s[d * 64 + k];
            }
#pragma unroll
    for (int nt = 0; nt < 4; nt++) {
        float sq0 = 0.f, sq1 = 0.f;
#pragma unroll
        for (int mt = 0; mt < 4; mt++) {
            sq0 += accv[mt][nt][0] * accv[mt][nt][0] + accv[mt][nt][2] * accv[mt][nt][2];
            sq1 += accv[mt][nt][1] * accv[mt][nt][1] + accv[mt][nt][3] * accv[mt][nt][3];
        }
        sq0 += __shfl_xor_sync(0xFFFFFFFFu, sq0, 4);
        sq0 += __shfl_xor_sync(0xFFFFFFFFu, sq0, 8);
        sq0 += __shfl_xor_sync(0xFFFFFFFFu, sq0, 16);
        sq1 += __shfl_xor_sync(0xFFFFFFFFu, sq1, 4);
        sq1 += __shfl_xor_sync(0xFFFFFFFFu, sq1, 8);
        sq1 += __shfl_xor_sync(0xFFFFFFFFu, sq1, 16);
        if (lr == 0) {
            int k0 = wn * 32 + nt * 8 + lc;
            redk[k0 * 4 + wm]       = sq0;
            redk[(k0 + 1) * 4 + wm] = sq1;
        }
    }
    __syncthreads();
    if (tid < 32) {
        float q0 = redk[lane * 4] + redk[lane * 4 + 1] + redk[lane * 4 + 2] + redk[lane * 4 + 3];
        int l2 = lane + 32;
        float q1 = redk[l2 * 4] + redk[l2 * 4 + 1] + redk[l2 * 4 + 2] + redk[l2 * 4 + 3];
        float i0 = 1.f / (sqrtf(q0) + 1e-12f);
        float i1 = 1.f / (sqrtf(q1) + 1e-12f);
        invk[lane] = i0; invk[l2] = i1;
        float tt = q0 * i0 * i0 + q1 * i1 * i1;
#pragma unroll
        for (int off = 16; off; off >>= 1) tt += __shfl_xor_sync(0xFFFFFFFFu, tt, off);
        if (lane == 0) invts[0] = 1.f / (sqrtf(tt) + 1e-12f);
    }
    __syncthreads();
    float invt = invts[0];

#pragma unroll
    for (int mt = 0; mt < 4; mt++)
#pragma unroll
        for (int nt = 0; nt < 4; nt++)
#pragma unroll
            for (int q = 0; q < 4; q++) {
                int d = wm * 64 + mt * 16 + lr + ((q >> 1) * 8);
                int k = wn * 32 + nt * 8 + lc + (q & 1);
                float val = accv[mt][nt][q] * invk[k] * invt;
                __nv_bfloat16 h = __float2bfloat16(val);
                *(__nv_bfloat16*)(sm + O_XH + (d * 66 + k) * 2) = h;
                *(__nv_bfloat16*)(sm + O_XL + (d * 66 + k) * 2) =
                    __float2bfloat16(val - __bfloat162float(h));
            }
    __syncthreads();
    for (int i = tid; i < 8192; i += 256) {
        int d = i >> 5, kp = i & 31;
        uint32_t vh = lds32(xh_s + (uint32_t)(d * 66 + kp * 2) * 2);
        uint32_t vl = lds32(xl_s + (uint32_t)(d * 66 + kp * 2) * 2);
        size_t go = (size_t)b * VLAD_DIM + d * 64 + kp * 2;
        *(uint32_t*)((char*)g_Ah + go * 2) = vh;
        *(uint32_t*)((char*)g_Al + go * 2) = vl;
    }
}

// ---------------------------------------------------------------------------
// Transpose + split (unchanged).
// ---------------------------------------------------------------------------
__global__ void __launch_bounds__(256) k_cvt_trans(
    const float* __restrict__ src, int ldsrc, int Kreal, int Nreal,
    __nv_bfloat16* __restrict__ dh, __nv_bfloat16* __restrict__ dl, int ldd)
{
    __shared__ float smt[32][33];
    int k0 = blockIdx.x * 32;
    int n0 = blockIdx.y * 32;
    int tx = threadIdx.x & 31;
    int ty = threadIdx.x >> 5;
#pragma unroll
    for (int i = 0; i < 4; i++) {
        int kk = ty + i * 8;
        int n = n0 + tx;
        float v = (k0 + kk < Kreal && n < Nreal) ? src[(size_t)(k0 + kk) * ldsrc + n] : 0.f;
        smt[kk][tx] = v;
    }
    __syncthreads();
#pragma unroll
    for (int i = 0; i < 4; i++) {
        int nn = ty + i * 8;
        float v = smt[tx][nn];
        __nv_bfloat16 h = __float2bfloat16(v);
        __nv_bfloat16 l = __float2bfloat16(v - __bfloat162float(h));
        size_t o = (size_t)(n0 + nn) * ldd + k0 + tx;
        dh[o] = h;
        dl[o] = l;
    }
}

// ---------------------------------------------------------------------------
// Split-bf16 HMMA GEMM (unchanged, passing).
// ---------------------------------------------------------------------------
#define KBLK 64
#define SPITCH 72
#define SPB (SPITCH * 2)
#define TILE_B (128 * SPB)
#define STAGE_B (4 * TILE_B)
#define MMA_SMEM_TOTAL (2 * STAGE_B)

__global__ void __launch_bounds__(256, 1) k_mma(
    const __nv_bfloat16* __restrict__ Ah, const __nv_bfloat16* __restrict__ Al,
    const __nv_bfloat16* __restrict__ Bh, const __nv_bfloat16* __restrict__ Bl,
    int K, float* __restrict__ C, int M, int N,
    const float* __restrict__ bias, int act,
    __nv_bfloat16* __restrict__ Dh, __nv_bfloat16* __restrict__ Dl, int ldd)
{
    extern __shared__ __align__(16) char smem[];
    uint32_t sb = smem_u32(smem);
    int tid = threadIdx.x;
    int wid = tid >> 5, lane = tid & 31;
    int wm = wid & 3;
    int wn = wid >> 2;
    int m0 = blockIdx.y * 128;
    int n0 = blockIdx.x * 128;

    const __nv_bfloat16* srcs[4] = {
        Ah + (size_t)m0 * K, Al + (size_t)m0 * K,
        Bh + (size_t)n0 * K, Bl + (size_t)n0 * K };

    int lrow = tid >> 3;
    int lchk = tid & 7;

    int l7  = lane & 7;
    int s8  = (lane & 8) ? 8 : 0;
    int s16 = (lane & 16) ? 8 : 0;

    float acc[2][8][4];
#pragma unroll
    for (int i = 0; i < 2; i++)
#pragma unroll
        for (int j = 0; j < 8; j++)
#pragma unroll
            for (int q = 0; q < 4; q++) acc[i][j][q] = 0.f;

    auto load_stage = [&](int s, int kb) {
        uint32_t sd = sb + s * STAGE_B;
        size_t kOff = (size_t)kb * KBLK;
#pragma unroll
        for (int v = 0; v < 4; v++) {
            const __nv_bfloat16* g = srcs[v] + kOff;
#pragma unroll
            for (int p = 0; p < 4; p++) {
                int rr = lrow + p * 32;
                uint32_t d = sd + v * TILE_B + rr * SPB + lchk * 16;
                const void* sptr = (const char*)(g + (size_t)rr * K) + lchk * 16;
                CP_ASYNC16(d, sptr);
            }
        }
        CP_COMMIT();
    };

    load_stage(0, 0);

    int lr = lane >> 2;
    int lc = (lane & 3) * 2;
    int nkb = K / KBLK;

    for (int kb = 0; kb < nkb; kb++) {
        int s = kb & 1;
        CP_WAIT0();
        __syncthreads();
        if (kb + 1 < nkb) load_stage(s ^ 1, kb + 1);

        uint32_t sAh = sb + s * STAGE_B;
        uint32_t sAl = sAh + TILE_B;
        uint32_t sBh = sAh + 2 * TILE_B;
        uint32_t sBl = sAh + 3 * TILE_B;

#pragma unroll
        for (int ks = 0; ks < 4; ks++) {
            int kl = ks * 16;
            uint32_t ah4[2][4], al4[2][4];
#pragma unroll
            for (int mt = 0; mt < 2; mt++) {
                uint32_t aoff = (uint32_t)((wm * 32 + mt * 16 + l7 + s8) * SPB + (kl + s16) * 2);
                ldm_x4(ah4[mt], sAh + aoff);
                ldm_x4(al4[mt], sAl + aoff);
            }
            uint32_t bh4[4][4], bl4[4][4];
#pragma unroll
            for (int ntp = 0; ntp < 4; ntp++) {
                uint32_t boff = (uint32_t)((wn * 64 + ntp * 16 + l7 + s16) * SPB + (kl + s8) * 2);
                ldm_x4(bh4[ntp], sBh + boff);
                ldm_x4(bl4[ntp], sBl + boff);
            }
#pragma unroll
            for (int mt = 0; mt < 2; mt++)
#pragma unroll
                for (int ntp = 0; ntp < 4; ntp++) {
                    mma16816(acc[mt][2 * ntp],     ah4[mt], bh4[ntp]);
                    mma16816(acc[mt][2 * ntp],     ah4[mt], bl4[ntp]);
                    mma16816(acc[mt][2 * ntp],     al4[mt], bh4[ntp]);
                    mma16816(acc[mt][2 * ntp + 1], ah4[mt], bh4[ntp] + 2);
                    mma16816(acc[mt][2 * ntp + 1], ah4[mt], bl4[ntp] + 2);
                    mma16816(acc[mt][2 * ntp + 1], al4[mt], bh4[ntp] + 2);
                }
        }
    }

    auto emit = [&](int r, int c, float v) {
        bool in = (r < M && c < N);
        float val = 0.f;
        if (in) {
            val = v + (bias ? bias[c] : 0.f);
            if (act == 1) val = fmaxf(val, 0.f);
            if (C) C[(size_t)r * N + c] = val;
        }
        if (Dh) {
            __nv_bfloat16 h = __float2bfloat16(val);
            Dh[(size_t)r * ldd + c] = h;
            Dl[(size_t)r * ldd + c] = __float2bfloat16(val - __bfloat162float(h));
        }
    };
#pragma unroll
    for (int mt = 0; mt < 2; mt++) {
#pragma unroll
        for (int nt = 0; nt < 8; nt++) {
            int r = m0 + wm * 32 + mt * 16 + lr;
            int c = n0 + wn * 64 + nt * 8 + lc;
            emit(r,     c,     acc[mt][nt][0]);
            emit(r,     c + 1, acc[mt][nt][1]);
            emit(r + 8, c,     acc[mt][nt][2]);
            emit(r + 8, c + 1, acc[mt][nt][3]);
        }
    }
}

// ---------------------------------------------------------------------------
// Small SGEMM (64x64x16) for G3.
// ---------------------------------------------------------------------------
__global__ void __launch_bounds__(256) k_sgemm(
    const float* __restrict__ A, const float* __restrict__ B,
    const float* __restrict__ bias, float* __restrict__ C,
    int M, int N, int K, int act)
{
    __shared__ __align__(16) float As[16][64];
    __shared__ __align__(16) float Bs[16][64];

    int tid = threadIdx.x;
    int tx = tid & 15, ty = tid >> 4;
    int row0 = blockIdx.y * 64, col0 = blockIdx.x * 64;

    float c[4][4];
#pragma unroll
    for (int i = 0; i < 4; i++)
#pragma unroll
        for (int j = 0; j < 4; j++) c[i][j] = 0.f;

    int am = tid >> 2;
    int ak = (tid & 3) * 4;
    int bk = tid >> 4;
    int bn = (tid & 15) * 4;

    for (int k0 = 0; k0 < K; k0 += 16) {
        int arow = row0 + am;
        if (arow < M && k0 + ak + 3 < K) {
            float4 v = *reinterpret_cast<const float4*>(&A[(size_t)arow * K + k0 + ak]);
            As[ak + 0][am] = v.x; As[ak + 1][am] = v.y;
            As[ak + 2][am] = v.z; As[ak + 3][am] = v.w;
        } else {
#pragma unroll
            for (int i = 0; i < 4; i++) {
                int kk = k0 + ak + i;
                As[ak + i][am] = (arow < M && kk < K) ? A[(size_t)arow * K + kk] : 0.f;
            }
        }
        int brow = k0 + bk;
        if (brow < K && col0 + bn + 3 < N) {
            float4 v = *reinterpret_cast<const float4*>(&B[(size_t)brow * N + col0 + bn]);
            *reinterpret_cast<float4*>(&Bs[bk][bn]) = v;
        } else {
#pragma unroll
            for (int i = 0; i < 4; i++) {
                int nn = col0 + bn + i;
                Bs[bk][bn + i] = (brow < K && nn < N) ? B[(size_t)brow * N + nn] : 0.f;
            }
        }
        __syncthreads();
#pragma unroll
        for (int kk = 0; kk < 16; kk++) {
            float4 av = *reinterpret_cast<const float4*>(&As[kk][ty * 4]);
            float4 bv = *reinterpret_cast<const float4*>(&Bs[kk][tx * 4]);
            float a[4] = {av.x, av.y, av.z, av.w};
            float bb[4] = {bv.x, bv.y, bv.z, bv.w};
#pragma unroll
            for (int i = 0; i < 4; i++)
#pragma unroll
                for (int j = 0; j < 4; j++) c[i][j] = fmaf(a[i], bb[j], c[i][j]);
        }
        __syncthreads();
    }

#pragma unroll
    for (int i = 0; i < 4; i++) {
        int r = row0 + ty * 4 + i;
        if (r >= M) continue;
#pragma unroll
        for (int j = 0; j < 4; j++) {
            int cc = col0 + tx * 4 + j;
            if (cc >= N) continue;
            float v = c[i][j];
            if (bias) v += bias[cc];
            if (act == 1) v = fmaxf(v, 0.f);
            C[(size_t)r * N + cc] = v;
        }
    }
}

// ---------------------------------------------------------------------------
// GAT: h = x@W, es/ed per node (unchanged math, no aggr zeroing needed).
// ---------------------------------------------------------------------------
__global__ void __launch_bounds__(128) k_gat_h(
    const float* __restrict__ W, const float* __restrict__ a_s,
    const float* __restrict__ a_d)
{
    int b = blockIdx.x, t = threadIdx.x;
    __shared__ float xsm[NODE_D];
    __shared__ float rs[8];
    xsm[t] = g_x[b * NODE_D + t];
    __syncthreads();
    float acc = 0.f;
#pragma unroll 8
    for (int d = 0; d < NODE_D; d++) acc = fmaf(xsm[d], __ldg(&W[d * NODE_D + t]), acc);
    g_h[b * NODE_D + t] = acc;
    float ps = acc * __ldg(&a_s[t]);
    float pd = acc * __ldg(&a_d[t]);
#pragma unroll
    for (int off = 16; off; off >>= 1) {
        ps += __shfl_xor_sync(0xFFFFFFFFu, ps, off);
        pd += __shfl_xor_sync(0xFFFFFFFFu, pd, off);
    }
    if ((t & 31) == 0) { rs[t >> 5] = ps; rs[4 + (t >> 5)] = pd; }
    __syncthreads();
    if (t == 0) g_es[b] = rs[0] + rs[1] + rs[2] + rs[3];
    if (t == 1) g_ed[b] = rs[4] + rs[5] + rs[6] + rs[7];
}

// ---------------------------------------------------------------------------
// GAT aggregation via CSR: one CTA (128 threads = channels) per dst node.
// Atomic-free: den by block reduction, then chunked weighted accumulation.
// Writes x = elu(aggr/den + bias) directly.
// ---------------------------------------------------------------------------
__global__ void __launch_bounds__(128) k_gat_aggr(
    const int* __restrict__ ei, const float* __restrict__ bias)
{
    __shared__ float exb[128];
    __shared__ int   srcb[128];
    __shared__ float rs[4];
    __shared__ float dens;

    int b = blockIdx.x, t = threadIdx.x;
    int beg = g_ofs[b], end = g_ofs[b + 1];
    float edv = g_ed[b];

    // phase 1: denominator
    float ds = 0.f;
    for (int j = beg + t; j < end; j += 128) {
        int e = g_eidx[j];
        int s = (e < N_EDGES) ? ei[e] : b;
        float v = g_es[s] + edv;
        v = (v > 0.f) ? v : 0.2f * v;
        ds += __expf(v);
    }
#pragma unroll
    for (int off = 16; off; off >>= 1) ds += __shfl_xor_sync(0xFFFFFFFFu, ds, off);
    if ((t & 31) == 0) rs[t >> 5] = ds;
    __syncthreads();
    if (t == 0) dens = rs[0] + rs[1] + rs[2] + rs[3];
    __syncthreads();
    float invden = 1.f / dens;

    // phase 2: chunked accumulation (channel t)
    float acc = 0.f;
    for (int c0 = beg; c0 < end; c0 += 128) {
        int j = c0 + t;
        if (j < end) {
            int e = g_eidx[j];
            int s = (e < N_EDGES) ? ei[e] : b;
            float v = g_es[s] + edv;
            v = (v > 0.f) ? v : 0.2f * v;
            exb[t] = __expf(v);
            srcb[t] = s;
        }
        __syncthreads();
        int lim = end - c0;
        if (lim > 128) lim = 128;
#pragma unroll 4
        for (int jj = 0; jj < lim; jj++)
            acc = fmaf(exb[jj], g_h[srcb[jj] * NODE_D + t], acc);
        __syncthreads();
    }
    float v = acc * invden + __ldg(&bias[t]);
    g_x[b * NODE_D + t] = (v > 0.f) ? v : (__expf(v) - 1.f);
}

// ---------------------------------------------------------------------------
// Edge-attr MLP: 1 -> 8 -> 16 -> 32 (unchanged)
// ---------------------------------------------------------------------------
__global__ void __launch_bounds__(256) k_ef(
    const float* __restrict__ ea,
    const float* __restrict__ w1, const float* __restrict__ b1,
    const float* __restrict__ w2, const float* __restrict__ b2,
    const float* __restrict__ w3, const float* __restrict__ b3)
{
    __shared__ float w1s[8], b1s[8], w2s[128], b2s[16], w3s[512], b3s[32];
    int t = threadIdx.x;
    if (t < 8)   { w1s[t] = w1[t]; b1s[t] = b1[t]; }
    if (t < 128) w2s[t] = w2[t];
    if (t < 16)  b2s[t] = b2[t];
    if (t < 32)  b3s[t] = b3[t];
    for (int i = t; i < 512; i += blockDim.x) w3s[i] = w3[i];
    __syncthreads();
    int e = blockIdx.x * blockDim.x + t;
    if (e >= N_EDGES) return;
    float a = ea[e];
    float t8[8];
#pragma unroll
    for (int j = 0; j < 8; j++) t8[j] = fmaxf(fmaf(a, w1s[j], b1s[j]), 0.f);
    float t16[16];
#pragma unroll
    for (int c = 0; c < 16; c++) {
        float acc = b2s[c];
#pragma unroll
        for (int j = 0; j < 8; j++) acc = fmaf(t8[j], w2s[j * 16 + c], acc);
        t16[c] = fmaxf(acc, 0.f);
    }
#pragma unroll
    for (int c = 0; c < 32; c++) {
        float acc = b3s[c];
#pragma unroll
        for (int j = 0; j < 16; j++) acc = fmaf(t16[j], w3s[j * 32 + c], acc);
        g_ef2[e * EDGE_D + c] = acc;
    }
}

// ---------------------------------------------------------------------------
// Final fused edge classifier (unchanged).
// ---------------------------------------------------------------------------
__global__ void __launch_bounds__(256) k_final(
    const int* __restrict__ ei,
    const float* __restrict__ dp_w, const float* __restrict__ dp_b,
    const float* __restrict__ ec_w1, const float* __restrict__ ec_b1,
    const float* __restrict__ ec_w2, const float* __restrict__ ec_b2,
    float* __restrict__ out)
{
    __shared__ float dpw_s[288 * 32];
    __shared__ float ecw1_s[32 * 16];
    __shared__ float dpb_s[32];
    __shared__ float ecb1_s[16];
    __shared__ float ecw2_s[16];
    __shared__ float vec_s[8][292];
    __shared__ float o32_s[8][32];

    int tid = threadIdx.x;
    for (int i = tid; i < 288 * 32; i += 256) dpw_s[i] = dp_w[i];
    for (int i = tid; i < 512; i += 256) ecw1_s[i] = ec_w1[i];
    if (tid < 32) dpb_s[tid] = dp_b[tid];
    if (tid < 16) { ecb1_s[tid] = ec_b1[tid]; ecw2_s[tid] = ec_w2[tid]; }
    __syncthreads();

    float b2 = __ldg(ec_b2);
    int warp = tid >> 5, lane = tid & 31;
    int gw = blockIdx.x * 8 + warp;
    int nw = gridDim.x * 8;

    for (int e = gw; e < N_EDGES; e += nw) {
        int s = ei[e], d = ei[N_EDGES + e];
        const float* xsp = g_x + s * NODE_D;
        const float* xdp = g_x + d * NODE_D;
#pragma unroll
        for (int i = 0; i < 4; i++) {
            vec_s[warp][lane + 32 * i]       = xsp[lane + 32 * i];
            vec_s[warp][128 + lane + 32 * i] = xdp[lane + 32 * i];
        }
        vec_s[warp][256 + lane] = g_ef2[e * EDGE_D + lane];
        __syncwarp();

        float acc = dpb_s[lane];
#pragma unroll 4
        for (int i = 0; i < 288; i++) acc = fmaf(vec_s[warp][i], dpw_s[i * 32 + lane], acc);
        o32_s[warp][lane] = acc;
        __syncwarp();

        float hh = 0.f;
        if (lane < 16) {
            hh = ecb1_s[lane];
#pragma unroll 4
            for (int j = 0; j < 32; j++) hh = fmaf(o32_s[warp][j], ecw1_s[j * 16 + lane], hh);
            hh = fmaxf(hh, 0.f) * ecw2_s[lane];
        }
#pragma unroll
        for (int off = 8; off; off >>= 1) hh += __shfl_xor_sync(0xFFFFFFFFu, hh, off);
        if (lane == 0) out[e] = 1.f / (1.f + __expf(-(hh + b2)));
        __syncwarp();
    }
}

// ---------------------------------------------------------------------------
extern "C" void kernel_launch(void* const* d_in, const int* in_sizes, int n_in,
                              void* d_out, int out_size)
{
    (void)in_sizes; (void)n_in; (void)out_size;
    const float* node_feats = (const float*)d_in[0];
    const float* edge_attr  = (const float*)d_in[1];
    const float* nv_cw      = (const float*)d_in[2];
    const float* nv_cb      = (const float*)d_in[3];
    const float* nv_cw2     = (const float*)d_in[4];
    const float* nv_hw      = (const float*)d_in[5];
    const float* ne_w1      = (const float*)d_in[6];
    const float* ne_b1      = (const float*)d_in[7];
    const float* ne_w2      = (const float*)d_in[8];
    const float* ne_b2      = (const float*)d_in[9];
    const float* ee_w1      = (const float*)d_in[10];
    const float* ee_b1      = (const float*)d_in[11];
    const float* ee_w2      = (const float*)d_in[12];
    const float* ee_b2      = (const float*)d_in[13];
    const float* ee_w3      = (const float*)d_in[14];
    const float* ee_b3      = (const float*)d_in[15];
    const float* gat_w      = (const float*)d_in[16];
    const float* gat_as     = (const float*)d_in[17];
    const float* gat_ad     = (const float*)d_in[18];
    const float* gat_b      = (const float*)d_in[19];
    const float* dp_w       = (const float*)d_in[20];
    const float* dp_b       = (const float*)d_in[21];
    const float* ec_w1      = (const float*)d_in[22];
    const float* ec_b1      = (const float*)d_in[23];
    const float* ec_w2      = (const float*)d_in[24];
    const float* ec_b2      = (const float*)d_in[25];
    const int*   edge_index = (const int*)d_in[26];
    float* out = (float*)d_out;

    float *p_h1, *p_x;
    __nv_bfloat16 *p_Ah, *p_Al, *p_Bh, *p_Bl, *p_Ah2, *p_Al2, *p_Bh2, *p_Bl2;
    cudaGetSymbolAddress((void**)&p_h1, g_h1);
    cudaGetSymbolAddress((void**)&p_x, g_x);
    cudaGetSymbolAddress((void**)&p_Ah, g_Ah);
    cudaGetSymbolAddress((void**)&p_Al, g_Al);
    cudaGetSymbolAddress((void**)&p_Bh, g_Bh);
    cudaGetSymbolAddress((void**)&p_Bl, g_Bl);
    cudaGetSymbolAddress((void**)&p_Ah2, g_Ah2);
    cudaGetSymbolAddress((void**)&p_Al2, g_Al2);
    cudaGetSymbolAddress((void**)&p_Bh2, g_Bh2);
    cudaGetSymbolAddress((void**)&p_Bl2, g_Bl2);

    static int s_init = 0;
    static cudaStream_t s2;
    static cudaEvent_t ev1, ev2;
    if (!s_init) {
        cudaFuncSetAttribute(k_mma, cudaFuncAttributeMaxDynamicSharedMemorySize, MMA_SMEM_TOTAL);
        cudaFuncSetAttribute(k_nv, cudaFuncAttributeMaxDynamicSharedMemorySize, NV_SMEM);
        cudaStreamCreateWithFlags(&s2, cudaStreamNonBlocking);
        cudaEventCreateWithFlags(&ev1, cudaEventDisableTiming);
        cudaEventCreateWithFlags(&ev2, cudaEventDisableTiming);
        s_init = 1;
    }

    // fork: B conversions + edge MLP + CSR build run concurrently with NetVLAD
    cudaEventRecord(ev1, 0);
    cudaStreamWaitEvent(s2, ev1, 0);
    {
        dim3 g(VLAD_DIM / 32, N_PAD / 32);
        k_cvt_trans<<<g, 256, 0, s2>>>(nv_hw, H0D, VLAD_DIM, H0D, p_Bh, p_Bl, VLAD_DIM);
    }
    {
        dim3 g(K2PAD / 32, N2PAD / 32);
        k_cvt_trans<<<g, 256, 0, s2>>>(ne_w1, H1D, H0D, H1D, p_Bh2, p_Bl2, K2PAD);
    }
    k_ef<<<(N_EDGES + 255) / 256, 256, 0, s2>>>(edge_attr, ee_w1, ee_b1, ee_w2, ee_b2,
                                                ee_w3, ee_b3);
    k_csr_zero<<<(N_NODES + 255) / 256, 256, 0, s2>>>();
    k_csr_hist<<<(E_EXT + 255) / 256, 256, 0, s2>>>(edge_index);
    k_csr_scan<<<1, 1, 0, s2>>>();
    k_csr_scatter<<<(E_EXT + 255) / 256, 256, 0, s2>>>(edge_index);
    cudaEventRecord(ev2, s2);

    // main stream: NetVLAD
    k_prep_cw<<<64, 256>>>(nv_cw);
    k_nv<<<N_NODES, 256, NV_SMEM>>>(node_feats, nv_cb, nv_cw2);

    // join before G1
    cudaStreamWaitEvent(0, ev2, 0);

    // G1 HMMA: h0 = vlad @ hw -> split-bf16 A operand of G2
    {
        dim3 g(N_PAD / 128, M_PAD / 128);
        k_mma<<<g, 256, MMA_SMEM_TOTAL>>>(p_Ah, p_Al, p_Bh, p_Bl, VLAD_DIM,
                                          nullptr, N_NODES, H0D, nullptr, 0,
                                          p_Ah2, p_Al2, K2PAD);
    }
    // G2 HMMA: h1 = relu(h0 @ ne_w1 + b1)
    {
        dim3 g(N2PAD / 128, M_PAD / 128);
        k_mma<<<g, 256, MMA_SMEM_TOTAL>>>(p_Ah2, p_Al2, p_Bh2, p_Bl2, K2PAD,
                                          p_h1, N_NODES, H1D, ne_b1, 1,
                                          nullptr, nullptr, 0);
    }
    // G3: x = h1 @ ne_w2 + b2
    {
        dim3 g((NODE_D + 63) / 64, (N_NODES + 63) / 64);
        k_sgemm<<<g, 256>>>(p_h1, ne_w2, ne_b2, p_x, N_NODES, NODE_D, H1D, 0);
    }

    // 3 GAT layers: 2 kernels each, atomic-free aggregation via CSR
    for (int l = 0; l < DEPTH; l++) {
        k_gat_h<<<N_NODES, 128>>>(gat_w + l * NODE_D * NODE_D,
                                  gat_as + l * NODE_D, gat_ad + l * NODE_D);
        k_gat_aggr<<<N_NODES, 128>>>(edge_index, gat_b + l * NODE_D);
    }

    // fused edge classifier -> out
    k_final<<<256, 256>>>(edge_index, dp_w, dp_b, ec_w1, ec_b1, ec_w2, ec_b2, out);
}

// round 14
// speedup vs baseline: 1.0265x; 1.0265x over previous
#include <cuda_runtime.h>
#include <cuda_bf16.h>
#include <math.h>
#include <stdint.h>

#define N_NODES 2000
#define NUM_KP 500
#define DESC 256
#define NVK 64
#define VLAD_DIM (DESC*NVK)        // 16384
#define H0D (NUM_KP*2)             // 1000
#define H1D NUM_KP                 // 500
#define NODE_D 128
#define EDGE_D 32
#define N_EDGES 64000
#define E_EXT (N_EDGES + N_NODES)  // 66000
#define DEPTH 3

#define M_PAD 2048
#define N_PAD 1024
#define K2PAD 1024
#define N2PAD 512

typedef unsigned long long u64;

// ---------------- scratch (device globals; no runtime allocation) ----------
__device__ float    g_h1[N_NODES * H1D];
__device__ float    g_x[N_NODES * NODE_D];
__device__ float    g_h[N_NODES * NODE_D];
__device__ float    g_es[N_NODES];
__device__ float    g_ed[N_NODES];
__device__ float    g_ex[E_EXT];
__device__ float    g_den[N_NODES];
__device__ float    g_aggr[N_NODES * NODE_D];
__device__ float    g_ef2[N_EDGES * EDGE_D];
// split-bf16 operands (pad regions stay zero: static zero-init, never written)
__device__ __nv_bfloat16 g_Ah[(size_t)M_PAD * VLAD_DIM];
__device__ __nv_bfloat16 g_Al[(size_t)M_PAD * VLAD_DIM];
__device__ __nv_bfloat16 g_Bh[(size_t)N_PAD * VLAD_DIM];
__device__ __nv_bfloat16 g_Bl[(size_t)N_PAD * VLAD_DIM];
__device__ __nv_bfloat16 g_Ah2[(size_t)M_PAD * K2PAD];
__device__ __nv_bfloat16 g_Al2[(size_t)M_PAD * K2PAD];
__device__ __nv_bfloat16 g_Bh2[(size_t)N2PAD * K2PAD];
__device__ __nv_bfloat16 g_Bl2[(size_t)N2PAD * K2PAD];
__device__ __nv_bfloat16 g_cwTh[NVK * DESC];
__device__ __nv_bfloat16 g_cwTl[NVK * DESC];

// ---------------- helpers ---------------------------------------------------
__device__ __forceinline__ uint32_t smem_u32(const void* p) {
    uint32_t a;
    asm("{ .reg .u64 t; cvta.to.shared.u64 t, %1; cvt.u32.u64 %0, t; }" : "=r"(a) : "l"(p));
    return a;
}
__device__ __forceinline__ uint32_t lds32(uint32_t addr) {
    uint32_t v;
    asm volatile("ld.shared.b32 %0, [%1];" : "=r"(v) : "r"(addr));
    return v;
}
__device__ __forceinline__ void ldm_x4(uint32_t* r, uint32_t addr) {
    asm volatile("ldmatrix.sync.aligned.m8n8.x4.shared.b16 {%0,%1,%2,%3}, [%4];"
        : "=r"(r[0]), "=r"(r[1]), "=r"(r[2]), "=r"(r[3]) : "r"(addr));
}
__device__ __forceinline__ void ldm_x4_t(uint32_t* r, uint32_t addr) {
    asm volatile("ldmatrix.sync.aligned.m8n8.x4.trans.shared.b16 {%0,%1,%2,%3}, [%4];"
        : "=r"(r[0]), "=r"(r[1]), "=r"(r[2]), "=r"(r[3]) : "r"(addr));
}
__device__ __forceinline__ void mma16816(float* c, const uint32_t* a, const uint32_t* b) {
    asm volatile(
        "mma.sync.aligned.m16n8k16.row.col.f32.bf16.bf16.f32 "
        "{%0,%1,%2,%3}, {%4,%5,%6,%7}, {%8,%9}, {%0,%1,%2,%3};"
        : "+f"(c[0]), "+f"(c[1]), "+f"(c[2]), "+f"(c[3])
        : "r"(a[0]), "r"(a[1]), "r"(a[2]), "r"(a[3]), "r"(b[0]), "r"(b[1]));
}
// packed bf16x2 convert: result = {hi=a, lo=b} (round-to-nearest, same as
// __float2bfloat16)
__device__ __forceinline__ uint32_t cvt2(float hi, float lo) {
    uint32_t r;
    asm("cvt.rn.bf16x2.f32 %0, %1, %2;" : "=r"(r) : "f"(hi), "f"(lo));
    return r;
}
// bf16 (in low/high half of packed reg) -> f32 exactly
__device__ __forceinline__ float bf_lo_f32(uint32_t p) { return __uint_as_float(p << 16); }
__device__ __forceinline__ float bf_hi_f32(uint32_t p) { return __uint_as_float(p & 0xFFFF0000u); }

#define CP_ASYNC16(dst, src) \
    asm volatile("cp.async.cg.shared.global [%0], [%1], 16;" :: "r"(dst), "l"(src) : "memory")
#define CP_COMMIT()  asm volatile("cp.async.commit_group;" ::: "memory")
#define CP_WAIT0()   asm volatile("cp.async.wait_group 0;" ::: "memory")

__device__ __forceinline__ float sanit(float v) {
    if (!isfinite(v)) v = (v != v) ? 0.f : (v > 0.f ? 3.402823466e38f : -3.402823466e38f);
    return v;
}

// ---------------------------------------------------------------------------
// Prep: cw [256][64] fp32 -> cw^T split-bf16 [64][256]
// ---------------------------------------------------------------------------
__global__ void k_prep_cw(const float* __restrict__ cw)
{
    int i = blockIdx.x * 256 + threadIdx.x;    // 0..16383
    int k = i >> 8, d = i & 255;
    float v = cw[d * 64 + k];
    __nv_bfloat16 h = __float2bfloat16(v);
    g_cwTh[k * 256 + d] = h;
    g_cwTl[k * 256 + d] = __float2bfloat16(v - __bfloat162float(h));
}

// ---------------------------------------------------------------------------
// FUSED NetVLAD (R12 structure, packed-cvt conversion).
// ---------------------------------------------------------------------------
#define O_CWH 0
#define O_CWL 33792
#define O_XH  67584
#define O_XL  101376
#define O_LOG 135168
#define O_ACTH 135168
#define O_ACTL 144384
#define O_RED 153600
#define O_ASUM 155648
#define O_REDK 155904
#define O_INVK 156928
#define O_INVT 157184
#define O_XF  157200
#define NV_SMEM 222736

__global__ void __launch_bounds__(256, 1) k_nv(
    const float* __restrict__ feats, const float* __restrict__ cb,
    const float* __restrict__ cw2)
{
    extern __shared__ __align__(16) char sm[];
    int b = blockIdx.x;
    int tid = threadIdx.x, lane = tid & 31, wid = tid >> 5;
    int wm = wid & 3, wn = wid >> 2;
    int lr = lane >> 2, lc = (lane & 3) * 2;

    uint32_t cwh_s = smem_u32(sm + O_CWH), cwl_s = smem_u32(sm + O_CWL);
    uint32_t xh_s  = smem_u32(sm + O_XH),  xl_s  = smem_u32(sm + O_XL);
    uint32_t ah_s  = smem_u32(sm + O_ACTH), al_s = smem_u32(sm + O_ACTL);
    uint32_t xf_s  = smem_u32(sm + O_XF);
    float* logit = (float*)(sm + O_LOG);
    float* red   = (float*)(sm + O_RED);
    float* asums = (float*)(sm + O_ASUM);
    float* redk  = (float*)(sm + O_REDK);
    float* invk  = (float*)(sm + O_INVK);
    float* invts = (float*)(sm + O_INVT);
    const float* xf = (const float*)(sm + O_XF);

    int l7  = lane & 7;
    int s8  = (lane & 8) ? 8 : 0;
    int s16 = (lane & 16) ? 8 : 0;
    int rowA_log = wm * 16 + l7 + s8;
    int rowB_nt  = l7 + s16;
    int rowX_n   = l7 + s16;

    auto issue_xf = [&](int kbi) {
        int n0 = kbi * 64;
#pragma unroll
        for (int p = 0; p < 16; p++) {
            int idx = tid + p * 256;
            int row = idx >> 6;
            int c16 = idx & 63;
            int gn = n0 + row;
            if (gn < NUM_KP) {
                uint32_t d = xf_s + (uint32_t)(row * 1024 + c16 * 16);
                const char* src = (const char*)(feats + ((size_t)b * NUM_KP + gn) * DESC) + c16 * 16;
                CP_ASYNC16(d, src);
            }
        }
        CP_COMMIT();
    };
    auto issue_cw2 = [&]() {
#pragma unroll
        for (int p = 0; p < 16; p++) {
            int idx = tid + p * 256;
            CP_ASYNC16(xf_s + (uint32_t)idx * 16, (const char*)cw2 + (size_t)idx * 16);
        }
        CP_COMMIT();
    };

    for (int i = tid; i < 2048; i += 256) {
        int k = i >> 5, c = i & 31;
        *(uint4*)(sm + O_CWH + k * 528 + c * 16) = ((const uint4*)g_cwTh)[i];
        *(uint4*)(sm + O_CWL + k * 528 + c * 16) = ((const uint4*)g_cwTl)[i];
    }
    issue_xf(0);

    float accv[4][4][4];
#pragma unroll
    for (int mt = 0; mt < 4; mt++)
#pragma unroll
        for (int nt = 0; nt < 4; nt++)
#pragma unroll
            for (int q = 0; q < 4; q++) accv[mt][nt][q] = 0.f;
    float s0 = 0.f, s1 = 0.f;
    float cb0 = cb[lane], cb1 = cb[lane + 32];

    for (int kb = 0; kb < 8; kb++) {
        CP_WAIT0();
        __syncthreads();
        int n0 = kb * 64;
        // ---- convert staging -> split-bf16 (packed cvt path) ----
        for (int i = tid; i < 4096; i += 256) {
            int row = i >> 6, c4 = i & 63;
            int gn = n0 + row;
            float4 v = make_float4(0.f, 0.f, 0.f, 0.f);
            if (gn < NUM_KP) v = *(const float4*)(xf + row * 256 + c4 * 4);
            float v0 = sanit(v.x), v1 = sanit(v.y), v2 = sanit(v.z), v3 = sanit(v.w);
            uint32_t h01 = cvt2(v1, v0);
            uint32_t h23 = cvt2(v3, v2);
            uint32_t l01 = cvt2(v1 - bf_hi_f32(h01), v0 - bf_lo_f32(h01));
            uint32_t l23 = cvt2(v3 - bf_hi_f32(h23), v2 - bf_lo_f32(h23));
            char* pxh = sm + O_XH + row * 528 + c4 * 8;
            char* pxl = sm + O_XL + row * 528 + c4 * 8;
            *(uint32_t*)pxh       = h01;
            *(uint32_t*)(pxh + 4) = h23;
            *(uint32_t*)pxl       = l01;
            *(uint32_t*)(pxl + 4) = l23;
        }
        __syncthreads();
        if (kb + 1 < 8) issue_xf(kb + 1);
        else            issue_cw2();

        // ---- logits GEMM ----
        float acc[4][4];
#pragma unroll
        for (int nt = 0; nt < 4; nt++)
#pragma unroll
            for (int q = 0; q < 4; q++) acc[nt][q] = 0.f;
#pragma unroll
        for (int ks = 0; ks < 16; ks++) {
            int kl = ks * 16;
            uint32_t aoff = (uint32_t)(rowA_log * 528 + (kl + s16) * 2);
            uint32_t a[4], al_[4];
            ldm_x4(a,  xh_s + aoff);
            ldm_x4(al_, xl_s + aoff);
#pragma unroll
            for (int ntp = 0; ntp < 2; ntp++) {
                uint32_t boff = (uint32_t)((wn * 32 + ntp * 16 + rowB_nt) * 528 + (kl + s8) * 2);
                uint32_t bh4[4], bl4[4];
                ldm_x4(bh4, cwh_s + boff);
                ldm_x4(bl4, cwl_s + boff);
                mma16816(acc[2 * ntp],     a,   bh4);
                mma16816(acc[2 * ntp],     a,   bl4);
                mma16816(acc[2 * ntp],     al_, bh4);
                mma16816(acc[2 * ntp + 1], a,   bh4 + 2);
                mma16816(acc[2 * ntp + 1], a,   bl4 + 2);
                mma16816(acc[2 * ntp + 1], al_, bh4 + 2);
            }
        }
#pragma unroll
        for (int nt = 0; nt < 4; nt++)
#pragma unroll
            for (int q = 0; q < 4; q++) {
                int row = wm * 16 + lr + ((q >> 1) * 8);
                int col = wn * 32 + nt * 8 + lc + (q & 1);
                logit[row * 68 + col] = acc[nt][q];
            }
        __syncthreads();

        // ---- softmax (no max subtraction) ----
        float l0r[8], l1r[8];
#pragma unroll
        for (int rr = 0; rr < 8; rr++) {
            int row = wid * 8 + rr;
            l0r[rr] = logit[row * 68 + lane] + cb0;
            l1r[rr] = logit[row * 68 + lane + 32] + cb1;
        }
        __syncthreads();
#pragma unroll
        for (int rr = 0; rr < 8; rr++) {
            int row = wid * 8 + rr;
            int gn = n0 + row;
            float e0 = __expf(l0r[rr]), e1 = __expf(l1r[rr]);
            float ss = e0 + e1;
#pragma unroll
            for (int off = 16; off; off >>= 1) ss += __shfl_xor_sync(0xFFFFFFFFu, ss, off);
            float inv = 1.f / ss;
            if (gn < NUM_KP) { e0 *= inv; e1 *= inv; s0 += e0; s1 += e1; }
            else             { e0 = 0.f;  e1 = 0.f; }
            __nv_bfloat16 h0 = __float2bfloat16(e0);
            __nv_bfloat16 h1 = __float2bfloat16(e1);
            *(__nv_bfloat16*)(sm + O_ACTH + lane * 144 + row * 2)        = h0;
            *(__nv_bfloat16*)(sm + O_ACTH + (lane + 32) * 144 + row * 2) = h1;
            *(__nv_bfloat16*)(sm + O_ACTL + lane * 144 + row * 2) =
                __float2bfloat16(e0 - __bfloat162float(h0));
            *(__nv_bfloat16*)(sm + O_ACTL + (lane + 32) * 144 + row * 2) =
                __float2bfloat16(e1 - __bfloat162float(h1));
        }
        __syncthreads();

        // ---- vlad GEMM ----
#pragma unroll
        for (int ks = 0; ks < 4; ks++) {
            int kl = ks * 16;
            uint32_t bh4[2][4], bl4[2][4];
#pragma unroll
            for (int ntp = 0; ntp < 2; ntp++) {
                uint32_t boff = (uint32_t)((wn * 32 + ntp * 16 + rowB_nt) * 144 + (kl + s8) * 2);
                ldm_x4(bh4[ntp], ah_s + boff);
                ldm_x4(bl4[ntp], al_s + boff);
            }
#pragma unroll
            for (int mt = 0; mt < 4; mt++) {
                uint32_t aoff = (uint32_t)((kl + rowX_n) * 528 + (wm * 64 + mt * 16 + s8) * 2);
                uint32_t a[4], al2[4];
                ldm_x4_t(a,   xh_s + aoff);
                ldm_x4_t(al2, xl_s + aoff);
#pragma unroll
                for (int ntp = 0; ntp < 2; ntp++) {
                    mma16816(accv[mt][2 * ntp],     a,   bh4[ntp]);
                    mma16816(accv[mt][2 * ntp],     a,   bl4[ntp]);
                    mma16816(accv[mt][2 * ntp],     al2, bh4[ntp]);
                    mma16816(accv[mt][2 * ntp + 1], a,   bh4[ntp] + 2);
                    mma16816(accv[mt][2 * ntp + 1], a,   bl4[ntp] + 2);
                    mma16816(accv[mt][2 * ntp + 1], al2, bh4[ntp] + 2);
                }
            }
        }
    }

    // ---- asum reduce; cw2 already streaming into XF ----
    red[wid * 64 + lane]      = s0;
    red[wid * 64 + lane + 32] = s1;
    CP_WAIT0();
    __syncthreads();
    if (tid < 32) {
        float t0 = 0.f, t1 = 0.f;
#pragma unroll
        for (int w = 0; w < 8; w++) { t0 += red[w * 64 + lane]; t1 += red[w * 64 + lane + 32]; }
        asums[lane] = t0; asums[lane + 32] = t1;
    }
    __syncthreads();
    const float* cw2s = xf;

#pragma unroll
    for (int mt = 0; mt < 4; mt++)
#pragma unroll
        for (int nt = 0; nt < 4; nt++)
#pragma unroll
            for (int q = 0; q < 4; q++) {
                int d = wm * 64 + mt * 16 + lr + ((q >> 1) * 8);
                int k = wn * 32 + nt * 8 + lc + (q & 1);
                accv[mt][nt][q] -= asums[k] * cw2s[d * 64 + k];
            }
#pragma unroll
    for (int nt = 0; nt < 4; nt++) {
        float sq0 = 0.f, sq1 = 0.f;
#pragma unroll
        for (int mt = 0; mt < 4; mt++) {
            sq0 += accv[mt][nt][0] * accv[mt][nt][0] + accv[mt][nt][2] * accv[mt][nt][2];
            sq1 += accv[mt][nt][1] * accv[mt][nt][1] + accv[mt][nt][3] * accv[mt][nt][3];
        }
        sq0 += __shfl_xor_sync(0xFFFFFFFFu, sq0, 4);
        sq0 += __shfl_xor_sync(0xFFFFFFFFu, sq0, 8);
        sq0 += __shfl_xor_sync(0xFFFFFFFFu, sq0, 16);
        sq1 += __shfl_xor_sync(0xFFFFFFFFu, sq1, 4);
        sq1 += __shfl_xor_sync(0xFFFFFFFFu, sq1, 8);
        sq1 += __shfl_xor_sync(0xFFFFFFFFu, sq1, 16);
        if (lr == 0) {
            int k0 = wn * 32 + nt * 8 + lc;
            redk[k0 * 4 + wm]       = sq0;
            redk[(k0 + 1) * 4 + wm] = sq1;
        }
    }
    __syncthreads();
    if (tid < 32) {
        float q0 = redk[lane * 4] + redk[lane * 4 + 1] + redk[lane * 4 + 2] + redk[lane * 4 + 3];
        int l2 = lane + 32;
        float q1 = redk[l2 * 4] + redk[l2 * 4 + 1] + redk[l2 * 4 + 2] + redk[l2 * 4 + 3];
        float i0 = 1.f / (sqrtf(q0) + 1e-12f);
        float i1 = 1.f / (sqrtf(q1) + 1e-12f);
        invk[lane] = i0; invk[l2] = i1;
        float tt = q0 * i0 * i0 + q1 * i1 * i1;
#pragma unroll
        for (int off = 16; off; off >>= 1) tt += __shfl_xor_sync(0xFFFFFFFFu, tt, off);
        if (lane == 0) invts[0] = 1.f / (sqrtf(tt) + 1e-12f);
    }
    __syncthreads();
    float invt = invts[0];

    // ---- split-bf16 staging (packed cvt for the k/k+1 pair) ----
#pragma unroll
    for (int mt = 0; mt < 4; mt++)
#pragma unroll
        for (int nt = 0; nt < 4; nt++)
#pragma unroll
            for (int q = 0; q < 4; q += 2) {         // q and q+1 share (d), k and k+1
                int d = wm * 64 + mt * 16 + lr + ((q >> 1) * 8);
                int k = wn * 32 + nt * 8 + lc;
                float va = accv[mt][nt][q]     * invk[k]     * invt;
                float vb = accv[mt][nt][q + 1] * invk[k + 1] * invt;
                uint32_t h = cvt2(vb, va);
                uint32_t l = cvt2(vb - bf_hi_f32(h), va - bf_lo_f32(h));
                *(uint32_t*)(sm + O_XH + (d * 66 + k) * 2) = h;
                *(uint32_t*)(sm + O_XL + (d * 66 + k) * 2) = l;
            }
    __syncthreads();
    for (int i = tid; i < 8192; i += 256) {
        int d = i >> 5, kp = i & 31;
        uint32_t vh = lds32(xh_s + (uint32_t)(d * 66 + kp * 2) * 2);
        uint32_t vl = lds32(xl_s + (uint32_t)(d * 66 + kp * 2) * 2);
        size_t go = (size_t)b * VLAD_DIM + d * 64 + kp * 2;
        *(uint32_t*)((char*)g_Ah + go * 2) = vh;
        *(uint32_t*)((char*)g_Al + go * 2) = vl;
    }
}

// ---------------------------------------------------------------------------
// Transpose + split (unchanged).
// ---------------------------------------------------------------------------
__global__ void __launch_bounds__(256) k_cvt_trans(
    const float* __restrict__ src, int ldsrc, int Kreal, int Nreal,
    __nv_bfloat16* __restrict__ dh, __nv_bfloat16* __restrict__ dl, int ldd)
{
    __shared__ float smt[32][33];
    int k0 = blockIdx.x * 32;
    int n0 = blockIdx.y * 32;
    int tx = threadIdx.x & 31;
    int ty = threadIdx.x >> 5;
#pragma unroll
    for (int i = 0; i < 4; i++) {
        int kk = ty + i * 8;
        int n = n0 + tx;
        float v = (k0 + kk < Kreal && n < Nreal) ? src[(size_t)(k0 + kk) * ldsrc + n] : 0.f;
        smt[kk][tx] = v;
    }
    __syncthreads();
#pragma unroll
    for (int i = 0; i < 4; i++) {
        int nn = ty + i * 8;
        float v = smt[tx][nn];
        __nv_bfloat16 h = __float2bfloat16(v);
        __nv_bfloat16 l = __float2bfloat16(v - __bfloat162float(h));
        size_t o = (size_t)(n0 + nn) * ldd + k0 + tx;
        dh[o] = h;
        dl[o] = l;
    }
}

// ---------------------------------------------------------------------------
// Split-bf16 HMMA GEMM (unchanged, passing).
// ---------------------------------------------------------------------------
#define KBLK 64
#define SPITCH 72
#define SPB (SPITCH * 2)
#define TILE_B (128 * SPB)
#define STAGE_B (4 * TILE_B)
#define MMA_SMEM_TOTAL (2 * STAGE_B)

__global__ void __launch_bounds__(256, 1) k_mma(
    const __nv_bfloat16* __restrict__ Ah, const __nv_bfloat16* __restrict__ Al,
    const __nv_bfloat16* __restrict__ Bh, const __nv_bfloat16* __restrict__ Bl,
    int K, float* __restrict__ C, int M, int N,
    const float* __restrict__ bias, int act,
    __nv_bfloat16* __restrict__ Dh, __nv_bfloat16* __restrict__ Dl, int ldd)
{
    extern __shared__ __align__(16) char smem[];
    uint32_t sb = smem_u32(smem);
    int tid = threadIdx.x;
    int wid = tid >> 5, lane = tid & 31;
    int wm = wid & 3;
    int wn = wid >> 2;
    int m0 = blockIdx.y * 128;
    int n0 = blockIdx.x * 128;

    const __nv_bfloat16* srcs[4] = {
        Ah + (size_t)m0 * K, Al + (size_t)m0 * K,
        Bh + (size_t)n0 * K, Bl + (size_t)n0 * K };

    int lrow = tid >> 3;
    int lchk = tid & 7;

    int l7  = lane & 7;
    int s8  = (lane & 8) ? 8 : 0;
    int s16 = (lane & 16) ? 8 : 0;

    float acc[2][8][4];
#pragma unroll
    for (int i = 0; i < 2; i++)
#pragma unroll
        for (int j = 0; j < 8; j++)
#pragma unroll
            for (int q = 0; q < 4; q++) acc[i][j][q] = 0.f;

    auto load_stage = [&](int s, int kb) {
        uint32_t sd = sb + s * STAGE_B;
        size_t kOff = (size_t)kb * KBLK;
#pragma unroll
        for (int v = 0; v < 4; v++) {
            const __nv_bfloat16* g = srcs[v] + kOff;
#pragma unroll
            for (int p = 0; p < 4; p++) {
                int rr = lrow + p * 32;
                uint32_t d = sd + v * TILE_B + rr * SPB + lchk * 16;
                const void* sptr = (const char*)(g + (size_t)rr * K) + lchk * 16;
                CP_ASYNC16(d, sptr);
            }
        }
        CP_COMMIT();
    };

    load_stage(0, 0);

    int lr = lane >> 2;
    int lc = (lane & 3) * 2;
    int nkb = K / KBLK;

    for (int kb = 0; kb < nkb; kb++) {
        int s = kb & 1;
        CP_WAIT0();
        __syncthreads();
        if (kb + 1 < nkb) load_stage(s ^ 1, kb + 1);

        uint32_t sAh = sb + s * STAGE_B;
        uint32_t sAl = sAh + TILE_B;
        uint32_t sBh = sAh + 2 * TILE_B;
        uint32_t sBl = sAh + 3 * TILE_B;

#pragma unroll
        for (int ks = 0; ks < 4; ks++) {
            int kl = ks * 16;
            uint32_t ah4[2][4], al4[2][4];
#pragma unroll
            for (int mt = 0; mt < 2; mt++) {
                uint32_t aoff = (uint32_t)((wm * 32 + mt * 16 + l7 + s8) * SPB + (kl + s16) * 2);
                ldm_x4(ah4[mt], sAh + aoff);
                ldm_x4(al4[mt], sAl + aoff);
            }
            uint32_t bh4[4][4], bl4[4][4];
#pragma unroll
            for (int ntp = 0; ntp < 4; ntp++) {
                uint32_t boff = (uint32_t)((wn * 64 + ntp * 16 + l7 + s16) * SPB + (kl + s8) * 2);
                ldm_x4(bh4[ntp], sBh + boff);
                ldm_x4(bl4[ntp], sBl + boff);
            }
#pragma unroll
            for (int mt = 0; mt < 2; mt++)
#pragma unroll
                for (int ntp = 0; ntp < 4; ntp++) {
                    mma16816(acc[mt][2 * ntp],     ah4[mt], bh4[ntp]);
                    mma16816(acc[mt][2 * ntp],     ah4[mt], bl4[ntp]);
                    mma16816(acc[mt][2 * ntp],     al4[mt], bh4[ntp]);
                    mma16816(acc[mt][2 * ntp + 1], ah4[mt], bh4[ntp] + 2);
                    mma16816(acc[mt][2 * ntp + 1], ah4[mt], bl4[ntp] + 2);
                    mma16816(acc[mt][2 * ntp + 1], al4[mt], bh4[ntp] + 2);
                }
        }
    }

    auto emit = [&](int r, int c, float v) {
        bool in = (r < M && c < N);
        float val = 0.f;
        if (in) {
            val = v + (bias ? bias[c] : 0.f);
            if (act == 1) val = fmaxf(val, 0.f);
            if (C) C[(size_t)r * N + c] = val;
        }
        if (Dh) {
            __nv_bfloat16 h = __float2bfloat16(val);
            Dh[(size_t)r * ldd + c] = h;
            Dl[(size_t)r * ldd + c] = __float2bfloat16(val - __bfloat162float(h));
        }
    };
#pragma unroll
    for (int mt = 0; mt < 2; mt++) {
#pragma unroll
        for (int nt = 0; nt < 8; nt++) {
            int r = m0 + wm * 32 + mt * 16 + lr;
            int c = n0 + wn * 64 + nt * 8 + lc;
            emit(r,     c,     acc[mt][nt][0]);
            emit(r,     c + 1, acc[mt][nt][1]);
            emit(r + 8, c,     acc[mt][nt][2]);
            emit(r + 8, c + 1, acc[mt][nt][3]);
        }
    }
}

// ---------------------------------------------------------------------------
// Small SGEMM (64x64x16) for G3.
// ---------------------------------------------------------------------------
__global__ void __launch_bounds__(256) k_sgemm(
    const float* __restrict__ A, const float* __restrict__ B,
    const float* __restrict__ bias, float* __restrict__ C,
    int M, int N, int K, int act)
{
    __shared__ __align__(16) float As[16][64];
    __shared__ __align__(16) float Bs[16][64];

    int tid = threadIdx.x;
    int tx = tid & 15, ty = tid >> 4;
    int row0 = blockIdx.y * 64, col0 = blockIdx.x * 64;

    float c[4][4];
#pragma unroll
    for (int i = 0; i < 4; i++)
#pragma unroll
        for (int j = 0; j < 4; j++) c[i][j] = 0.f;

    int am = tid >> 2;
    int ak = (tid & 3) * 4;
    int bk = tid >> 4;
    int bn = (tid & 15) * 4;

    for (int k0 = 0; k0 < K; k0 += 16) {
        int arow = row0 + am;
        if (arow < M && k0 + ak + 3 < K) {
            float4 v = *reinterpret_cast<const float4*>(&A[(size_t)arow * K + k0 + ak]);
            As[ak + 0][am] = v.x; As[ak + 1][am] = v.y;
            As[ak + 2][am] = v.z; As[ak + 3][am] = v.w;
        } else {
#pragma unroll
            for (int i = 0; i < 4; i++) {
                int kk = k0 + ak + i;
                As[ak + i][am] = (arow < M && kk < K) ? A[(size_t)arow * K + kk] : 0.f;
            }
        }
        int brow = k0 + bk;
        if (brow < K && col0 + bn + 3 < N) {
            float4 v = *reinterpret_cast<const float4*>(&B[(size_t)brow * N + col0 + bn]);
            *reinterpret_cast<float4*>(&Bs[bk][bn]) = v;
        } else {
#pragma unroll
            for (int i = 0; i < 4; i++) {
                int nn = col0 + bn + i;
                Bs[bk][bn + i] = (brow < K && nn < N) ? B[(size_t)brow * N + nn] : 0.f;
            }
        }
        __syncthreads();
#pragma unroll
        for (int kk = 0; kk < 16; kk++) {
            float4 av = *reinterpret_cast<const float4*>(&As[kk][ty * 4]);
            float4 bv = *reinterpret_cast<const float4*>(&Bs[kk][tx * 4]);
            float a[4] = {av.x, av.y, av.z, av.w};
            float bb[4] = {bv.x, bv.y, bv.z, bv.w};
#pragma unroll
            for (int i = 0; i < 4; i++)
#pragma unroll
                for (int j = 0; j < 4; j++) c[i][j] = fmaf(a[i], bb[j], c[i][j]);
        }
        __syncthreads();
    }

#pragma unroll
    for (int i = 0; i < 4; i++) {
        int r = row0 + ty * 4 + i;
        if (r >= M) continue;
#pragma unroll
        for (int j = 0; j < 4; j++) {
            int cc = col0 + tx * 4 + j;
            if (cc >= N) continue;
            float v = c[i][j];
            if (bias) v += bias[cc];
            if (act == 1) v = fmaxf(v, 0.f);
            C[(size_t)r * N + cc] = v;
        }
    }
}

// ---------------------------------------------------------------------------
// GAT kernels (R12-measured path: fused init + atomics).
// ---------------------------------------------------------------------------
__global__ void __launch_bounds__(128) k_gat_h(
    const float* __restrict__ W, const float* __restrict__ a_s,
    const float* __restrict__ a_d)
{
    int b = blockIdx.x, t = threadIdx.x;
    __shared__ float xsm[NODE_D];
    __shared__ float rs[8];
    xsm[t] = g_x[b * NODE_D + t];
    g_aggr[b * NODE_D + t] = 0.f;
    if (t == 0) g_den[b] = 0.f;
    __syncthreads();
    float acc = 0.f;
#pragma unroll 8
    for (int d = 0; d < NODE_D; d++) acc = fmaf(xsm[d], __ldg(&W[d * NODE_D + t]), acc);
    g_h[b * NODE_D + t] = acc;
    float ps = acc * __ldg(&a_s[t]);
    float pd = acc * __ldg(&a_d[t]);
#pragma unroll
    for (int off = 16; off; off >>= 1) {
        ps += __shfl_xor_sync(0xFFFFFFFFu, ps, off);
        pd += __shfl_xor_sync(0xFFFFFFFFu, pd, off);
    }
    if ((t & 31) == 0) { rs[t >> 5] = ps; rs[4 + (t >> 5)] = pd; }
    __syncthreads();
    if (t == 0) g_es[b] = rs[0] + rs[1] + rs[2] + rs[3];
    if (t == 1) g_ed[b] = rs[4] + rs[5] + rs[6] + rs[7];
}

__global__ void k_edge12(const int* __restrict__ ei)
{
    int e = blockIdx.x * blockDim.x + threadIdx.x;
    if (e >= E_EXT) return;
    int s, d;
    if (e < N_EDGES) { s = ei[e]; d = ei[N_EDGES + e]; }
    else { s = e - N_EDGES; d = s; }
    float v = g_es[s] + g_ed[d];
    v = (v > 0.f) ? v : 0.2f * v;
    float ex = __expf(v);
    g_ex[e] = ex;
    atomicAdd(&g_den[d], ex);
}

__global__ void k_edge3(const int* __restrict__ ei)
{
    int gt = blockIdx.x * blockDim.x + threadIdx.x;
    int w = gt >> 5, lane = gt & 31;
    if (w >= E_EXT) return;
    int s, d;
    if (w < N_EDGES) { s = ei[w]; d = ei[N_EDGES + w]; }
    else { s = w - N_EDGES; d = s; }
    float alpha = g_ex[w] / g_den[d];
#pragma unroll
    for (int i = 0; i < 4; i++) {
        int c = lane + 32 * i;
        atomicAdd(&g_aggr[d * NODE_D + c], g_h[s * NODE_D + c] * alpha);
    }
}

__global__ void k_gat_fin(const float* __restrict__ b)
{
    int i = blockIdx.x * blockDim.x + threadIdx.x;
    if (i >= N_NODES * NODE_D) return;
    float v = g_aggr[i] + __ldg(&b[i & (NODE_D - 1)]);
    g_x[i] = (v > 0.f) ? v : (__expf(v) - 1.f);
}

// ---------------------------------------------------------------------------
// Edge-attr MLP: 1 -> 8 -> 16 -> 32 (unchanged)
// ---------------------------------------------------------------------------
__global__ void __launch_bounds__(256) k_ef(
    const float* __restrict__ ea,
    const float* __restrict__ w1, const float* __restrict__ b1,
    const float* __restrict__ w2, const float* __restrict__ b2,
    const float* __restrict__ w3, const float* __restrict__ b3)
{
    __shared__ float w1s[8], b1s[8], w2s[128], b2s[16], w3s[512], b3s[32];
    int t = threadIdx.x;
    if (t < 8)   { w1s[t] = w1[t]; b1s[t] = b1[t]; }
    if (t < 128) w2s[t] = w2[t];
    if (t < 16)  b2s[t] = b2[t];
    if (t < 32)  b3s[t] = b3[t];
    for (int i = t; i < 512; i += blockDim.x) w3s[i] = w3[i];
    __syncthreads();
    int e = blockIdx.x * blockDim.x + t;
    if (e >= N_EDGES) return;
    float a = ea[e];
    float t8[8];
#pragma unroll
    for (int j = 0; j < 8; j++) t8[j] = fmaxf(fmaf(a, w1s[j], b1s[j]), 0.f);
    float t16[16];
#pragma unroll
    for (int c = 0; c < 16; c++) {
        float acc = b2s[c];
#pragma unroll
        for (int j = 0; j < 8; j++) acc = fmaf(t8[j], w2s[j * 16 + c], acc);
        t16[c] = fmaxf(acc, 0.f);
    }
#pragma unroll
    for (int c = 0; c < 32; c++) {
        float acc = b3s[c];
#pragma unroll
        for (int j = 0; j < 16; j++) acc = fmaf(t16[j], w3s[j * 32 + c], acc);
        g_ef2[e * EDGE_D + c] = acc;
    }
}

// ---------------------------------------------------------------------------
// Final fused edge classifier (unchanged).
// ---------------------------------------------------------------------------
__global__ void __launch_bounds__(256) k_final(
    const int* __restrict__ ei,
    const float* __restrict__ dp_w, const float* __restrict__ dp_b,
    const float* __restrict__ ec_w1, const float* __restrict__ ec_b1,
    const float* __restrict__ ec_w2, const float* __restrict__ ec_b2,
    float* __restrict__ out)
{
    __shared__ float dpw_s[288 * 32];
    __shared__ float ecw1_s[32 * 16];
    __shared__ float dpb_s[32];
    __shared__ float ecb1_s[16];
    __shared__ float ecw2_s[16];
    __shared__ float vec_s[8][292];
    __shared__ float o32_s[8][32];

    int tid = threadIdx.x;
    for (int i = tid; i < 288 * 32; i += 256) dpw_s[i] = dp_w[i];
    for (int i = tid; i < 512; i += 256) ecw1_s[i] = ec_w1[i];
    if (tid < 32) dpb_s[tid] = dp_b[tid];
    if (tid < 16) { ecb1_s[tid] = ec_b1[tid]; ecw2_s[tid] = ec_w2[tid]; }
    __syncthreads();

    float b2 = __ldg(ec_b2);
    int warp = tid >> 5, lane = tid & 31;
    int gw = blockIdx.x * 8 + warp;
    int nw = gridDim.x * 8;

    for (int e = gw; e < N_EDGES; e += nw) {
        int s = ei[e], d = ei[N_EDGES + e];
        const float* xsp = g_x + s * NODE_D;
        const float* xdp = g_x + d * NODE_D;
#pragma unroll
        for (int i = 0; i < 4; i++) {
            vec_s[warp][lane + 32 * i]       = xsp[lane + 32 * i];
            vec_s[warp][128 + lane + 32 * i] = xdp[lane + 32 * i];
        }
        vec_s[warp][256 + lane] = g_ef2[e * EDGE_D + lane];
        __syncwarp();

        float acc = dpb_s[lane];
#pragma unroll 4
        for (int i = 0; i < 288; i++) acc = fmaf(vec_s[warp][i], dpw_s[i * 32 + lane], acc);
        o32_s[warp][lane] = acc;
        __syncwarp();

        float hh = 0.f;
        if (lane < 16) {
            hh = ecb1_s[lane];
#pragma unroll 4
            for (int j = 0; j < 32; j++) hh = fmaf(o32_s[warp][j], ecw1_s[j * 16 + lane], hh);
            hh = fmaxf(hh, 0.f) * ecw2_s[lane];
        }
#pragma unroll
        for (int off = 8; off; off >>= 1) hh += __shfl_xor_sync(0xFFFFFFFFu, hh, off);
        if (lane == 0) out[e] = 1.f / (1.f + __expf(-(hh + b2)));
        __syncwarp();
    }
}

// ---------------------------------------------------------------------------
extern "C" void kernel_launch(void* const* d_in, const int* in_sizes, int n_in,
                              void* d_out, int out_size)
{
    (void)in_sizes; (void)n_in; (void)out_size;
    const float* node_feats = (const float*)d_in[0];
    const float* edge_attr  = (const float*)d_in[1];
    const float* nv_cw      = (const float*)d_in[2];
    const float* nv_cb      = (const float*)d_in[3];
    const float* nv_cw2     = (const float*)d_in[4];
    const float* nv_hw      = (const float*)d_in[5];
    const float* ne_w1      = (const float*)d_in[6];
    const float* ne_b1      = (const float*)d_in[7];
    const float* ne_w2      = (const float*)d_in[8];
    const float* ne_b2      = (const float*)d_in[9];
    const float* ee_w1      = (const float*)d_in[10];
    const float* ee_b1      = (const float*)d_in[11];
    const float* ee_w2      = (const float*)d_in[12];
    const float* ee_b2      = (const float*)d_in[13];
    const float* ee_w3      = (const float*)d_in[14];
    const float* ee_b3      = (const float*)d_in[15];
    const float* gat_w      = (const float*)d_in[16];
    const float* gat_as     = (const float*)d_in[17];
    const float* gat_ad     = (const float*)d_in[18];
    const float* gat_b      = (const float*)d_in[19];
    const float* dp_w       = (const float*)d_in[20];
    const float* dp_b       = (const float*)d_in[21];
    const float* ec_w1      = (const float*)d_in[22];
    const float* ec_b1      = (const float*)d_in[23];
    const float* ec_w2      = (const float*)d_in[24];
    const float* ec_b2      = (const float*)d_in[25];
    const int*   edge_index = (const int*)d_in[26];
    float* out = (float*)d_out;

    float *p_h1, *p_x;
    __nv_bfloat16 *p_Ah, *p_Al, *p_Bh, *p_Bl, *p_Ah2, *p_Al2, *p_Bh2, *p_Bl2;
    cudaGetSymbolAddress((void**)&p_h1, g_h1);
    cudaGetSymbolAddress((void**)&p_x, g_x);
    cudaGetSymbolAddress((void**)&p_Ah, g_Ah);
    cudaGetSymbolAddress((void**)&p_Al, g_Al);
    cudaGetSymbolAddress((void**)&p_Bh, g_Bh);
    cudaGetSymbolAddress((void**)&p_Bl, g_Bl);
    cudaGetSymbolAddress((void**)&p_Ah2, g_Ah2);
    cudaGetSymbolAddress((void**)&p_Al2, g_Al2);
    cudaGetSymbolAddress((void**)&p_Bh2, g_Bh2);
    cudaGetSymbolAddress((void**)&p_Bl2, g_Bl2);

    static int s_init = 0;
    static cudaStream_t s2;
    static cudaEvent_t ev1, ev2;
    if (!s_init) {
        cudaFuncSetAttribute(k_mma, cudaFuncAttributeMaxDynamicSharedMemorySize, MMA_SMEM_TOTAL);
        cudaFuncSetAttribute(k_nv, cudaFuncAttributeMaxDynamicSharedMemorySize, NV_SMEM);
        cudaStreamCreateWithFlags(&s2, cudaStreamNonBlocking);
        cudaEventCreateWithFlags(&ev1, cudaEventDisableTiming);
        cudaEventCreateWithFlags(&ev2, cudaEventDisableTiming);
        s_init = 1;
    }

    // fork: B conversions + edge MLP run concurrently with NetVLAD
    cudaEventRecord(ev1, 0);
    cudaStreamWaitEvent(s2, ev1, 0);
    {
        dim3 g(VLAD_DIM / 32, N_PAD / 32);
        k_cvt_trans<<<g, 256, 0, s2>>>(nv_hw, H0D, VLAD_DIM, H0D, p_Bh, p_Bl, VLAD_DIM);
    }
    {
        dim3 g(K2PAD / 32, N2PAD / 32);
        k_cvt_trans<<<g, 256, 0, s2>>>(ne_w1, H1D, H0D, H1D, p_Bh2, p_Bl2, K2PAD);
    }
    k_ef<<<(N_EDGES + 255) / 256, 256, 0, s2>>>(edge_attr, ee_w1, ee_b1, ee_w2, ee_b2,
                                                ee_w3, ee_b3);
    cudaEventRecord(ev2, s2);

    // main stream: NetVLAD
    k_prep_cw<<<64, 256>>>(nv_cw);
    k_nv<<<N_NODES, 256, NV_SMEM>>>(node_feats, nv_cb, nv_cw2);

    // join before G1
    cudaStreamWaitEvent(0, ev2, 0);

    // G1 HMMA: h0 = vlad @ hw -> split-bf16 A operand of G2
    {
        dim3 g(N_PAD / 128, M_PAD / 128);
        k_mma<<<g, 256, MMA_SMEM_TOTAL>>>(p_Ah, p_Al, p_Bh, p_Bl, VLAD_DIM,
                                          nullptr, N_NODES, H0D, nullptr, 0,
                                          p_Ah2, p_Al2, K2PAD);
    }
    // G2 HMMA: h1 = relu(h0 @ ne_w1 + b1)
    {
        dim3 g(N2PAD / 128, M_PAD / 128);
        k_mma<<<g, 256, MMA_SMEM_TOTAL>>>(p_Ah2, p_Al2, p_Bh2, p_Bl2, K2PAD,
                                          p_h1, N_NODES, H1D, ne_b1, 1,
                                          nullptr, nullptr, 0);
    }
    // G3: x = h1 @ ne_w2 + b2
    {
        dim3 g((NODE_D + 63) / 64, (N_NODES + 63) / 64);
        k_sgemm<<<g, 256>>>(p_h1, ne_w2, ne_b2, p_x, N_NODES, NODE_D, H1D, 0);
    }

    // 3 GAT layers (R12 path: fused init + atomic aggregation)
    for (int l = 0; l < DEPTH; l++) {
        k_gat_h<<<N_NODES, 128>>>(gat_w + l * NODE_D * NODE_D,
                                  gat_as + l * NODE_D, gat_ad + l * NODE_D);
        k_edge12<<<(E_EXT + 255) / 256, 256>>>(edge_index);
        k_edge3<<<((E_EXT * 32) + 255) / 256, 256>>>(edge_index);
        k_gat_fin<<<(N_NODES * NODE_D + 255) / 256, 256>>>(gat_b + l * NODE_D);
    }

    // fused edge classifier -> out
    k_final<<<256, 256>>>(edge_index, dp_w, dp_b, ec_w1, ec_b1, ec_w2, ec_b2, out);
}

// round 15
// speedup vs baseline: 1.0279x; 1.0014x over previous
#include <cuda_runtime.h>
#include <cuda_bf16.h>
#include <math.h>
#include <stdint.h>

#define N_NODES 2000
#define NUM_KP 500
#define DESC 256
#define NVK 64
#define VLAD_DIM (DESC*NVK)        // 16384
#define H0D (NUM_KP*2)             // 1000
#define H1D NUM_KP                 // 500
#define NODE_D 128
#define EDGE_D 32
#define N_EDGES 64000
#define E_EXT (N_EDGES + N_NODES)  // 66000
#define DEPTH 3

#define M_PAD 2048
#define N_PAD 1024
#define K2PAD 1024
#define N2PAD 512
#define K3PAD 512
#define N3PAD 128

typedef unsigned long long u64;

// ---------------- scratch (device globals; no runtime allocation) ----------
__device__ float    g_x[N_NODES * NODE_D];
__device__ float    g_h[N_NODES * NODE_D];
__device__ float    g_es[N_NODES];
__device__ float    g_ed[N_NODES];
__device__ float    g_ex[E_EXT];
__device__ float    g_den[N_NODES];
__device__ float    g_aggr[N_NODES * NODE_D];
__device__ float    g_ef2[N_EDGES * EDGE_D];
// split-bf16 operands (pad regions stay zero: static zero-init, never written)
__device__ __nv_bfloat16 g_Ah[(size_t)M_PAD * VLAD_DIM];
__device__ __nv_bfloat16 g_Al[(size_t)M_PAD * VLAD_DIM];
__device__ __nv_bfloat16 g_Bh[(size_t)N_PAD * VLAD_DIM];
__device__ __nv_bfloat16 g_Bl[(size_t)N_PAD * VLAD_DIM];
__device__ __nv_bfloat16 g_Ah2[(size_t)M_PAD * K2PAD];
__device__ __nv_bfloat16 g_Al2[(size_t)M_PAD * K2PAD];
__device__ __nv_bfloat16 g_Bh2[(size_t)N2PAD * K2PAD];
__device__ __nv_bfloat16 g_Bl2[(size_t)N2PAD * K2PAD];
__device__ __nv_bfloat16 g_Ah3[(size_t)M_PAD * K3PAD];
__device__ __nv_bfloat16 g_Al3[(size_t)M_PAD * K3PAD];
__device__ __nv_bfloat16 g_Bh3[(size_t)N3PAD * K3PAD];
__device__ __nv_bfloat16 g_Bl3[(size_t)N3PAD * K3PAD];
__device__ __nv_bfloat16 g_cwTh[NVK * DESC];
__device__ __nv_bfloat16 g_cwTl[NVK * DESC];

// ---------------- helpers ---------------------------------------------------
__device__ __forceinline__ uint32_t smem_u32(const void* p) {
    uint32_t a;
    asm("{ .reg .u64 t; cvta.to.shared.u64 t, %1; cvt.u32.u64 %0, t; }" : "=r"(a) : "l"(p));
    return a;
}
__device__ __forceinline__ uint32_t lds32(uint32_t addr) {
    uint32_t v;
    asm volatile("ld.shared.b32 %0, [%1];" : "=r"(v) : "r"(addr));
    return v;
}
__device__ __forceinline__ void ldm_x4(uint32_t* r, uint32_t addr) {
    asm volatile("ldmatrix.sync.aligned.m8n8.x4.shared.b16 {%0,%1,%2,%3}, [%4];"
        : "=r"(r[0]), "=r"(r[1]), "=r"(r[2]), "=r"(r[3]) : "r"(addr));
}
__device__ __forceinline__ void ldm_x4_t(uint32_t* r, uint32_t addr) {
    asm volatile("ldmatrix.sync.aligned.m8n8.x4.trans.shared.b16 {%0,%1,%2,%3}, [%4];"
        : "=r"(r[0]), "=r"(r[1]), "=r"(r[2]), "=r"(r[3]) : "r"(addr));
}
__device__ __forceinline__ void mma16816(float* c, const uint32_t* a, const uint32_t* b) {
    asm volatile(
        "mma.sync.aligned.m16n8k16.row.col.f32.bf16.bf16.f32 "
        "{%0,%1,%2,%3}, {%4,%5,%6,%7}, {%8,%9}, {%0,%1,%2,%3};"
        : "+f"(c[0]), "+f"(c[1]), "+f"(c[2]), "+f"(c[3])
        : "r"(a[0]), "r"(a[1]), "r"(a[2]), "r"(a[3]), "r"(b[0]), "r"(b[1]));
}
__device__ __forceinline__ uint32_t cvt2(float hi, float lo) {
    uint32_t r;
    asm("cvt.rn.bf16x2.f32 %0, %1, %2;" : "=r"(r) : "f"(hi), "f"(lo));
    return r;
}
__device__ __forceinline__ float bf_lo_f32(uint32_t p) { return __uint_as_float(p << 16); }
__device__ __forceinline__ float bf_hi_f32(uint32_t p) { return __uint_as_float(p & 0xFFFF0000u); }

#define CP_ASYNC16(dst, src) \
    asm volatile("cp.async.cg.shared.global [%0], [%1], 16;" :: "r"(dst), "l"(src) : "memory")
#define CP_COMMIT()  asm volatile("cp.async.commit_group;" ::: "memory")
#define CP_WAIT0()   asm volatile("cp.async.wait_group 0;" ::: "memory")

__device__ __forceinline__ float sanit(float v) {
    if (!isfinite(v)) v = (v != v) ? 0.f : (v > 0.f ? 3.402823466e38f : -3.402823466e38f);
    return v;
}

// ---------------------------------------------------------------------------
// Prep: cw [256][64] fp32 -> cw^T split-bf16 [64][256]
// ---------------------------------------------------------------------------
__global__ void k_prep_cw(const float* __restrict__ cw)
{
    int i = blockIdx.x * 256 + threadIdx.x;    // 0..16383
    int k = i >> 8, d = i & 255;
    float v = cw[d * 64 + k];
    __nv_bfloat16 h = __float2bfloat16(v);
    g_cwTh[k * 256 + d] = h;
    g_cwTl[k * 256 + d] = __float2bfloat16(v - __bfloat162float(h));
}

// ---------------------------------------------------------------------------
// FUSED NetVLAD (R14, passing).
// ---------------------------------------------------------------------------
#define O_CWH 0
#define O_CWL 33792
#define O_XH  67584
#define O_XL  101376
#define O_LOG 135168
#define O_ACTH 135168
#define O_ACTL 144384
#define O_RED 153600
#define O_ASUM 155648
#define O_REDK 155904
#define O_INVK 156928
#define O_INVT 157184
#define O_XF  157200
#define NV_SMEM 222736

__global__ void __launch_bounds__(256, 1) k_nv(
    const float* __restrict__ feats, const float* __restrict__ cb,
    const float* __restrict__ cw2)
{
    extern __shared__ __align__(16) char sm[];
    int b = blockIdx.x;
    int tid = threadIdx.x, lane = tid & 31, wid = tid >> 5;
    int wm = wid & 3, wn = wid >> 2;
    int lr = lane >> 2, lc = (lane & 3) * 2;

    uint32_t cwh_s = smem_u32(sm + O_CWH), cwl_s = smem_u32(sm + O_CWL);
    uint32_t xh_s  = smem_u32(sm + O_XH),  xl_s  = smem_u32(sm + O_XL);
    uint32_t ah_s  = smem_u32(sm + O_ACTH), al_s = smem_u32(sm + O_ACTL);
    uint32_t xf_s  = smem_u32(sm + O_XF);
    float* logit = (float*)(sm + O_LOG);
    float* red   = (float*)(sm + O_RED);
    float* asums = (float*)(sm + O_ASUM);
    float* redk  = (float*)(sm + O_REDK);
    float* invk  = (float*)(sm + O_INVK);
    float* invts = (float*)(sm + O_INVT);
    const float* xf = (const float*)(sm + O_XF);

    int l7  = lane & 7;
    int s8  = (lane & 8) ? 8 : 0;
    int s16 = (lane & 16) ? 8 : 0;
    int rowA_log = wm * 16 + l7 + s8;
    int rowB_nt  = l7 + s16;
    int rowX_n   = l7 + s16;

    auto issue_xf = [&](int kbi) {
        int n0 = kbi * 64;
#pragma unroll
        for (int p = 0; p < 16; p++) {
            int idx = tid + p * 256;
            int row = idx >> 6;
            int c16 = idx & 63;
            int gn = n0 + row;
            if (gn < NUM_KP) {
                uint32_t d = xf_s + (uint32_t)(row * 1024 + c16 * 16);
                const char* src = (const char*)(feats + ((size_t)b * NUM_KP + gn) * DESC) + c16 * 16;
                CP_ASYNC16(d, src);
            }
        }
        CP_COMMIT();
    };
    auto issue_cw2 = [&]() {
#pragma unroll
        for (int p = 0; p < 16; p++) {
            int idx = tid + p * 256;
            CP_ASYNC16(xf_s + (uint32_t)idx * 16, (const char*)cw2 + (size_t)idx * 16);
        }
        CP_COMMIT();
    };

    for (int i = tid; i < 2048; i += 256) {
        int k = i >> 5, c = i & 31;
        *(uint4*)(sm + O_CWH + k * 528 + c * 16) = ((const uint4*)g_cwTh)[i];
        *(uint4*)(sm + O_CWL + k * 528 + c * 16) = ((const uint4*)g_cwTl)[i];
    }
    issue_xf(0);

    float accv[4][4][4];
#pragma unroll
    for (int mt = 0; mt < 4; mt++)
#pragma unroll
        for (int nt = 0; nt < 4; nt++)
#pragma unroll
            for (int q = 0; q < 4; q++) accv[mt][nt][q] = 0.f;
    float s0 = 0.f, s1 = 0.f;
    float cb0 = cb[lane], cb1 = cb[lane + 32];

    for (int kb = 0; kb < 8; kb++) {
        CP_WAIT0();
        __syncthreads();
        int n0 = kb * 64;
        for (int i = tid; i < 4096; i += 256) {
            int row = i >> 6, c4 = i & 63;
            int gn = n0 + row;
            float4 v = make_float4(0.f, 0.f, 0.f, 0.f);
            if (gn < NUM_KP) v = *(const float4*)(xf + row * 256 + c4 * 4);
            float v0 = sanit(v.x), v1 = sanit(v.y), v2 = sanit(v.z), v3 = sanit(v.w);
            uint32_t h01 = cvt2(v1, v0);
            uint32_t h23 = cvt2(v3, v2);
            uint32_t l01 = cvt2(v1 - bf_hi_f32(h01), v0 - bf_lo_f32(h01));
            uint32_t l23 = cvt2(v3 - bf_hi_f32(h23), v2 - bf_lo_f32(h23));
            char* pxh = sm + O_XH + row * 528 + c4 * 8;
            char* pxl = sm + O_XL + row * 528 + c4 * 8;
            *(uint32_t*)pxh       = h01;
            *(uint32_t*)(pxh + 4) = h23;
            *(uint32_t*)pxl       = l01;
            *(uint32_t*)(pxl + 4) = l23;
        }
        __syncthreads();
        if (kb + 1 < 8) issue_xf(kb + 1);
        else            issue_cw2();

        // ---- logits GEMM ----
        float acc[4][4];
#pragma unroll
        for (int nt = 0; nt < 4; nt++)
#pragma unroll
            for (int q = 0; q < 4; q++) acc[nt][q] = 0.f;
#pragma unroll
        for (int ks = 0; ks < 16; ks++) {
            int kl = ks * 16;
            uint32_t aoff = (uint32_t)(rowA_log * 528 + (kl + s16) * 2);
            uint32_t a[4], al_[4];
            ldm_x4(a,  xh_s + aoff);
            ldm_x4(al_, xl_s + aoff);
#pragma unroll
            for (int ntp = 0; ntp < 2; ntp++) {
                uint32_t boff = (uint32_t)((wn * 32 + ntp * 16 + rowB_nt) * 528 + (kl + s8) * 2);
                uint32_t bh4[4], bl4[4];
                ldm_x4(bh4, cwh_s + boff);
                ldm_x4(bl4, cwl_s + boff);
                mma16816(acc[2 * ntp],     a,   bh4);
                mma16816(acc[2 * ntp],     a,   bl4);
                mma16816(acc[2 * ntp],     al_, bh4);
                mma16816(acc[2 * ntp + 1], a,   bh4 + 2);
                mma16816(acc[2 * ntp + 1], a,   bl4 + 2);
                mma16816(acc[2 * ntp + 1], al_, bh4 + 2);
            }
        }
#pragma unroll
        for (int nt = 0; nt < 4; nt++)
#pragma unroll
            for (int q = 0; q < 4; q++) {
                int row = wm * 16 + lr + ((q >> 1) * 8);
                int col = wn * 32 + nt * 8 + lc + (q & 1);
                logit[row * 68 + col] = acc[nt][q];
            }
        __syncthreads();

        // ---- softmax (no max subtraction) ----
        float l0r[8], l1r[8];
#pragma unroll
        for (int rr = 0; rr < 8; rr++) {
            int row = wid * 8 + rr;
            l0r[rr] = logit[row * 68 + lane] + cb0;
            l1r[rr] = logit[row * 68 + lane + 32] + cb1;
        }
        __syncthreads();
#pragma unroll
        for (int rr = 0; rr < 8; rr++) {
            int row = wid * 8 + rr;
            int gn = n0 + row;
            float e0 = __expf(l0r[rr]), e1 = __expf(l1r[rr]);
            float ss = e0 + e1;
#pragma unroll
            for (int off = 16; off; off >>= 1) ss += __shfl_xor_sync(0xFFFFFFFFu, ss, off);
            float inv = 1.f / ss;
            if (gn < NUM_KP) { e0 *= inv; e1 *= inv; s0 += e0; s1 += e1; }
            else             { e0 = 0.f;  e1 = 0.f; }
            __nv_bfloat16 h0 = __float2bfloat16(e0);
            __nv_bfloat16 h1 = __float2bfloat16(e1);
            *(__nv_bfloat16*)(sm + O_ACTH + lane * 144 + row * 2)        = h0;
            *(__nv_bfloat16*)(sm + O_ACTH + (lane + 32) * 144 + row * 2) = h1;
            *(__nv_bfloat16*)(sm + O_ACTL + lane * 144 + row * 2) =
                __float2bfloat16(e0 - __bfloat162float(h0));
            *(__nv_bfloat16*)(sm + O_ACTL + (lane + 32) * 144 + row * 2) =
                __float2bfloat16(e1 - __bfloat162float(h1));
        }
        __syncthreads();

        // ---- vlad GEMM ----
#pragma unroll
        for (int ks = 0; ks < 4; ks++) {
            int kl = ks * 16;
            uint32_t bh4[2][4], bl4[2][4];
#pragma unroll
            for (int ntp = 0; ntp < 2; ntp++) {
                uint32_t boff = (uint32_t)((wn * 32 + ntp * 16 + rowB_nt) * 144 + (kl + s8) * 2);
                ldm_x4(bh4[ntp], ah_s + boff);
                ldm_x4(bl4[ntp], al_s + boff);
            }
#pragma unroll
            for (int mt = 0; mt < 4; mt++) {
                uint32_t aoff = (uint32_t)((kl + rowX_n) * 528 + (wm * 64 + mt * 16 + s8) * 2);
                uint32_t a[4], al2[4];
                ldm_x4_t(a,   xh_s + aoff);
                ldm_x4_t(al2, xl_s + aoff);
#pragma unroll
                for (int ntp = 0; ntp < 2; ntp++) {
                    mma16816(accv[mt][2 * ntp],     a,   bh4[ntp]);
                    mma16816(accv[mt][2 * ntp],     a,   bl4[ntp]);
                    mma16816(accv[mt][2 * ntp],     al2, bh4[ntp]);
                    mma16816(accv[mt][2 * ntp + 1], a,   bh4[ntp] + 2);
                    mma16816(accv[mt][2 * ntp + 1], a,   bl4[ntp] + 2);
                    mma16816(accv[mt][2 * ntp + 1], al2, bh4[ntp] + 2);
                }
            }
        }
    }

    // ---- asum reduce; cw2 already streaming into XF ----
    red[wid * 64 + lane]      = s0;
    red[wid * 64 + lane + 32] = s1;
    CP_WAIT0();
    __syncthreads();
    if (tid < 32) {
        float t0 = 0.f, t1 = 0.f;
#pragma unroll
        for (int w = 0; w < 8; w++) { t0 += red[w * 64 + lane]; t1 += red[w * 64 + lane + 32]; }
        asums[lane] = t0; asums[lane + 32] = t1;
    }
    __syncthreads();
    const float* cw2s = xf;

#pragma unroll
    for (int mt = 0; mt < 4; mt++)
#pragma unroll
        for (int nt = 0; nt < 4; nt++)
#pragma unroll
            for (int q = 0; q < 4; q++) {
                int d = wm * 64 + mt * 16 + lr + ((q >> 1) * 8);
                int k = wn * 32 + nt * 8 + lc + (q & 1);
                accv[mt][nt][q] -= asums[k] * cw2s[d * 64 + k];
            }
#pragma unroll
    for (int nt = 0; nt < 4; nt++) {
        float sq0 = 0.f, sq1 = 0.f;
#pragma unroll
        for (int mt = 0; mt < 4; mt++) {
            sq0 += accv[mt][nt][0] * accv[mt][nt][0] + accv[mt][nt][2] * accv[mt][nt][2];
            sq1 += accv[mt][nt][1] * accv[mt][nt][1] + accv[mt][nt][3] * accv[mt][nt][3];
        }
        sq0 += __shfl_xor_sync(0xFFFFFFFFu, sq0, 4);
        sq0 += __shfl_xor_sync(0xFFFFFFFFu, sq0, 8);
        sq0 += __shfl_xor_sync(0xFFFFFFFFu, sq0, 16);
        sq1 += __shfl_xor_sync(0xFFFFFFFFu, sq1, 4);
        sq1 += __shfl_xor_sync(0xFFFFFFFFu, sq1, 8);
        sq1 += __shfl_xor_sync(0xFFFFFFFFu, sq1, 16);
        if (lr == 0) {
            int k0 = wn * 32 + nt * 8 + lc;
            redk[k0 * 4 + wm]       = sq0;
            redk[(k0 + 1) * 4 + wm] = sq1;
        }
    }
    __syncthreads();
    if (tid < 32) {
        float q0 = redk[lane * 4] + redk[lane * 4 + 1] + redk[lane * 4 + 2] + redk[lane * 4 + 3];
        int l2 = lane + 32;
        float q1 = redk[l2 * 4] + redk[l2 * 4 + 1] + redk[l2 * 4 + 2] + redk[l2 * 4 + 3];
        float i0 = 1.f / (sqrtf(q0) + 1e-12f);
        float i1 = 1.f / (sqrtf(q1) + 1e-12f);
        invk[lane] = i0; invk[l2] = i1;
        float tt = q0 * i0 * i0 + q1 * i1 * i1;
#pragma unroll
        for (int off = 16; off; off >>= 1) tt += __shfl_xor_sync(0xFFFFFFFFu, tt, off);
        if (lane == 0) invts[0] = 1.f / (sqrtf(tt) + 1e-12f);
    }
    __syncthreads();
    float invt = invts[0];

#pragma unroll
    for (int mt = 0; mt < 4; mt++)
#pragma unroll
        for (int nt = 0; nt < 4; nt++)
#pragma unroll
            for (int q = 0; q < 4; q += 2) {
                int d = wm * 64 + mt * 16 + lr + ((q >> 1) * 8);
                int k = wn * 32 + nt * 8 + lc;
                float va = accv[mt][nt][q]     * invk[k]     * invt;
                float vb = accv[mt][nt][q + 1] * invk[k + 1] * invt;
                uint32_t h = cvt2(vb, va);
                uint32_t l = cvt2(vb - bf_hi_f32(h), va - bf_lo_f32(h));
                *(uint32_t*)(sm + O_XH + (d * 66 + k) * 2) = h;
                *(uint32_t*)(sm + O_XL + (d * 66 + k) * 2) = l;
            }
    __syncthreads();
    for (int i = tid; i < 8192; i += 256) {
        int d = i >> 5, kp = i & 31;
        uint32_t vh = lds32(xh_s + (uint32_t)(d * 66 + kp * 2) * 2);
        uint32_t vl = lds32(xl_s + (uint32_t)(d * 66 + kp * 2) * 2);
        size_t go = (size_t)b * VLAD_DIM + d * 64 + kp * 2;
        *(uint32_t*)((char*)g_Ah + go * 2) = vh;
        *(uint32_t*)((char*)g_Al + go * 2) = vl;
    }
}

// ---------------------------------------------------------------------------
// Transpose + split: src[k][n] fp32 -> dh/dl[n][k] bf16 (pads zero-filled).
// ---------------------------------------------------------------------------
__global__ void __launch_bounds__(256) k_cvt_trans(
    const float* __restrict__ src, int ldsrc, int Kreal, int Nreal,
    __nv_bfloat16* __restrict__ dh, __nv_bfloat16* __restrict__ dl, int ldd)
{
    __shared__ float smt[32][33];
    int k0 = blockIdx.x * 32;
    int n0 = blockIdx.y * 32;
    int tx = threadIdx.x & 31;
    int ty = threadIdx.x >> 5;
#pragma unroll
    for (int i = 0; i < 4; i++) {
        int kk = ty + i * 8;
        int n = n0 + tx;
        float v = (k0 + kk < Kreal && n < Nreal) ? src[(size_t)(k0 + kk) * ldsrc + n] : 0.f;
        smt[kk][tx] = v;
    }
    __syncthreads();
#pragma unroll
    for (int i = 0; i < 4; i++) {
        int nn = ty + i * 8;
        float v = smt[tx][nn];
        __nv_bfloat16 h = __float2bfloat16(v);
        __nv_bfloat16 l = __float2bfloat16(v - __bfloat162float(h));
        size_t o = (size_t)(n0 + nn) * ldd + k0 + tx;
        dh[o] = h;
        dl[o] = l;
    }
}

// ---------------------------------------------------------------------------
// Split-bf16 HMMA GEMM (unchanged, passing).
// ---------------------------------------------------------------------------
#define KBLK 64
#define SPITCH 72
#define SPB (SPITCH * 2)
#define TILE_B (128 * SPB)
#define STAGE_B (4 * TILE_B)
#define MMA_SMEM_TOTAL (2 * STAGE_B)

__global__ void __launch_bounds__(256, 1) k_mma(
    const __nv_bfloat16* __restrict__ Ah, const __nv_bfloat16* __restrict__ Al,
    const __nv_bfloat16* __restrict__ Bh, const __nv_bfloat16* __restrict__ Bl,
    int K, float* __restrict__ C, int M, int N,
    const float* __restrict__ bias, int act,
    __nv_bfloat16* __restrict__ Dh, __nv_bfloat16* __restrict__ Dl, int ldd)
{
    extern __shared__ __align__(16) char smem[];
    uint32_t sb = smem_u32(smem);
    int tid = threadIdx.x;
    int wid = tid >> 5, lane = tid & 31;
    int wm = wid & 3;
    int wn = wid >> 2;
    int m0 = blockIdx.y * 128;
    int n0 = blockIdx.x * 128;

    const __nv_bfloat16* srcs[4] = {
        Ah + (size_t)m0 * K, Al + (size_t)m0 * K,
        Bh + (size_t)n0 * K, Bl + (size_t)n0 * K };

    int lrow = tid >> 3;
    int lchk = tid & 7;

    int l7  = lane & 7;
    int s8  = (lane & 8) ? 8 : 0;
    int s16 = (lane & 16) ? 8 : 0;

    float acc[2][8][4];
#pragma unroll
    for (int i = 0; i < 2; i++)
#pragma unroll
        for (int j = 0; j < 8; j++)
#pragma unroll
            for (int q = 0; q < 4; q++) acc[i][j][q] = 0.f;

    auto load_stage = [&](int s, int kb) {
        uint32_t sd = sb + s * STAGE_B;
        size_t kOff = (size_t)kb * KBLK;
#pragma unroll
        for (int v = 0; v < 4; v++) {
            const __nv_bfloat16* g = srcs[v] + kOff;
#pragma unroll
            for (int p = 0; p < 4; p++) {
                int rr = lrow + p * 32;
                uint32_t d = sd + v * TILE_B + rr * SPB + lchk * 16;
                const void* sptr = (const char*)(g + (size_t)rr * K) + lchk * 16;
                CP_ASYNC16(d, sptr);
            }
        }
        CP_COMMIT();
    };

    load_stage(0, 0);

    int lr = lane >> 2;
    int lc = (lane & 3) * 2;
    int nkb = K / KBLK;

    for (int kb = 0; kb < nkb; kb++) {
        int s = kb & 1;
        CP_WAIT0();
        __syncthreads();
        if (kb + 1 < nkb) load_stage(s ^ 1, kb + 1);

        uint32_t sAh = sb + s * STAGE_B;
        uint32_t sAl = sAh + TILE_B;
        uint32_t sBh = sAh + 2 * TILE_B;
        uint32_t sBl = sAh + 3 * TILE_B;

#pragma unroll
        for (int ks = 0; ks < 4; ks++) {
            int kl = ks * 16;
            uint32_t ah4[2][4], al4[2][4];
#pragma unroll
            for (int mt = 0; mt < 2; mt++) {
                uint32_t aoff = (uint32_t)((wm * 32 + mt * 16 + l7 + s8) * SPB + (kl + s16) * 2);
                ldm_x4(ah4[mt], sAh + aoff);
                ldm_x4(al4[mt], sAl + aoff);
            }
            uint32_t bh4[4][4], bl4[4][4];
#pragma unroll
            for (int ntp = 0; ntp < 4; ntp++) {
                uint32_t boff = (uint32_t)((wn * 64 + ntp * 16 + l7 + s16) * SPB + (kl + s8) * 2);
                ldm_x4(bh4[ntp], sBh + boff);
                ldm_x4(bl4[ntp], sBl + boff);
            }
#pragma unroll
            for (int mt = 0; mt < 2; mt++)
#pragma unroll
                for (int ntp = 0; ntp < 4; ntp++) {
                    mma16816(acc[mt][2 * ntp],     ah4[mt], bh4[ntp]);
                    mma16816(acc[mt][2 * ntp],     ah4[mt], bl4[ntp]);
                    mma16816(acc[mt][2 * ntp],     al4[mt], bh4[ntp]);
                    mma16816(acc[mt][2 * ntp + 1], ah4[mt], bh4[ntp] + 2);
                    mma16816(acc[mt][2 * ntp + 1], ah4[mt], bl4[ntp] + 2);
                    mma16816(acc[mt][2 * ntp + 1], al4[mt], bh4[ntp] + 2);
                }
        }
    }

    auto emit = [&](int r, int c, float v) {
        bool in = (r < M && c < N);
        float val = 0.f;
        if (in) {
            val = v + (bias ? bias[c] : 0.f);
            if (act == 1) val = fmaxf(val, 0.f);
            if (C) C[(size_t)r * N + c] = val;
        }
        if (Dh) {
            __nv_bfloat16 h = __float2bfloat16(val);
            Dh[(size_t)r * ldd + c] = h;
            Dl[(size_t)r * ldd + c] = __float2bfloat16(val - __bfloat162float(h));
        }
    };
#pragma unroll
    for (int mt = 0; mt < 2; mt++) {
#pragma unroll
        for (int nt = 0; nt < 8; nt++) {
            int r = m0 + wm * 32 + mt * 16 + lr;
            int c = n0 + wn * 64 + nt * 8 + lc;
            emit(r,     c,     acc[mt][nt][0]);
            emit(r,     c + 1, acc[mt][nt][1]);
            emit(r + 8, c,     acc[mt][nt][2]);
            emit(r + 8, c + 1, acc[mt][nt][3]);
        }
    }
}

// ---------------------------------------------------------------------------
// GAT kernels (R12-measured path). k_gat_h reads g_x; k_gat_h2 reads
// aggr + prev-layer bias and applies elu in-register (folds k_gat_fin).
// ---------------------------------------------------------------------------
__device__ __forceinline__ void gat_h_core(
    float xv, int b, int t,
    const float* __restrict__ W, const float* __restrict__ a_s,
    const float* __restrict__ a_d, float* xsm, float* rs)
{
    xsm[t] = xv;
    g_aggr[b * NODE_D + t] = 0.f;
    if (t == 0) g_den[b] = 0.f;
    __syncthreads();
    float acc = 0.f;
#pragma unroll 8
    for (int d = 0; d < NODE_D; d++) acc = fmaf(xsm[d], __ldg(&W[d * NODE_D + t]), acc);
    g_h[b * NODE_D + t] = acc;
    float ps = acc * __ldg(&a_s[t]);
    float pd = acc * __ldg(&a_d[t]);
#pragma unroll
    for (int off = 16; off; off >>= 1) {
        ps += __shfl_xor_sync(0xFFFFFFFFu, ps, off);
        pd += __shfl_xor_sync(0xFFFFFFFFu, pd, off);
    }
    if ((t & 31) == 0) { rs[t >> 5] = ps; rs[4 + (t >> 5)] = pd; }
    __syncthreads();
    if (t == 0) g_es[b] = rs[0] + rs[1] + rs[2] + rs[3];
    if (t == 1) g_ed[b] = rs[4] + rs[5] + rs[6] + rs[7];
}

__global__ void __launch_bounds__(128) k_gat_h(
    const float* __restrict__ W, const float* __restrict__ a_s,
    const float* __restrict__ a_d)
{
    int b = blockIdx.x, t = threadIdx.x;
    __shared__ float xsm[NODE_D];
    __shared__ float rs[8];
    gat_h_core(g_x[b * NODE_D + t], b, t, W, a_s, a_d, xsm, rs);
}

__global__ void __launch_bounds__(128) k_gat_h2(
    const float* __restrict__ W, const float* __restrict__ a_s,
    const float* __restrict__ a_d, const float* __restrict__ bprev)
{
    int b = blockIdx.x, t = threadIdx.x;
    __shared__ float xsm[NODE_D];
    __shared__ float rs[8];
    float v = g_aggr[b * NODE_D + t] + __ldg(&bprev[t]);
    v = (v > 0.f) ? v : (__expf(v) - 1.f);
    gat_h_core(v, b, t, W, a_s, a_d, xsm, rs);
}

__global__ void k_edge12(const int* __restrict__ ei)
{
    int e = blockIdx.x * blockDim.x + threadIdx.x;
    if (e >= E_EXT) return;
    int s, d;
    if (e < N_EDGES) { s = ei[e]; d = ei[N_EDGES + e]; }
    else { s = e - N_EDGES; d = s; }
    float v = g_es[s] + g_ed[d];
    v = (v > 0.f) ? v : 0.2f * v;
    float ex = __expf(v);
    g_ex[e] = ex;
    atomicAdd(&g_den[d], ex);
}

__global__ void k_edge3(const int* __restrict__ ei)
{
    int gt = blockIdx.x * blockDim.x + threadIdx.x;
    int w = gt >> 5, lane = gt & 31;
    if (w >= E_EXT) return;
    int s, d;
    if (w < N_EDGES) { s = ei[w]; d = ei[N_EDGES + w]; }
    else { s = w - N_EDGES; d = s; }
    float alpha = g_ex[w] / g_den[d];
#pragma unroll
    for (int i = 0; i < 4; i++) {
        int c = lane + 32 * i;
        atomicAdd(&g_aggr[d * NODE_D + c], g_h[s * NODE_D + c] * alpha);
    }
}

__global__ void k_gat_fin(const float* __restrict__ b)
{
    int i = blockIdx.x * blockDim.x + threadIdx.x;
    if (i >= N_NODES * NODE_D) return;
    float v = g_aggr[i] + __ldg(&b[i & (NODE_D - 1)]);
    g_x[i] = (v > 0.f) ? v : (__expf(v) - 1.f);
}

// ---------------------------------------------------------------------------
// Edge-attr MLP: 1 -> 8 -> 16 -> 32 (unchanged)
// ---------------------------------------------------------------------------
__global__ void __launch_bounds__(256) k_ef(
    const float* __restrict__ ea,
    const float* __restrict__ w1, const float* __restrict__ b1,
    const float* __restrict__ w2, const float* __restrict__ b2,
    const float* __restrict__ w3, const float* __restrict__ b3)
{
    __shared__ float w1s[8], b1s[8], w2s[128], b2s[16], w3s[512], b3s[32];
    int t = threadIdx.x;
    if (t < 8)   { w1s[t] = w1[t]; b1s[t] = b1[t]; }
    if (t < 128) w2s[t] = w2[t];
    if (t < 16)  b2s[t] = b2[t];
    if (t < 32)  b3s[t] = b3[t];
    for (int i = t; i < 512; i += blockDim.x) w3s[i] = w3[i];
    __syncthreads();
    int e = blockIdx.x * blockDim.x + t;
    if (e >= N_EDGES) return;
    float a = ea[e];
    float t8[8];
#pragma unroll
    for (int j = 0; j < 8; j++) t8[j] = fmaxf(fmaf(a, w1s[j], b1s[j]), 0.f);
    float t16[16];
#pragma unroll
    for (int c = 0; c < 16; c++) {
        float acc = b2s[c];
#pragma unroll
        for (int j = 0; j < 8; j++) acc = fmaf(t8[j], w2s[j * 16 + c], acc);
        t16[c] = fmaxf(acc, 0.f);
    }
#pragma unroll
    for (int c = 0; c < 32; c++) {
        float acc = b3s[c];
#pragma unroll
        for (int j = 0; j < 16; j++) acc = fmaf(t16[j], w3s[j * 32 + c], acc);
        g_ef2[e * EDGE_D + c] = acc;
    }
}

// ---------------------------------------------------------------------------
// Final fused edge classifier (unchanged).
// ---------------------------------------------------------------------------
__global__ void __launch_bounds__(256) k_final(
    const int* __restrict__ ei,
    const float* __restrict__ dp_w, const float* __restrict__ dp_b,
    const float* __restrict__ ec_w1, const float* __restrict__ ec_b1,
    const float* __restrict__ ec_w2, const float* __restrict__ ec_b2,
    float* __restrict__ out)
{
    __shared__ float dpw_s[288 * 32];
    __shared__ float ecw1_s[32 * 16];
    __shared__ float dpb_s[32];
    __shared__ float ecb1_s[16];
    __shared__ float ecw2_s[16];
    __shared__ float vec_s[8][292];
    __shared__ float o32_s[8][32];

    int tid = threadIdx.x;
    for (int i = tid; i < 288 * 32; i += 256) dpw_s[i] = dp_w[i];
    for (int i = tid; i < 512; i += 256) ecw1_s[i] = ec_w1[i];
    if (tid < 32) dpb_s[tid] = dp_b[tid];
    if (tid < 16) { ecb1_s[tid] = ec_b1[tid]; ecw2_s[tid] = ec_w2[tid]; }
    __syncthreads();

    float b2 = __ldg(ec_b2);
    int warp = tid >> 5, lane = tid & 31;
    int gw = blockIdx.x * 8 + warp;
    int nw = gridDim.x * 8;

    for (int e = gw; e < N_EDGES; e += nw) {
        int s = ei[e], d = ei[N_EDGES + e];
        const float* xsp = g_x + s * NODE_D;
        const float* xdp = g_x + d * NODE_D;
#pragma unroll
        for (int i = 0; i < 4; i++) {
            vec_s[warp][lane + 32 * i]       = xsp[lane + 32 * i];
            vec_s[warp][128 + lane + 32 * i] = xdp[lane + 32 * i];
        }
        vec_s[warp][256 + lane] = g_ef2[e * EDGE_D + lane];
        __syncwarp();

        float acc = dpb_s[lane];
#pragma unroll 4
        for (int i = 0; i < 288; i++) acc = fmaf(vec_s[warp][i], dpw_s[i * 32 + lane], acc);
        o32_s[warp][lane] = acc;
        __syncwarp();

        float hh = 0.f;
        if (lane < 16) {
            hh = ecb1_s[lane];
#pragma unroll 4
            for (int j = 0; j < 32; j++) hh = fmaf(o32_s[warp][j], ecw1_s[j * 16 + lane], hh);
            hh = fmaxf(hh, 0.f) * ecw2_s[lane];
        }
#pragma unroll
        for (int off = 8; off; off >>= 1) hh += __shfl_xor_sync(0xFFFFFFFFu, hh, off);
        if (lane == 0) out[e] = 1.f / (1.f + __expf(-(hh + b2)));
        __syncwarp();
    }
}

// ---------------------------------------------------------------------------
extern "C" void kernel_launch(void* const* d_in, const int* in_sizes, int n_in,
                              void* d_out, int out_size)
{
    (void)in_sizes; (void)n_in; (void)out_size;
    const float* node_feats = (const float*)d_in[0];
    const float* edge_attr  = (const float*)d_in[1];
    const float* nv_cw      = (const float*)d_in[2];
    const float* nv_cb      = (const float*)d_in[3];
    const float* nv_cw2     = (const float*)d_in[4];
    const float* nv_hw      = (const float*)d_in[5];
    const float* ne_w1      = (const float*)d_in[6];
    const float* ne_b1      = (const float*)d_in[7];
    const float* ne_w2      = (const float*)d_in[8];
    const float* ne_b2      = (const float*)d_in[9];
    const float* ee_w1      = (const float*)d_in[10];
    const float* ee_b1      = (const float*)d_in[11];
    const float* ee_w2      = (const float*)d_in[12];
    const float* ee_b2      = (const float*)d_in[13];
    const float* ee_w3      = (const float*)d_in[14];
    const float* ee_b3      = (const float*)d_in[15];
    const float* gat_w      = (const float*)d_in[16];
    const float* gat_as     = (const float*)d_in[17];
    const float* gat_ad     = (const float*)d_in[18];
    const float* gat_b      = (const float*)d_in[19];
    const float* dp_w       = (const float*)d_in[20];
    const float* dp_b       = (const float*)d_in[21];
    const float* ec_w1      = (const float*)d_in[22];
    const float* ec_b1      = (const float*)d_in[23];
    const float* ec_w2      = (const float*)d_in[24];
    const float* ec_b2      = (const float*)d_in[25];
    const int*   edge_index = (const int*)d_in[26];
    float* out = (float*)d_out;

    float* p_x;
    __nv_bfloat16 *p_Ah, *p_Al, *p_Bh, *p_Bl;
    __nv_bfloat16 *p_Ah2, *p_Al2, *p_Bh2, *p_Bl2;
    __nv_bfloat16 *p_Ah3, *p_Al3, *p_Bh3, *p_Bl3;
    cudaGetSymbolAddress((void**)&p_x, g_x);
    cudaGetSymbolAddress((void**)&p_Ah, g_Ah);
    cudaGetSymbolAddress((void**)&p_Al, g_Al);
    cudaGetSymbolAddress((void**)&p_Bh, g_Bh);
    cudaGetSymbolAddress((void**)&p_Bl, g_Bl);
    cudaGetSymbolAddress((void**)&p_Ah2, g_Ah2);
    cudaGetSymbolAddress((void**)&p_Al2, g_Al2);
    cudaGetSymbolAddress((void**)&p_Bh2, g_Bh2);
    cudaGetSymbolAddress((void**)&p_Bl2, g_Bl2);
    cudaGetSymbolAddress((void**)&p_Ah3, g_Ah3);
    cudaGetSymbolAddress((void**)&p_Al3, g_Al3);
    cudaGetSymbolAddress((void**)&p_Bh3, g_Bh3);
    cudaGetSymbolAddress((void**)&p_Bl3, g_Bl3);

    static int s_init = 0;
    static cudaStream_t s2;
    static cudaEvent_t ev1, ev2;
    if (!s_init) {
        cudaFuncSetAttribute(k_mma, cudaFuncAttributeMaxDynamicSharedMemorySize, MMA_SMEM_TOTAL);
        cudaFuncSetAttribute(k_nv, cudaFuncAttributeMaxDynamicSharedMemorySize, NV_SMEM);
        cudaStreamCreateWithFlags(&s2, cudaStreamNonBlocking);
        cudaEventCreateWithFlags(&ev1, cudaEventDisableTiming);
        cudaEventCreateWithFlags(&ev2, cudaEventDisableTiming);
        s_init = 1;
    }

    // fork: B conversions + edge MLP run concurrently with NetVLAD
    cudaEventRecord(ev1, 0);
    cudaStreamWaitEvent(s2, ev1, 0);
    {
        dim3 g(VLAD_DIM / 32, N_PAD / 32);
        k_cvt_trans<<<g, 256, 0, s2>>>(nv_hw, H0D, VLAD_DIM, H0D, p_Bh, p_Bl, VLAD_DIM);
    }
    {
        dim3 g(K2PAD / 32, N2PAD / 32);
        k_cvt_trans<<<g, 256, 0, s2>>>(ne_w1, H1D, H0D, H1D, p_Bh2, p_Bl2, K2PAD);
    }
    {
        dim3 g(K3PAD / 32, N3PAD / 32);
        k_cvt_trans<<<g, 256, 0, s2>>>(ne_w2, NODE_D, H1D, NODE_D, p_Bh3, p_Bl3, K3PAD);
    }
    k_ef<<<(N_EDGES + 255) / 256, 256, 0, s2>>>(edge_attr, ee_w1, ee_b1, ee_w2, ee_b2,
                                                ee_w3, ee_b3);
    cudaEventRecord(ev2, s2);

    // main stream: NetVLAD
    k_prep_cw<<<64, 256>>>(nv_cw);
    k_nv<<<N_NODES, 256, NV_SMEM>>>(node_feats, nv_cb, nv_cw2);

    // join before G1
    cudaStreamWaitEvent(0, ev2, 0);

    // G1 HMMA: h0 = vlad @ hw -> split-bf16 A operand of G2
    {
        dim3 g(N_PAD / 128, M_PAD / 128);
        k_mma<<<g, 256, MMA_SMEM_TOTAL>>>(p_Ah, p_Al, p_Bh, p_Bl, VLAD_DIM,
                                          nullptr, N_NODES, H0D, nullptr, 0,
                                          p_Ah2, p_Al2, K2PAD);
    }
    // G2 HMMA: h1 = relu(h0 @ ne_w1 + b1) -> split-bf16 A operand of G3
    {
        dim3 g(N2PAD / 128, M_PAD / 128);
        k_mma<<<g, 256, MMA_SMEM_TOTAL>>>(p_Ah2, p_Al2, p_Bh2, p_Bl2, K2PAD,
                                          nullptr, N_NODES, H1D, ne_b1, 1,
                                          p_Ah3, p_Al3, K3PAD);
    }
    // G3 HMMA: x = h1 @ ne_w2 + b2
    {
        dim3 g(1, M_PAD / 128);
        k_mma<<<g, 256, MMA_SMEM_TOTAL>>>(p_Ah3, p_Al3, p_Bh3, p_Bl3, K3PAD,
                                          p_x, N_NODES, NODE_D, ne_b2, 0,
                                          nullptr, nullptr, 0);
    }

    // 3 GAT layers; elu+bias of layers 0/1 folded into the next k_gat_h2
    for (int l = 0; l < DEPTH; l++) {
        if (l == 0)
            k_gat_h<<<N_NODES, 128>>>(gat_w, gat_as, gat_ad);
        else
            k_gat_h2<<<N_NODES, 128>>>(gat_w + l * NODE_D * NODE_D,
                                       gat_as + l * NODE_D, gat_ad + l * NODE_D,
                                       gat_b + (l - 1) * NODE_D);
        k_edge12<<<(E_EXT + 255) / 256, 256>>>(edge_index);
        k_edge3<<<((E_EXT * 32) + 255) / 256, 256>>>(edge_index);
    }
    k_gat_fin<<<(N_NODES * NODE_D + 255) / 256, 256>>>(gat_b + 2 * NODE_D);

    // fused edge classifier -> out
    k_final<<<256, 256>>>(edge_index, dp_w, dp_b, ec_w1, ec_b1, ec_w2, ec_b2, out);
}

// round 16
// speedup vs baseline: 1.0484x; 1.0199x over previous
#include <cuda_runtime.h>
#include <cuda_bf16.h>
#include <math.h>
#include <stdint.h>

#define N_NODES 2000
#define NUM_KP 500
#define DESC 256
#define NVK 64
#define VLAD_DIM (DESC*NVK)        // 16384
#define H0D (NUM_KP*2)             // 1000
#define H1D NUM_KP                 // 500
#define NODE_D 128
#define EDGE_D 32
#define N_EDGES 64000
#define E_EXT (N_EDGES + N_NODES)  // 66000
#define DEPTH 3

#define M_PAD 2048
#define N_PAD 1024
#define K2PAD 1024
#define N2PAD 512
#define K3PAD 512
#define N3PAD 128

typedef unsigned long long u64;

// ---------------- scratch (device globals; no runtime allocation) ----------
__device__ float    g_x[N_NODES * NODE_D];
__device__ float    g_h[N_NODES * NODE_D];
__device__ float    g_es[N_NODES];
__device__ float    g_ed[N_NODES];
__device__ float    g_ex[E_EXT];
__device__ float    g_den[N_NODES];
__device__ float    g_aggr[N_NODES * NODE_D];
__device__ float    g_ef2[N_EDGES * EDGE_D];
// split-bf16 operands (pad regions stay zero: static zero-init, never written)
__device__ __nv_bfloat16 g_Ah[(size_t)M_PAD * VLAD_DIM];
__device__ __nv_bfloat16 g_Al[(size_t)M_PAD * VLAD_DIM];
__device__ __nv_bfloat16 g_Bh[(size_t)N_PAD * VLAD_DIM];
__device__ __nv_bfloat16 g_Bl[(size_t)N_PAD * VLAD_DIM];
__device__ __nv_bfloat16 g_Ah2[(size_t)M_PAD * K2PAD];
__device__ __nv_bfloat16 g_Al2[(size_t)M_PAD * K2PAD];
__device__ __nv_bfloat16 g_Bh2[(size_t)N2PAD * K2PAD];
__device__ __nv_bfloat16 g_Bl2[(size_t)N2PAD * K2PAD];
__device__ __nv_bfloat16 g_Ah3[(size_t)M_PAD * K3PAD];
__device__ __nv_bfloat16 g_Al3[(size_t)M_PAD * K3PAD];
__device__ __nv_bfloat16 g_Bh3[(size_t)N3PAD * K3PAD];
__device__ __nv_bfloat16 g_Bl3[(size_t)N3PAD * K3PAD];
__device__ __nv_bfloat16 g_cwTh[NVK * DESC];
__device__ __nv_bfloat16 g_cwTl[NVK * DESC];

// ---------------- helpers ---------------------------------------------------
__device__ __forceinline__ uint32_t smem_u32(const void* p) {
    uint32_t a;
    asm("{ .reg .u64 t; cvta.to.shared.u64 t, %1; cvt.u32.u64 %0, t; }" : "=r"(a) : "l"(p));
    return a;
}
__device__ __forceinline__ uint32_t lds32(uint32_t addr) {
    uint32_t v;
    asm volatile("ld.shared.b32 %0, [%1];" : "=r"(v) : "r"(addr));
    return v;
}
__device__ __forceinline__ void ldm_x4(uint32_t* r, uint32_t addr) {
    asm volatile("ldmatrix.sync.aligned.m8n8.x4.shared.b16 {%0,%1,%2,%3}, [%4];"
        : "=r"(r[0]), "=r"(r[1]), "=r"(r[2]), "=r"(r[3]) : "r"(addr));
}
__device__ __forceinline__ void ldm_x4_t(uint32_t* r, uint32_t addr) {
    asm volatile("ldmatrix.sync.aligned.m8n8.x4.trans.shared.b16 {%0,%1,%2,%3}, [%4];"
        : "=r"(r[0]), "=r"(r[1]), "=r"(r[2]), "=r"(r[3]) : "r"(addr));
}
__device__ __forceinline__ void mma16816(float* c, const uint32_t* a, const uint32_t* b) {
    asm volatile(
        "mma.sync.aligned.m16n8k16.row.col.f32.bf16.bf16.f32 "
        "{%0,%1,%2,%3}, {%4,%5,%6,%7}, {%8,%9}, {%0,%1,%2,%3};"
        : "+f"(c[0]), "+f"(c[1]), "+f"(c[2]), "+f"(c[3])
        : "r"(a[0]), "r"(a[1]), "r"(a[2]), "r"(a[3]), "r"(b[0]), "r"(b[1]));
}
__device__ __forceinline__ uint32_t cvt2(float hi, float lo) {
    uint32_t r;
    asm("cvt.rn.bf16x2.f32 %0, %1, %2;" : "=r"(r) : "f"(hi), "f"(lo));
    return r;
}
__device__ __forceinline__ float bf_lo_f32(uint32_t p) { return __uint_as_float(p << 16); }
__device__ __forceinline__ float bf_hi_f32(uint32_t p) { return __uint_as_float(p & 0xFFFF0000u); }

#define CP_ASYNC16(dst, src) \
    asm volatile("cp.async.cg.shared.global [%0], [%1], 16;" :: "r"(dst), "l"(src) : "memory")
#define CP_COMMIT()  asm volatile("cp.async.commit_group;" ::: "memory")
#define CP_WAIT0()   asm volatile("cp.async.wait_group 0;" ::: "memory")

__device__ __forceinline__ float sanit(float v) {
    if (!isfinite(v)) v = (v != v) ? 0.f : (v > 0.f ? 3.402823466e38f : -3.402823466e38f);
    return v;
}

// ---------------------------------------------------------------------------
// Prep: cw [256][64] fp32 -> cw^T split-bf16 [64][256]
// ---------------------------------------------------------------------------
__global__ void k_prep_cw(const float* __restrict__ cw)
{
    int i = blockIdx.x * 256 + threadIdx.x;    // 0..16383
    int k = i >> 8, d = i & 255;
    float v = cw[d * 64 + k];
    __nv_bfloat16 h = __float2bfloat16(v);
    g_cwTh[k * 256 + d] = h;
    g_cwTl[k * 256 + d] = __float2bfloat16(v - __bfloat162float(h));
}

// ---------------------------------------------------------------------------
// FUSED NetVLAD, 512 threads (16 warps = 4/SMSP for latency hiding).
// Logits warp tile 16x16; vlad warp tile 32x32.
// ---------------------------------------------------------------------------
#define NV_T 512
#define O_CWH 0          // cwT hi [64 k][264 d] bf16 (pitch 528B), 33792B
#define O_CWL 33792
#define O_XH  67584      // x hi [64 n][264 d], 33792B
#define O_XL  101376
#define O_LOG 135168     // logits [64][68] f32 (17408B); reused as actT
#define O_ACTH 135168    // actT hi [64 k][72 n] bf16 pitch 144B (9216B)
#define O_ACTL 144384
#define O_RED 153600     // [16][64] f32 (4096B)
#define O_ASUM 157696    // [64] f32
#define O_REDK 157952    // [64][8] f32 (2048B)
#define O_INVK 160000    // [64] f32
#define O_INVT 160256    // 16B
#define O_XF  160272     // fp32 staging 65536B (cw2 at the end)
#define NV_SMEM 225808

__global__ void __launch_bounds__(NV_T, 1) k_nv(
    const float* __restrict__ feats, const float* __restrict__ cb,
    const float* __restrict__ cw2)
{
    extern __shared__ __align__(16) char sm[];
    int b = blockIdx.x;
    int tid = threadIdx.x, lane = tid & 31, wid = tid >> 5;
    // logits decomposition: rows by wm (4x16), cols by wn (4x16)
    int wm = wid & 3, wn = wid >> 2;
    // vlad decomposition: d-rows by wm2 (8x32), k-cols by wn2 (2x32)
    int wm2 = wid & 7, wn2 = wid >> 3;
    int lr = lane >> 2, lc = (lane & 3) * 2;

    uint32_t cwh_s = smem_u32(sm + O_CWH), cwl_s = smem_u32(sm + O_CWL);
    uint32_t xh_s  = smem_u32(sm + O_XH),  xl_s  = smem_u32(sm + O_XL);
    uint32_t ah_s  = smem_u32(sm + O_ACTH), al_s = smem_u32(sm + O_ACTL);
    uint32_t xf_s  = smem_u32(sm + O_XF);
    float* logit = (float*)(sm + O_LOG);
    float* red   = (float*)(sm + O_RED);
    float* asums = (float*)(sm + O_ASUM);
    float* redk  = (float*)(sm + O_REDK);
    float* invk  = (float*)(sm + O_INVK);
    float* invts = (float*)(sm + O_INVT);
    const float* xf = (const float*)(sm + O_XF);

    int l7  = lane & 7;
    int s8  = (lane & 8) ? 8 : 0;
    int s16 = (lane & 16) ? 8 : 0;
    int rowA_log = wm * 16 + l7 + s8;
    int rowB_nt  = l7 + s16;
    int rowX_n   = l7 + s16;

    auto issue_xf = [&](int kbi) {
        int n0 = kbi * 64;
#pragma unroll
        for (int p = 0; p < 8; p++) {
            int idx = tid + p * NV_T;
            int row = idx >> 6;
            int c16 = idx & 63;
            int gn = n0 + row;
            if (gn < NUM_KP) {
                uint32_t d = xf_s + (uint32_t)(row * 1024 + c16 * 16);
                const char* src = (const char*)(feats + ((size_t)b * NUM_KP + gn) * DESC) + c16 * 16;
                CP_ASYNC16(d, src);
            }
        }
        CP_COMMIT();
    };
    auto issue_cw2 = [&]() {
#pragma unroll
        for (int p = 0; p < 8; p++) {
            int idx = tid + p * NV_T;
            CP_ASYNC16(xf_s + (uint32_t)idx * 16, (const char*)cw2 + (size_t)idx * 16);
        }
        CP_COMMIT();
    };

    for (int i = tid; i < 2048; i += NV_T) {
        int k = i >> 5, c = i & 31;
        *(uint4*)(sm + O_CWH + k * 528 + c * 16) = ((const uint4*)g_cwTh)[i];
        *(uint4*)(sm + O_CWL + k * 528 + c * 16) = ((const uint4*)g_cwTl)[i];
    }
    issue_xf(0);

    float accv[2][4][4];
#pragma unroll
    for (int mt = 0; mt < 2; mt++)
#pragma unroll
        for (int nt = 0; nt < 4; nt++)
#pragma unroll
            for (int q = 0; q < 4; q++) accv[mt][nt][q] = 0.f;
    float s0 = 0.f, s1 = 0.f;
    float cb0 = cb[lane], cb1 = cb[lane + 32];

    for (int kb = 0; kb < 8; kb++) {
        CP_WAIT0();
        __syncthreads();
        int n0 = kb * 64;
        // ---- convert staging -> split-bf16 ----
        for (int i = tid; i < 4096; i += NV_T) {
            int row = i >> 6, c4 = i & 63;
            int gn = n0 + row;
            float4 v = make_float4(0.f, 0.f, 0.f, 0.f);
            if (gn < NUM_KP) v = *(const float4*)(xf + row * 256 + c4 * 4);
            float v0 = sanit(v.x), v1 = sanit(v.y), v2 = sanit(v.z), v3 = sanit(v.w);
            uint32_t h01 = cvt2(v1, v0);
            uint32_t h23 = cvt2(v3, v2);
            uint32_t l01 = cvt2(v1 - bf_hi_f32(h01), v0 - bf_lo_f32(h01));
            uint32_t l23 = cvt2(v3 - bf_hi_f32(h23), v2 - bf_lo_f32(h23));
            char* pxh = sm + O_XH + row * 528 + c4 * 8;
            char* pxl = sm + O_XL + row * 528 + c4 * 8;
            *(uint32_t*)pxh       = h01;
            *(uint32_t*)(pxh + 4) = h23;
            *(uint32_t*)pxl       = l01;
            *(uint32_t*)(pxl + 4) = l23;
        }
        __syncthreads();
        if (kb + 1 < 8) issue_xf(kb + 1);
        else            issue_cw2();

        // ---- logits GEMM: C[n=64][k=64], warp tile 16x16 ----
        float acc[2][4];
#pragma unroll
        for (int nt = 0; nt < 2; nt++)
#pragma unroll
            for (int q = 0; q < 4; q++) acc[nt][q] = 0.f;
#pragma unroll
        for (int ks = 0; ks < 16; ks++) {
            int kl = ks * 16;
            uint32_t aoff = (uint32_t)(rowA_log * 528 + (kl + s16) * 2);
            uint32_t a[4], al_[4];
            ldm_x4(a,  xh_s + aoff);
            ldm_x4(al_, xl_s + aoff);
            uint32_t boff = (uint32_t)((wn * 16 + rowB_nt) * 528 + (kl + s8) * 2);
            uint32_t bh4[4], bl4[4];
            ldm_x4(bh4, cwh_s + boff);
            ldm_x4(bl4, cwl_s + boff);
            mma16816(acc[0], a,   bh4);
            mma16816(acc[0], a,   bl4);
            mma16816(acc[0], al_, bh4);
            mma16816(acc[1], a,   bh4 + 2);
            mma16816(acc[1], a,   bl4 + 2);
            mma16816(acc[1], al_, bh4 + 2);
        }
#pragma unroll
        for (int nt = 0; nt < 2; nt++)
#pragma unroll
            for (int q = 0; q < 4; q++) {
                int row = wm * 16 + lr + ((q >> 1) * 8);
                int col = wn * 16 + nt * 8 + lc + (q & 1);
                logit[row * 68 + col] = acc[nt][q];
            }
        __syncthreads();

        // ---- softmax: 4 rows per warp ----
        float l0r[4], l1r[4];
#pragma unroll
        for (int rr = 0; rr < 4; rr++) {
            int row = wid * 4 + rr;
            l0r[rr] = logit[row * 68 + lane] + cb0;
            l1r[rr] = logit[row * 68 + lane + 32] + cb1;
        }
        __syncthreads();
#pragma unroll
        for (int rr = 0; rr < 4; rr++) {
            int row = wid * 4 + rr;
            int gn = n0 + row;
            float e0 = __expf(l0r[rr]), e1 = __expf(l1r[rr]);
            float ss = e0 + e1;
#pragma unroll
            for (int off = 16; off; off >>= 1) ss += __shfl_xor_sync(0xFFFFFFFFu, ss, off);
            float inv = 1.f / ss;
            if (gn < NUM_KP) { e0 *= inv; e1 *= inv; s0 += e0; s1 += e1; }
            else             { e0 = 0.f;  e1 = 0.f; }
            __nv_bfloat16 h0 = __float2bfloat16(e0);
            __nv_bfloat16 h1 = __float2bfloat16(e1);
            *(__nv_bfloat16*)(sm + O_ACTH + lane * 144 + row * 2)        = h0;
            *(__nv_bfloat16*)(sm + O_ACTH + (lane + 32) * 144 + row * 2) = h1;
            *(__nv_bfloat16*)(sm + O_ACTL + lane * 144 + row * 2) =
                __float2bfloat16(e0 - __bfloat162float(h0));
            *(__nv_bfloat16*)(sm + O_ACTL + (lane + 32) * 144 + row * 2) =
                __float2bfloat16(e1 - __bfloat162float(h1));
        }
        __syncthreads();

        // ---- vlad GEMM: C[d=256][k=64], warp tile 32x32 ----
#pragma unroll
        for (int ks = 0; ks < 4; ks++) {
            int kl = ks * 16;
            uint32_t bh4[2][4], bl4[2][4];
#pragma unroll
            for (int ntp = 0; ntp < 2; ntp++) {
                uint32_t boff = (uint32_t)((wn2 * 32 + ntp * 16 + rowB_nt) * 144 + (kl + s8) * 2);
                ldm_x4(bh4[ntp], ah_s + boff);
                ldm_x4(bl4[ntp], al_s + boff);
            }
#pragma unroll
            for (int mt = 0; mt < 2; mt++) {
                uint32_t aoff = (uint32_t)((kl + rowX_n) * 528 + (wm2 * 32 + mt * 16 + s8) * 2);
                uint32_t a[4], al2[4];
                ldm_x4_t(a,   xh_s + aoff);
                ldm_x4_t(al2, xl_s + aoff);
#pragma unroll
                for (int ntp = 0; ntp < 2; ntp++) {
                    mma16816(accv[mt][2 * ntp],     a,   bh4[ntp]);
                    mma16816(accv[mt][2 * ntp],     a,   bl4[ntp]);
                    mma16816(accv[mt][2 * ntp],     al2, bh4[ntp]);
                    mma16816(accv[mt][2 * ntp + 1], a,   bh4[ntp] + 2);
                    mma16816(accv[mt][2 * ntp + 1], a,   bl4[ntp] + 2);
                    mma16816(accv[mt][2 * ntp + 1], al2, bh4[ntp] + 2);
                }
            }
        }
    }

    // ---- asum reduce; cw2 already streaming into XF ----
    red[wid * 64 + lane]      = s0;
    red[wid * 64 + lane + 32] = s1;
    CP_WAIT0();
    __syncthreads();
    if (tid < 32) {
        float t0 = 0.f, t1 = 0.f;
#pragma unroll
        for (int w = 0; w < 16; w++) { t0 += red[w * 64 + lane]; t1 += red[w * 64 + lane + 32]; }
        asums[lane] = t0; asums[lane + 32] = t1;
    }
    __syncthreads();
    const float* cw2s = xf;

#pragma unroll
    for (int mt = 0; mt < 2; mt++)
#pragma unroll
        for (int nt = 0; nt < 4; nt++)
#pragma unroll
            for (int q = 0; q < 4; q++) {
                int d = wm2 * 32 + mt * 16 + lr + ((q >> 1) * 8);
                int k = wn2 * 32 + nt * 8 + lc + (q & 1);
                accv[mt][nt][q] -= asums[k] * cw2s[d * 64 + k];
            }
#pragma unroll
    for (int nt = 0; nt < 4; nt++) {
        float sq0 = 0.f, sq1 = 0.f;
#pragma unroll
        for (int mt = 0; mt < 2; mt++) {
            sq0 += accv[mt][nt][0] * accv[mt][nt][0] + accv[mt][nt][2] * accv[mt][nt][2];
            sq1 += accv[mt][nt][1] * accv[mt][nt][1] + accv[mt][nt][3] * accv[mt][nt][3];
        }
        sq0 += __shfl_xor_sync(0xFFFFFFFFu, sq0, 4);
        sq0 += __shfl_xor_sync(0xFFFFFFFFu, sq0, 8);
        sq0 += __shfl_xor_sync(0xFFFFFFFFu, sq0, 16);
        sq1 += __shfl_xor_sync(0xFFFFFFFFu, sq1, 4);
        sq1 += __shfl_xor_sync(0xFFFFFFFFu, sq1, 8);
        sq1 += __shfl_xor_sync(0xFFFFFFFFu, sq1, 16);
        if (lr == 0) {
            int k0 = wn2 * 32 + nt * 8 + lc;
            redk[k0 * 8 + wm2]       = sq0;
            redk[(k0 + 1) * 8 + wm2] = sq1;
        }
    }
    __syncthreads();
    if (tid < 32) {
        float q0 = 0.f, q1 = 0.f;
#pragma unroll
        for (int w = 0; w < 8; w++) {
            q0 += redk[lane * 8 + w];
            q1 += redk[(lane + 32) * 8 + w];
        }
        float i0 = 1.f / (sqrtf(q0) + 1e-12f);
        float i1 = 1.f / (sqrtf(q1) + 1e-12f);
        invk[lane] = i0; invk[lane + 32] = i1;
        float tt = q0 * i0 * i0 + q1 * i1 * i1;
#pragma unroll
        for (int off = 16; off; off >>= 1) tt += __shfl_xor_sync(0xFFFFFFFFu, tt, off);
        if (lane == 0) invts[0] = 1.f / (sqrtf(tt) + 1e-12f);
    }
    __syncthreads();
    float invt = invts[0];

#pragma unroll
    for (int mt = 0; mt < 2; mt++)
#pragma unroll
        for (int nt = 0; nt < 4; nt++)
#pragma unroll
            for (int q = 0; q < 4; q += 2) {
                int d = wm2 * 32 + mt * 16 + lr + ((q >> 1) * 8);
                int k = wn2 * 32 + nt * 8 + lc;
                float va = accv[mt][nt][q]     * invk[k]     * invt;
                float vb = accv[mt][nt][q + 1] * invk[k + 1] * invt;
                uint32_t h = cvt2(vb, va);
                uint32_t l = cvt2(vb - bf_hi_f32(h), va - bf_lo_f32(h));
                *(uint32_t*)(sm + O_XH + (d * 66 + k) * 2) = h;
                *(uint32_t*)(sm + O_XL + (d * 66 + k) * 2) = l;
            }
    __syncthreads();
    for (int i = tid; i < 8192; i += NV_T) {
        int d = i >> 5, kp = i & 31;
        uint32_t vh = lds32(xh_s + (uint32_t)(d * 66 + kp * 2) * 2);
        uint32_t vl = lds32(xl_s + (uint32_t)(d * 66 + kp * 2) * 2);
        size_t go = (size_t)b * VLAD_DIM + d * 64 + kp * 2;
        *(uint32_t*)((char*)g_Ah + go * 2) = vh;
        *(uint32_t*)((char*)g_Al + go * 2) = vl;
    }
}

// ---------------------------------------------------------------------------
// Transpose + split: src[k][n] fp32 -> dh/dl[n][k] bf16 (pads zero-filled).
// ---------------------------------------------------------------------------
__global__ void __launch_bounds__(256) k_cvt_trans(
    const float* __restrict__ src, int ldsrc, int Kreal, int Nreal,
    __nv_bfloat16* __restrict__ dh, __nv_bfloat16* __restrict__ dl, int ldd)
{
    __shared__ float smt[32][33];
    int k0 = blockIdx.x * 32;
    int n0 = blockIdx.y * 32;
    int tx = threadIdx.x & 31;
    int ty = threadIdx.x >> 5;
#pragma unroll
    for (int i = 0; i < 4; i++) {
        int kk = ty + i * 8;
        int n = n0 + tx;
        float v = (k0 + kk < Kreal && n < Nreal) ? src[(size_t)(k0 + kk) * ldsrc + n] : 0.f;
        smt[kk][tx] = v;
    }
    __syncthreads();
#pragma unroll
    for (int i = 0; i < 4; i++) {
        int nn = ty + i * 8;
        float v = smt[tx][nn];
        __nv_bfloat16 h = __float2bfloat16(v);
        __nv_bfloat16 l = __float2bfloat16(v - __bfloat162float(h));
        size_t o = (size_t)(n0 + nn) * ldd + k0 + tx;
        dh[o] = h;
        dl[o] = l;
    }
}

// ---------------------------------------------------------------------------
// Split-bf16 HMMA GEMM (unchanged, passing).
// ---------------------------------------------------------------------------
#define KBLK 64
#define SPITCH 72
#define SPB (SPITCH * 2)
#define TILE_B (128 * SPB)
#define STAGE_B (4 * TILE_B)
#define MMA_SMEM_TOTAL (2 * STAGE_B)

__global__ void __launch_bounds__(256, 1) k_mma(
    const __nv_bfloat16* __restrict__ Ah, const __nv_bfloat16* __restrict__ Al,
    const __nv_bfloat16* __restrict__ Bh, const __nv_bfloat16* __restrict__ Bl,
    int K, float* __restrict__ C, int M, int N,
    const float* __restrict__ bias, int act,
    __nv_bfloat16* __restrict__ Dh, __nv_bfloat16* __restrict__ Dl, int ldd)
{
    extern __shared__ __align__(16) char smem[];
    uint32_t sb = smem_u32(smem);
    int tid = threadIdx.x;
    int wid = tid >> 5, lane = tid & 31;
    int wm = wid & 3;
    int wn = wid >> 2;
    int m0 = blockIdx.y * 128;
    int n0 = blockIdx.x * 128;

    const __nv_bfloat16* srcs[4] = {
        Ah + (size_t)m0 * K, Al + (size_t)m0 * K,
        Bh + (size_t)n0 * K, Bl + (size_t)n0 * K };

    int lrow = tid >> 3;
    int lchk = tid & 7;

    int l7  = lane & 7;
    int s8  = (lane & 8) ? 8 : 0;
    int s16 = (lane & 16) ? 8 : 0;

    float acc[2][8][4];
#pragma unroll
    for (int i = 0; i < 2; i++)
#pragma unroll
        for (int j = 0; j < 8; j++)
#pragma unroll
            for (int q = 0; q < 4; q++) acc[i][j][q] = 0.f;

    auto load_stage = [&](int s, int kb) {
        uint32_t sd = sb + s * STAGE_B;
        size_t kOff = (size_t)kb * KBLK;
#pragma unroll
        for (int v = 0; v < 4; v++) {
            const __nv_bfloat16* g = srcs[v] + kOff;
#pragma unroll
            for (int p = 0; p < 4; p++) {
                int rr = lrow + p * 32;
                uint32_t d = sd + v * TILE_B + rr * SPB + lchk * 16;
                const void* sptr = (const char*)(g + (size_t)rr * K) + lchk * 16;
                CP_ASYNC16(d, sptr);
            }
        }
        CP_COMMIT();
    };

    load_stage(0, 0);

    int lr = lane >> 2;
    int lc = (lane & 3) * 2;
    int nkb = K / KBLK;

    for (int kb = 0; kb < nkb; kb++) {
        int s = kb & 1;
        CP_WAIT0();
        __syncthreads();
        if (kb + 1 < nkb) load_stage(s ^ 1, kb + 1);

        uint32_t sAh = sb + s * STAGE_B;
        uint32_t sAl = sAh + TILE_B;
        uint32_t sBh = sAh + 2 * TILE_B;
        uint32_t sBl = sAh + 3 * TILE_B;

#pragma unroll
        for (int ks = 0; ks < 4; ks++) {
            int kl = ks * 16;
            uint32_t ah4[2][4], al4[2][4];
#pragma unroll
            for (int mt = 0; mt < 2; mt++) {
                uint32_t aoff = (uint32_t)((wm * 32 + mt * 16 + l7 + s8) * SPB + (kl + s16) * 2);
                ldm_x4(ah4[mt], sAh + aoff);
                ldm_x4(al4[mt], sAl + aoff);
            }
            uint32_t bh4[4][4], bl4[4][4];
#pragma unroll
            for (int ntp = 0; ntp < 4; ntp++) {
                uint32_t boff = (uint32_t)((wn * 64 + ntp * 16 + l7 + s16) * SPB + (kl + s8) * 2);
                ldm_x4(bh4[ntp], sBh + boff);
                ldm_x4(bl4[ntp], sBl + boff);
            }
#pragma unroll
            for (int mt = 0; mt < 2; mt++)
#pragma unroll
                for (int ntp = 0; ntp < 4; ntp++) {
                    mma16816(acc[mt][2 * ntp],     ah4[mt], bh4[ntp]);
                    mma16816(acc[mt][2 * ntp],     ah4[mt], bl4[ntp]);
                    mma16816(acc[mt][2 * ntp],     al4[mt], bh4[ntp]);
                    mma16816(acc[mt][2 * ntp + 1], ah4[mt], bh4[ntp] + 2);
                    mma16816(acc[mt][2 * ntp + 1], ah4[mt], bl4[ntp] + 2);
                    mma16816(acc[mt][2 * ntp + 1], al4[mt], bh4[ntp] + 2);
                }
        }
    }

    auto emit = [&](int r, int c, float v) {
        bool in = (r < M && c < N);
        float val = 0.f;
        if (in) {
            val = v + (bias ? bias[c] : 0.f);
            if (act == 1) val = fmaxf(val, 0.f);
            if (C) C[(size_t)r * N + c] = val;
        }
        if (Dh) {
            __nv_bfloat16 h = __float2bfloat16(val);
            Dh[(size_t)r * ldd + c] = h;
            Dl[(size_t)r * ldd + c] = __float2bfloat16(val - __bfloat162float(h));
        }
    };
#pragma unroll
    for (int mt = 0; mt < 2; mt++) {
#pragma unroll
        for (int nt = 0; nt < 8; nt++) {
            int r = m0 + wm * 32 + mt * 16 + lr;
            int c = n0 + wn * 64 + nt * 8 + lc;
            emit(r,     c,     acc[mt][nt][0]);
            emit(r,     c + 1, acc[mt][nt][1]);
            emit(r + 8, c,     acc[mt][nt][2]);
            emit(r + 8, c + 1, acc[mt][nt][3]);
        }
    }
}

// ---------------------------------------------------------------------------
// GAT kernels (R12-measured path; gat_fin of layers 0/1 folded into k_gat_h2).
// ---------------------------------------------------------------------------
__device__ __forceinline__ void gat_h_core(
    float xv, int b, int t,
    const float* __restrict__ W, const float* __restrict__ a_s,
    const float* __restrict__ a_d, float* xsm, float* rs)
{
    xsm[t] = xv;
    g_aggr[b * NODE_D + t] = 0.f;
    if (t == 0) g_den[b] = 0.f;
    __syncthreads();
    float acc = 0.f;
#pragma unroll 8
    for (int d = 0; d < NODE_D; d++) acc = fmaf(xsm[d], __ldg(&W[d * NODE_D + t]), acc);
    g_h[b * NODE_D + t] = acc;
    float ps = acc * __ldg(&a_s[t]);
    float pd = acc * __ldg(&a_d[t]);
#pragma unroll
    for (int off = 16; off; off >>= 1) {
        ps += __shfl_xor_sync(0xFFFFFFFFu, ps, off);
        pd += __shfl_xor_sync(0xFFFFFFFFu, pd, off);
    }
    if ((t & 31) == 0) { rs[t >> 5] = ps; rs[4 + (t >> 5)] = pd; }
    __syncthreads();
    if (t == 0) g_es[b] = rs[0] + rs[1] + rs[2] + rs[3];
    if (t == 1) g_ed[b] = rs[4] + rs[5] + rs[6] + rs[7];
}

__global__ void __launch_bounds__(128) k_gat_h(
    const float* __restrict__ W, const float* __restrict__ a_s,
    const float* __restrict__ a_d)
{
    int b = blockIdx.x, t = threadIdx.x;
    __shared__ float xsm[NODE_D];
    __shared__ float rs[8];
    gat_h_core(g_x[b * NODE_D + t], b, t, W, a_s, a_d, xsm, rs);
}

__global__ void __launch_bounds__(128) k_gat_h2(
    const float* __restrict__ W, const float* __restrict__ a_s,
    const float* __restrict__ a_d, const float* __restrict__ bprev)
{
    int b = blockIdx.x, t = threadIdx.x;
    __shared__ float xsm[NODE_D];
    __shared__ float rs[8];
    float v = g_aggr[b * NODE_D + t] + __ldg(&bprev[t]);
    v = (v > 0.f) ? v : (__expf(v) - 1.f);
    gat_h_core(v, b, t, W, a_s, a_d, xsm, rs);
}

__global__ void k_edge12(const int* __restrict__ ei)
{
    int e = blockIdx.x * blockDim.x + threadIdx.x;
    if (e >= E_EXT) return;
    int s, d;
    if (e < N_EDGES) { s = ei[e]; d = ei[N_EDGES + e]; }
    else { s = e - N_EDGES; d = s; }
    float v = g_es[s] + g_ed[d];
    v = (v > 0.f) ? v : 0.2f * v;
    float ex = __expf(v);
    g_ex[e] = ex;
    atomicAdd(&g_den[d], ex);
}

__global__ void k_edge3(const int* __restrict__ ei)
{
    int gt = blockIdx.x * blockDim.x + threadIdx.x;
    int w = gt >> 5, lane = gt & 31;
    if (w >= E_EXT) return;
    int s, d;
    if (w < N_EDGES) { s = ei[w]; d = ei[N_EDGES + w]; }
    else { s = w - N_EDGES; d = s; }
    float alpha = g_ex[w] / g_den[d];
#pragma unroll
    for (int i = 0; i < 4; i++) {
        int c = lane + 32 * i;
        atomicAdd(&g_aggr[d * NODE_D + c], g_h[s * NODE_D + c] * alpha);
    }
}

__global__ void k_gat_fin(const float* __restrict__ b)
{
    int i = blockIdx.x * blockDim.x + threadIdx.x;
    if (i >= N_NODES * NODE_D) return;
    float v = g_aggr[i] + __ldg(&b[i & (NODE_D - 1)]);
    g_x[i] = (v > 0.f) ? v : (__expf(v) - 1.f);
}

// ---------------------------------------------------------------------------
// Edge-attr MLP: 1 -> 8 -> 16 -> 32 (unchanged)
// ---------------------------------------------------------------------------
__global__ void __launch_bounds__(256) k_ef(
    const float* __restrict__ ea,
    const float* __restrict__ w1, const float* __restrict__ b1,
    const float* __restrict__ w2, const float* __restrict__ b2,
    const float* __restrict__ w3, const float* __restrict__ b3)
{
    __shared__ float w1s[8], b1s[8], w2s[128], b2s[16], w3s[512], b3s[32];
    int t = threadIdx.x;
    if (t < 8)   { w1s[t] = w1[t]; b1s[t] = b1[t]; }
    if (t < 128) w2s[t] = w2[t];
    if (t < 16)  b2s[t] = b2[t];
    if (t < 32)  b3s[t] = b3[t];
    for (int i = t; i < 512; i += blockDim.x) w3s[i] = w3[i];
    __syncthreads();
    int e = blockIdx.x * blockDim.x + t;
    if (e >= N_EDGES) return;
    float a = ea[e];
    float t8[8];
#pragma unroll
    for (int j = 0; j < 8; j++) t8[j] = fmaxf(fmaf(a, w1s[j], b1s[j]), 0.f);
    float t16[16];
#pragma unroll
    for (int c = 0; c < 16; c++) {
        float acc = b2s[c];
#pragma unroll
        for (int j = 0; j < 8; j++) acc = fmaf(t8[j], w2s[j * 16 + c], acc);
        t16[c] = fmaxf(acc, 0.f);
    }
#pragma unroll
    for (int c = 0; c < 32; c++) {
        float acc = b3s[c];
#pragma unroll
        for (int j = 0; j < 16; j++) acc = fmaf(t16[j], w3s[j * 32 + c], acc);
        g_ef2[e * EDGE_D + c] = acc;
    }
}

// ---------------------------------------------------------------------------
// Final fused edge classifier (unchanged).
// ---------------------------------------------------------------------------
__global__ void __launch_bounds__(256) k_final(
    const int* __restrict__ ei,
    const float* __restrict__ dp_w, const float* __restrict__ dp_b,
    const float* __restrict__ ec_w1, const float* __restrict__ ec_b1,
    const float* __restrict__ ec_w2, const float* __restrict__ ec_b2,
    float* __restrict__ out)
{
    __shared__ float dpw_s[288 * 32];
    __shared__ float ecw1_s[32 * 16];
    __shared__ float dpb_s[32];
    __shared__ float ecb1_s[16];
    __shared__ float ecw2_s[16];
    __shared__ float vec_s[8][292];
    __shared__ float o32_s[8][32];

    int tid = threadIdx.x;
    for (int i = tid; i < 288 * 32; i += 256) dpw_s[i] = dp_w[i];
    for (int i = tid; i < 512; i += 256) ecw1_s[i] = ec_w1[i];
    if (tid < 32) dpb_s[tid] = dp_b[tid];
    if (tid < 16) { ecb1_s[tid] = ec_b1[tid]; ecw2_s[tid] = ec_w2[tid]; }
    __syncthreads();

    float b2 = __ldg(ec_b2);
    int warp = tid >> 5, lane = tid & 31;
    int gw = blockIdx.x * 8 + warp;
    int nw = gridDim.x * 8;

    for (int e = gw; e < N_EDGES; e += nw) {
        int s = ei[e], d = ei[N_EDGES + e];
        const float* xsp = g_x + s * NODE_D;
        const float* xdp = g_x + d * NODE_D;
#pragma unroll
        for (int i = 0; i < 4; i++) {
            vec_s[warp][lane + 32 * i]       = xsp[lane + 32 * i];
            vec_s[warp][128 + lane + 32 * i] = xdp[lane + 32 * i];
        }
        vec_s[warp][256 + lane] = g_ef2[e * EDGE_D + lane];
        __syncwarp();

        float acc = dpb_s[lane];
#pragma unroll 4
        for (int i = 0; i < 288; i++) acc = fmaf(vec_s[warp][i], dpw_s[i * 32 + lane], acc);
        o32_s[warp][lane] = acc;
        __syncwarp();

        float hh = 0.f;
        if (lane < 16) {
            hh = ecb1_s[lane];
#pragma unroll 4
            for (int j = 0; j < 32; j++) hh = fmaf(o32_s[warp][j], ecw1_s[j * 16 + lane], hh);
            hh = fmaxf(hh, 0.f) * ecw2_s[lane];
        }
#pragma unroll
        for (int off = 8; off; off >>= 1) hh += __shfl_xor_sync(0xFFFFFFFFu, hh, off);
        if (lane == 0) out[e] = 1.f / (1.f + __expf(-(hh + b2)));
        __syncwarp();
    }
}

// ---------------------------------------------------------------------------
extern "C" void kernel_launch(void* const* d_in, const int* in_sizes, int n_in,
                              void* d_out, int out_size)
{
    (void)in_sizes; (void)n_in; (void)out_size;
    const float* node_feats = (const float*)d_in[0];
    const float* edge_attr  = (const float*)d_in[1];
    const float* nv_cw      = (const float*)d_in[2];
    const float* nv_cb      = (const float*)d_in[3];
    const float* nv_cw2     = (const float*)d_in[4];
    const float* nv_hw      = (const float*)d_in[5];
    const float* ne_w1      = (const float*)d_in[6];
    const float* ne_b1      = (const float*)d_in[7];
    const float* ne_w2      = (const float*)d_in[8];
    const float* ne_b2      = (const float*)d_in[9];
    const float* ee_w1      = (const float*)d_in[10];
    const float* ee_b1      = (const float*)d_in[11];
    const float* ee_w2      = (const float*)d_in[12];
    const float* ee_b2      = (const float*)d_in[13];
    const float* ee_w3      = (const float*)d_in[14];
    const float* ee_b3      = (const float*)d_in[15];
    const float* gat_w      = (const float*)d_in[16];
    const float* gat_as     = (const float*)d_in[17];
    const float* gat_ad     = (const float*)d_in[18];
    const float* gat_b      = (const float*)d_in[19];
    const float* dp_w       = (const float*)d_in[20];
    const float* dp_b       = (const float*)d_in[21];
    const float* ec_w1      = (const float*)d_in[22];
    const float* ec_b1      = (const float*)d_in[23];
    const float* ec_w2      = (const float*)d_in[24];
    const float* ec_b2      = (const float*)d_in[25];
    const int*   edge_index = (const int*)d_in[26];
    float* out = (float*)d_out;

    float* p_x;
    __nv_bfloat16 *p_Ah, *p_Al, *p_Bh, *p_Bl;
    __nv_bfloat16 *p_Ah2, *p_Al2, *p_Bh2, *p_Bl2;
    __nv_bfloat16 *p_Ah3, *p_Al3, *p_Bh3, *p_Bl3;
    cudaGetSymbolAddress((void**)&p_x, g_x);
    cudaGetSymbolAddress((void**)&p_Ah, g_Ah);
    cudaGetSymbolAddress((void**)&p_Al, g_Al);
    cudaGetSymbolAddress((void**)&p_Bh, g_Bh);
    cudaGetSymbolAddress((void**)&p_Bl, g_Bl);
    cudaGetSymbolAddress((void**)&p_Ah2, g_Ah2);
    cudaGetSymbolAddress((void**)&p_Al2, g_Al2);
    cudaGetSymbolAddress((void**)&p_Bh2, g_Bh2);
    cudaGetSymbolAddress((void**)&p_Bl2, g_Bl2);
    cudaGetSymbolAddress((void**)&p_Ah3, g_Ah3);
    cudaGetSymbolAddress((void**)&p_Al3, g_Al3);
    cudaGetSymbolAddress((void**)&p_Bh3, g_Bh3);
    cudaGetSymbolAddress((void**)&p_Bl3, g_Bl3);

    static int s_init = 0;
    static cudaStream_t s2;
    static cudaEvent_t ev1, ev2;
    if (!s_init) {
        cudaFuncSetAttribute(k_mma, cudaFuncAttributeMaxDynamicSharedMemorySize, MMA_SMEM_TOTAL);
        cudaFuncSetAttribute(k_nv, cudaFuncAttributeMaxDynamicSharedMemorySize, NV_SMEM);
        cudaStreamCreateWithFlags(&s2, cudaStreamNonBlocking);
        cudaEventCreateWithFlags(&ev1, cudaEventDisableTiming);
        cudaEventCreateWithFlags(&ev2, cudaEventDisableTiming);
        s_init = 1;
    }

    // fork: B conversions + edge MLP run concurrently with NetVLAD
    cudaEventRecord(ev1, 0);
    cudaStreamWaitEvent(s2, ev1, 0);
    {
        dim3 g(VLAD_DIM / 32, N_PAD / 32);
        k_cvt_trans<<<g, 256, 0, s2>>>(nv_hw, H0D, VLAD_DIM, H0D, p_Bh, p_Bl, VLAD_DIM);
    }
    {
        dim3 g(K2PAD / 32, N2PAD / 32);
        k_cvt_trans<<<g, 256, 0, s2>>>(ne_w1, H1D, H0D, H1D, p_Bh2, p_Bl2, K2PAD);
    }
    {
        dim3 g(K3PAD / 32, N3PAD / 32);
        k_cvt_trans<<<g, 256, 0, s2>>>(ne_w2, NODE_D, H1D, NODE_D, p_Bh3, p_Bl3, K3PAD);
    }
    k_ef<<<(N_EDGES + 255) / 256, 256, 0, s2>>>(edge_attr, ee_w1, ee_b1, ee_w2, ee_b2,
                                                ee_w3, ee_b3);
    cudaEventRecord(ev2, s2);

    // main stream: NetVLAD (512 threads)
    k_prep_cw<<<64, 256>>>(nv_cw);
    k_nv<<<N_NODES, NV_T, NV_SMEM>>>(node_feats, nv_cb, nv_cw2);

    // join before G1
    cudaStreamWaitEvent(0, ev2, 0);

    // G1 HMMA: h0 = vlad @ hw -> split-bf16 A operand of G2
    {
        dim3 g(N_PAD / 128, M_PAD / 128);
        k_mma<<<g, 256, MMA_SMEM_TOTAL>>>(p_Ah, p_Al, p_Bh, p_Bl, VLAD_DIM,
                                          nullptr, N_NODES, H0D, nullptr, 0,
                                          p_Ah2, p_Al2, K2PAD);
    }
    // G2 HMMA: h1 = relu(h0 @ ne_w1 + b1) -> split-bf16 A operand of G3
    {
        dim3 g(N2PAD / 128, M_PAD / 128);
        k_mma<<<g, 256, MMA_SMEM_TOTAL>>>(p_Ah2, p_Al2, p_Bh2, p_Bl2, K2PAD,
                                          nullptr, N_NODES, H1D, ne_b1, 1,
                                          p_Ah3, p_Al3, K3PAD);
    }
    // G3 HMMA: x = h1 @ ne_w2 + b2
    {
        dim3 g(1, M_PAD / 128);
        k_mma<<<g, 256, MMA_SMEM_TOTAL>>>(p_Ah3, p_Al3, p_Bh3, p_Bl3, K3PAD,
                                          p_x, N_NODES, NODE_D, ne_b2, 0,
                                          nullptr, nullptr, 0);
    }

    // 3 GAT layers; elu+bias of layers 0/1 folded into the next k_gat_h2
    for (int l = 0; l < DEPTH; l++) {
        if (l == 0)
            k_gat_h<<<N_NODES, 128>>>(gat_w, gat_as, gat_ad);
        else
            k_gat_h2<<<N_NODES, 128>>>(gat_w + l * NODE_D * NODE_D,
                                       gat_as + l * NODE_D, gat_ad + l * NODE_D,
                                       gat_b + (l - 1) * NODE_D);
        k_edge12<<<(E_EXT + 255) / 256, 256>>>(edge_index);
        k_edge3<<<((E_EXT * 32) + 255) / 256, 256>>>(edge_index);
    }
    k_gat_fin<<<(N_NODES * NODE_D + 255) / 256, 256>>>(gat_b + 2 * NODE_D);

    // fused edge classifier -> out
    k_final<<<256, 256>>>(edge_index, dp_w, dp_b, ec_w1, ec_b1, ec_w2, ec_b2, out);
}

// round 17
// speedup vs baseline: 1.0658x; 1.0166x over previous
#include <cuda_runtime.h>
#include <cuda_bf16.h>
#include <math.h>
#include <stdint.h>

#define N_NODES 2000
#define NUM_KP 500
#define DESC 256
#define NVK 64
#define VLAD_DIM (DESC*NVK)        // 16384
#define H0D (NUM_KP*2)             // 1000
#define H1D NUM_KP                 // 500
#define NODE_D 128
#define EDGE_D 32
#define N_EDGES 64000
#define E_EXT (N_EDGES + N_NODES)  // 66000
#define DEPTH 3

#define M_PAD 2048
#define N_PAD 1024
#define K2PAD 1024
#define N2PAD 512
#define K3PAD 512
#define N3PAD 128

typedef unsigned long long u64;

// ---------------- scratch (device globals; no runtime allocation) ----------
__device__ float    g_x[N_NODES * NODE_D];
__device__ float    g_h[N_NODES * NODE_D];
__device__ float    g_es[N_NODES];
__device__ float    g_ed[N_NODES];
__device__ float    g_ex[E_EXT];
__device__ float    g_den[N_NODES];
__device__ float    g_aggr[N_NODES * NODE_D];
__device__ float    g_ef2[N_EDGES * EDGE_D];
// split-bf16 operands (pad regions stay zero: static zero-init, never written)
__device__ __nv_bfloat16 g_Ah[(size_t)M_PAD * VLAD_DIM];
__device__ __nv_bfloat16 g_Al[(size_t)M_PAD * VLAD_DIM];
__device__ __nv_bfloat16 g_Bh[(size_t)N_PAD * VLAD_DIM];
__device__ __nv_bfloat16 g_Bl[(size_t)N_PAD * VLAD_DIM];
__device__ __nv_bfloat16 g_Ah2[(size_t)M_PAD * K2PAD];
__device__ __nv_bfloat16 g_Al2[(size_t)M_PAD * K2PAD];
__device__ __nv_bfloat16 g_Bh2[(size_t)N2PAD * K2PAD];
__device__ __nv_bfloat16 g_Bl2[(size_t)N2PAD * K2PAD];
__device__ __nv_bfloat16 g_Ah3[(size_t)M_PAD * K3PAD];
__device__ __nv_bfloat16 g_Al3[(size_t)M_PAD * K3PAD];
__device__ __nv_bfloat16 g_Bh3[(size_t)N3PAD * K3PAD];
__device__ __nv_bfloat16 g_Bl3[(size_t)N3PAD * K3PAD];
__device__ __nv_bfloat16 g_cwTh[NVK * DESC];
__device__ __nv_bfloat16 g_cwTl[NVK * DESC];

// ---------------- helpers ---------------------------------------------------
__device__ __forceinline__ uint32_t smem_u32(const void* p) {
    uint32_t a;
    asm("{ .reg .u64 t; cvta.to.shared.u64 t, %1; cvt.u32.u64 %0, t; }" : "=r"(a) : "l"(p));
    return a;
}
__device__ __forceinline__ uint32_t lds32(uint32_t addr) {
    uint32_t v;
    asm volatile("ld.shared.b32 %0, [%1];" : "=r"(v) : "r"(addr));
    return v;
}
__device__ __forceinline__ void ldm_x4(uint32_t* r, uint32_t addr) {
    asm volatile("ldmatrix.sync.aligned.m8n8.x4.shared.b16 {%0,%1,%2,%3}, [%4];"
        : "=r"(r[0]), "=r"(r[1]), "=r"(r[2]), "=r"(r[3]) : "r"(addr));
}
__device__ __forceinline__ void ldm_x4_t(uint32_t* r, uint32_t addr) {
    asm volatile("ldmatrix.sync.aligned.m8n8.x4.trans.shared.b16 {%0,%1,%2,%3}, [%4];"
        : "=r"(r[0]), "=r"(r[1]), "=r"(r[2]), "=r"(r[3]) : "r"(addr));
}
__device__ __forceinline__ void mma16816(float* c, const uint32_t* a, const uint32_t* b) {
    asm volatile(
        "mma.sync.aligned.m16n8k16.row.col.f32.bf16.bf16.f32 "
        "{%0,%1,%2,%3}, {%4,%5,%6,%7}, {%8,%9}, {%0,%1,%2,%3};"
        : "+f"(c[0]), "+f"(c[1]), "+f"(c[2]), "+f"(c[3])
        : "r"(a[0]), "r"(a[1]), "r"(a[2]), "r"(a[3]), "r"(b[0]), "r"(b[1]));
}
__device__ __forceinline__ uint32_t cvt2(float hi, float lo) {
    uint32_t r;
    asm("cvt.rn.bf16x2.f32 %0, %1, %2;" : "=r"(r) : "f"(hi), "f"(lo));
    return r;
}
__device__ __forceinline__ float bf_lo_f32(uint32_t p) { return __uint_as_float(p << 16); }
__device__ __forceinline__ float bf_hi_f32(uint32_t p) { return __uint_as_float(p & 0xFFFF0000u); }

#define CP_ASYNC16(dst, src) \
    asm volatile("cp.async.cg.shared.global [%0], [%1], 16;" :: "r"(dst), "l"(src) : "memory")
#define CP_COMMIT()  asm volatile("cp.async.commit_group;" ::: "memory")
#define CP_WAIT0()   asm volatile("cp.async.wait_group 0;" ::: "memory")

__device__ __forceinline__ float sanit(float v) {
    if (!isfinite(v)) v = (v != v) ? 0.f : (v > 0.f ? 3.402823466e38f : -3.402823466e38f);
    return v;
}

// ---------------------------------------------------------------------------
// Prep: cw [256][64] fp32 -> cw^T split-bf16 [64][256]
// ---------------------------------------------------------------------------
__global__ void k_prep_cw(const float* __restrict__ cw)
{
    int i = blockIdx.x * 256 + threadIdx.x;    // 0..16383
    int k = i >> 8, d = i & 255;
    float v = cw[d * 64 + k];
    __nv_bfloat16 h = __float2bfloat16(v);
    g_cwTh[k * 256 + d] = h;
    g_cwTl[k * 256 + d] = __float2bfloat16(v - __bfloat162float(h));
}

// ---------------------------------------------------------------------------
// FUSED NetVLAD, 512 threads (R16, passing).
// ---------------------------------------------------------------------------
#define NV_T 512
#define O_CWH 0
#define O_CWL 33792
#define O_XH  67584
#define O_XL  101376
#define O_LOG 135168
#define O_ACTH 135168
#define O_ACTL 144384
#define O_RED 153600
#define O_ASUM 157696
#define O_REDK 157952
#define O_INVK 160000
#define O_INVT 160256
#define O_XF  160272
#define NV_SMEM 225808

__global__ void __launch_bounds__(NV_T, 1) k_nv(
    const float* __restrict__ feats, const float* __restrict__ cb,
    const float* __restrict__ cw2)
{
    extern __shared__ __align__(16) char sm[];
    int b = blockIdx.x;
    int tid = threadIdx.x, lane = tid & 31, wid = tid >> 5;
    int wm = wid & 3, wn = wid >> 2;
    int wm2 = wid & 7, wn2 = wid >> 3;
    int lr = lane >> 2, lc = (lane & 3) * 2;

    uint32_t cwh_s = smem_u32(sm + O_CWH), cwl_s = smem_u32(sm + O_CWL);
    uint32_t xh_s  = smem_u32(sm + O_XH),  xl_s  = smem_u32(sm + O_XL);
    uint32_t ah_s  = smem_u32(sm + O_ACTH), al_s = smem_u32(sm + O_ACTL);
    uint32_t xf_s  = smem_u32(sm + O_XF);
    float* logit = (float*)(sm + O_LOG);
    float* red   = (float*)(sm + O_RED);
    float* asums = (float*)(sm + O_ASUM);
    float* redk  = (float*)(sm + O_REDK);
    float* invk  = (float*)(sm + O_INVK);
    float* invts = (float*)(sm + O_INVT);
    const float* xf = (const float*)(sm + O_XF);

    int l7  = lane & 7;
    int s8  = (lane & 8) ? 8 : 0;
    int s16 = (lane & 16) ? 8 : 0;
    int rowA_log = wm * 16 + l7 + s8;
    int rowB_nt  = l7 + s16;
    int rowX_n   = l7 + s16;

    auto issue_xf = [&](int kbi) {
        int n0 = kbi * 64;
#pragma unroll
        for (int p = 0; p < 8; p++) {
            int idx = tid + p * NV_T;
            int row = idx >> 6;
            int c16 = idx & 63;
            int gn = n0 + row;
            if (gn < NUM_KP) {
                uint32_t d = xf_s + (uint32_t)(row * 1024 + c16 * 16);
                const char* src = (const char*)(feats + ((size_t)b * NUM_KP + gn) * DESC) + c16 * 16;
                CP_ASYNC16(d, src);
            }
        }
        CP_COMMIT();
    };
    auto issue_cw2 = [&]() {
#pragma unroll
        for (int p = 0; p < 8; p++) {
            int idx = tid + p * NV_T;
            CP_ASYNC16(xf_s + (uint32_t)idx * 16, (const char*)cw2 + (size_t)idx * 16);
        }
        CP_COMMIT();
    };

    for (int i = tid; i < 2048; i += NV_T) {
        int k = i >> 5, c = i & 31;
        *(uint4*)(sm + O_CWH + k * 528 + c * 16) = ((const uint4*)g_cwTh)[i];
        *(uint4*)(sm + O_CWL + k * 528 + c * 16) = ((const uint4*)g_cwTl)[i];
    }
    issue_xf(0);

    float accv[2][4][4];
#pragma unroll
    for (int mt = 0; mt < 2; mt++)
#pragma unroll
        for (int nt = 0; nt < 4; nt++)
#pragma unroll
            for (int q = 0; q < 4; q++) accv[mt][nt][q] = 0.f;
    float s0 = 0.f, s1 = 0.f;
    float cb0 = cb[lane], cb1 = cb[lane + 32];

    for (int kb = 0; kb < 8; kb++) {
        CP_WAIT0();
        __syncthreads();
        int n0 = kb * 64;
        for (int i = tid; i < 4096; i += NV_T) {
            int row = i >> 6, c4 = i & 63;
            int gn = n0 + row;
            float4 v = make_float4(0.f, 0.f, 0.f, 0.f);
            if (gn < NUM_KP) v = *(const float4*)(xf + row * 256 + c4 * 4);
            float v0 = sanit(v.x), v1 = sanit(v.y), v2 = sanit(v.z), v3 = sanit(v.w);
            uint32_t h01 = cvt2(v1, v0);
            uint32_t h23 = cvt2(v3, v2);
            uint32_t l01 = cvt2(v1 - bf_hi_f32(h01), v0 - bf_lo_f32(h01));
            uint32_t l23 = cvt2(v3 - bf_hi_f32(h23), v2 - bf_lo_f32(h23));
            char* pxh = sm + O_XH + row * 528 + c4 * 8;
            char* pxl = sm + O_XL + row * 528 + c4 * 8;
            *(uint32_t*)pxh       = h01;
            *(uint32_t*)(pxh + 4) = h23;
            *(uint32_t*)pxl       = l01;
            *(uint32_t*)(pxl + 4) = l23;
        }
        __syncthreads();
        if (kb + 1 < 8) issue_xf(kb + 1);
        else            issue_cw2();

        // ---- logits GEMM: warp tile 16x16 ----
        float acc[2][4];
#pragma unroll
        for (int nt = 0; nt < 2; nt++)
#pragma unroll
            for (int q = 0; q < 4; q++) acc[nt][q] = 0.f;
#pragma unroll
        for (int ks = 0; ks < 16; ks++) {
            int kl = ks * 16;
            uint32_t aoff = (uint32_t)(rowA_log * 528 + (kl + s16) * 2);
            uint32_t a[4], al_[4];
            ldm_x4(a,  xh_s + aoff);
            ldm_x4(al_, xl_s + aoff);
            uint32_t boff = (uint32_t)((wn * 16 + rowB_nt) * 528 + (kl + s8) * 2);
            uint32_t bh4[4], bl4[4];
            ldm_x4(bh4, cwh_s + boff);
            ldm_x4(bl4, cwl_s + boff);
            mma16816(acc[0], a,   bh4);
            mma16816(acc[0], a,   bl4);
            mma16816(acc[0], al_, bh4);
            mma16816(acc[1], a,   bh4 + 2);
            mma16816(acc[1], a,   bl4 + 2);
            mma16816(acc[1], al_, bh4 + 2);
        }
#pragma unroll
        for (int nt = 0; nt < 2; nt++)
#pragma unroll
            for (int q = 0; q < 4; q++) {
                int row = wm * 16 + lr + ((q >> 1) * 8);
                int col = wn * 16 + nt * 8 + lc + (q & 1);
                logit[row * 68 + col] = acc[nt][q];
            }
        __syncthreads();

        // ---- softmax: 4 rows per warp ----
        float l0r[4], l1r[4];
#pragma unroll
        for (int rr = 0; rr < 4; rr++) {
            int row = wid * 4 + rr;
            l0r[rr] = logit[row * 68 + lane] + cb0;
            l1r[rr] = logit[row * 68 + lane + 32] + cb1;
        }
        __syncthreads();
#pragma unroll
        for (int rr = 0; rr < 4; rr++) {
            int row = wid * 4 + rr;
            int gn = n0 + row;
            float e0 = __expf(l0r[rr]), e1 = __expf(l1r[rr]);
            float ss = e0 + e1;
#pragma unroll
            for (int off = 16; off; off >>= 1) ss += __shfl_xor_sync(0xFFFFFFFFu, ss, off);
            float inv = 1.f / ss;
            if (gn < NUM_KP) { e0 *= inv; e1 *= inv; s0 += e0; s1 += e1; }
            else             { e0 = 0.f;  e1 = 0.f; }
            __nv_bfloat16 h0 = __float2bfloat16(e0);
            __nv_bfloat16 h1 = __float2bfloat16(e1);
            *(__nv_bfloat16*)(sm + O_ACTH + lane * 144 + row * 2)        = h0;
            *(__nv_bfloat16*)(sm + O_ACTH + (lane + 32) * 144 + row * 2) = h1;
            *(__nv_bfloat16*)(sm + O_ACTL + lane * 144 + row * 2) =
                __float2bfloat16(e0 - __bfloat162float(h0));
            *(__nv_bfloat16*)(sm + O_ACTL + (lane + 32) * 144 + row * 2) =
                __float2bfloat16(e1 - __bfloat162float(h1));
        }
        __syncthreads();

        // ---- vlad GEMM: warp tile 32x32 ----
#pragma unroll
        for (int ks = 0; ks < 4; ks++) {
            int kl = ks * 16;
            uint32_t bh4[2][4], bl4[2][4];
#pragma unroll
            for (int ntp = 0; ntp < 2; ntp++) {
                uint32_t boff = (uint32_t)((wn2 * 32 + ntp * 16 + rowB_nt) * 144 + (kl + s8) * 2);
                ldm_x4(bh4[ntp], ah_s + boff);
                ldm_x4(bl4[ntp], al_s + boff);
            }
#pragma unroll
            for (int mt = 0; mt < 2; mt++) {
                uint32_t aoff = (uint32_t)((kl + rowX_n) * 528 + (wm2 * 32 + mt * 16 + s8) * 2);
                uint32_t a[4], al2[4];
                ldm_x4_t(a,   xh_s + aoff);
                ldm_x4_t(al2, xl_s + aoff);
#pragma unroll
                for (int ntp = 0; ntp < 2; ntp++) {
                    mma16816(accv[mt][2 * ntp],     a,   bh4[ntp]);
                    mma16816(accv[mt][2 * ntp],     a,   bl4[ntp]);
                    mma16816(accv[mt][2 * ntp],     al2, bh4[ntp]);
                    mma16816(accv[mt][2 * ntp + 1], a,   bh4[ntp] + 2);
                    mma16816(accv[mt][2 * ntp + 1], a,   bl4[ntp] + 2);
                    mma16816(accv[mt][2 * ntp + 1], al2, bh4[ntp] + 2);
                }
            }
        }
    }

    // ---- asum reduce; cw2 already streaming into XF ----
    red[wid * 64 + lane]      = s0;
    red[wid * 64 + lane + 32] = s1;
    CP_WAIT0();
    __syncthreads();
    if (tid < 32) {
        float t0 = 0.f, t1 = 0.f;
#pragma unroll
        for (int w = 0; w < 16; w++) { t0 += red[w * 64 + lane]; t1 += red[w * 64 + lane + 32]; }
        asums[lane] = t0; asums[lane + 32] = t1;
    }
    __syncthreads();
    const float* cw2s = xf;

#pragma unroll
    for (int mt = 0; mt < 2; mt++)
#pragma unroll
        for (int nt = 0; nt < 4; nt++)
#pragma unroll
            for (int q = 0; q < 4; q++) {
                int d = wm2 * 32 + mt * 16 + lr + ((q >> 1) * 8);
                int k = wn2 * 32 + nt * 8 + lc + (q & 1);
                accv[mt][nt][q] -= asums[k] * cw2s[d * 64 + k];
            }
#pragma unroll
    for (int nt = 0; nt < 4; nt++) {
        float sq0 = 0.f, sq1 = 0.f;
#pragma unroll
        for (int mt = 0; mt < 2; mt++) {
            sq0 += accv[mt][nt][0] * accv[mt][nt][0] + accv[mt][nt][2] * accv[mt][nt][2];
            sq1 += accv[mt][nt][1] * accv[mt][nt][1] + accv[mt][nt][3] * accv[mt][nt][3];
        }
        sq0 += __shfl_xor_sync(0xFFFFFFFFu, sq0, 4);
        sq0 += __shfl_xor_sync(0xFFFFFFFFu, sq0, 8);
        sq0 += __shfl_xor_sync(0xFFFFFFFFu, sq0, 16);
        sq1 += __shfl_xor_sync(0xFFFFFFFFu, sq1, 4);
        sq1 += __shfl_xor_sync(0xFFFFFFFFu, sq1, 8);
        sq1 += __shfl_xor_sync(0xFFFFFFFFu, sq1, 16);
        if (lr == 0) {
            int k0 = wn2 * 32 + nt * 8 + lc;
            redk[k0 * 8 + wm2]       = sq0;
            redk[(k0 + 1) * 8 + wm2] = sq1;
        }
    }
    __syncthreads();
    if (tid < 32) {
        float q0 = 0.f, q1 = 0.f;
#pragma unroll
        for (int w = 0; w < 8; w++) {
            q0 += redk[lane * 8 + w];
            q1 += redk[(lane + 32) * 8 + w];
        }
        float i0 = 1.f / (sqrtf(q0) + 1e-12f);
        float i1 = 1.f / (sqrtf(q1) + 1e-12f);
        invk[lane] = i0; invk[lane + 32] = i1;
        float tt = q0 * i0 * i0 + q1 * i1 * i1;
#pragma unroll
        for (int off = 16; off; off >>= 1) tt += __shfl_xor_sync(0xFFFFFFFFu, tt, off);
        if (lane == 0) invts[0] = 1.f / (sqrtf(tt) + 1e-12f);
    }
    __syncthreads();
    float invt = invts[0];

#pragma unroll
    for (int mt = 0; mt < 2; mt++)
#pragma unroll
        for (int nt = 0; nt < 4; nt++)
#pragma unroll
            for (int q = 0; q < 4; q += 2) {
                int d = wm2 * 32 + mt * 16 + lr + ((q >> 1) * 8);
                int k = wn2 * 32 + nt * 8 + lc;
                float va = accv[mt][nt][q]     * invk[k]     * invt;
                float vb = accv[mt][nt][q + 1] * invk[k + 1] * invt;
                uint32_t h = cvt2(vb, va);
                uint32_t l = cvt2(vb - bf_hi_f32(h), va - bf_lo_f32(h));
                *(uint32_t*)(sm + O_XH + (d * 66 + k) * 2) = h;
                *(uint32_t*)(sm + O_XL + (d * 66 + k) * 2) = l;
            }
    __syncthreads();
    for (int i = tid; i < 8192; i += NV_T) {
        int d = i >> 5, kp = i & 31;
        uint32_t vh = lds32(xh_s + (uint32_t)(d * 66 + kp * 2) * 2);
        uint32_t vl = lds32(xl_s + (uint32_t)(d * 66 + kp * 2) * 2);
        size_t go = (size_t)b * VLAD_DIM + d * 64 + kp * 2;
        *(uint32_t*)((char*)g_Ah + go * 2) = vh;
        *(uint32_t*)((char*)g_Al + go * 2) = vl;
    }
}

// ---------------------------------------------------------------------------
// Transpose + split: src[k][n] fp32 -> dh/dl[n][k] bf16 (pads zero-filled).
// ---------------------------------------------------------------------------
__global__ void __launch_bounds__(256) k_cvt_trans(
    const float* __restrict__ src, int ldsrc, int Kreal, int Nreal,
    __nv_bfloat16* __restrict__ dh, __nv_bfloat16* __restrict__ dl, int ldd)
{
    __shared__ float smt[32][33];
    int k0 = blockIdx.x * 32;
    int n0 = blockIdx.y * 32;
    int tx = threadIdx.x & 31;
    int ty = threadIdx.x >> 5;
#pragma unroll
    for (int i = 0; i < 4; i++) {
        int kk = ty + i * 8;
        int n = n0 + tx;
        float v = (k0 + kk < Kreal && n < Nreal) ? src[(size_t)(k0 + kk) * ldsrc + n] : 0.f;
        smt[kk][tx] = v;
    }
    __syncthreads();
#pragma unroll
    for (int i = 0; i < 4; i++) {
        int nn = ty + i * 8;
        float v = smt[tx][nn];
        __nv_bfloat16 h = __float2bfloat16(v);
        __nv_bfloat16 l = __float2bfloat16(v - __bfloat162float(h));
        size_t o = (size_t)(n0 + nn) * ldd + k0 + tx;
        dh[o] = h;
        dl[o] = l;
    }
}

// ---------------------------------------------------------------------------
// Split-bf16 HMMA GEMM, 512 threads (16 warps, 4x4 warp grid, 32x32 warp tile).
// ---------------------------------------------------------------------------
#define KBLK 64
#define SPITCH 72
#define SPB (SPITCH * 2)
#define TILE_B (128 * SPB)
#define STAGE_B (4 * TILE_B)
#define MMA_SMEM_TOTAL (2 * STAGE_B)
#define MMA_T 512

__global__ void __launch_bounds__(MMA_T, 1) k_mma(
    const __nv_bfloat16* __restrict__ Ah, const __nv_bfloat16* __restrict__ Al,
    const __nv_bfloat16* __restrict__ Bh, const __nv_bfloat16* __restrict__ Bl,
    int K, float* __restrict__ C, int M, int N,
    const float* __restrict__ bias, int act,
    __nv_bfloat16* __restrict__ Dh, __nv_bfloat16* __restrict__ Dl, int ldd)
{
    extern __shared__ __align__(16) char smem[];
    uint32_t sb = smem_u32(smem);
    int tid = threadIdx.x;
    int wid = tid >> 5, lane = tid & 31;
    int wm = wid & 3;          // 4 m-groups of 32
    int wn = wid >> 2;         // 4 n-groups of 32
    int m0 = blockIdx.y * 128;
    int n0 = blockIdx.x * 128;

    const __nv_bfloat16* srcs[4] = {
        Ah + (size_t)m0 * K, Al + (size_t)m0 * K,
        Bh + (size_t)n0 * K, Bl + (size_t)n0 * K };

    int l7  = lane & 7;
    int s8  = (lane & 8) ? 8 : 0;
    int s16 = (lane & 16) ? 8 : 0;

    float acc[2][4][4];
#pragma unroll
    for (int i = 0; i < 2; i++)
#pragma unroll
        for (int j = 0; j < 4; j++)
#pragma unroll
            for (int q = 0; q < 4; q++) acc[i][j][q] = 0.f;

    // stage load: 4 operand tiles x 1024 16B-chunks, 512 threads -> 2/thread/tile
    auto load_stage = [&](int s, int kb) {
        uint32_t sd = sb + s * STAGE_B;
        size_t kOff = (size_t)kb * KBLK;
#pragma unroll
        for (int v = 0; v < 4; v++) {
            const __nv_bfloat16* g = srcs[v] + kOff;
#pragma unroll
            for (int p = 0; p < 2; p++) {
                int idx = tid + p * MMA_T;     // 0..1023
                int rr = idx >> 3;             // 0..127
                int ch = idx & 7;
                uint32_t d = sd + v * TILE_B + rr * SPB + ch * 16;
                const void* sptr = (const char*)(g + (size_t)rr * K) + ch * 16;
                CP_ASYNC16(d, sptr);
            }
        }
        CP_COMMIT();
    };

    load_stage(0, 0);

    int lr = lane >> 2;
    int lc = (lane & 3) * 2;
    int nkb = K / KBLK;

    for (int kb = 0; kb < nkb; kb++) {
        int s = kb & 1;
        CP_WAIT0();
        __syncthreads();
        if (kb + 1 < nkb) load_stage(s ^ 1, kb + 1);

        uint32_t sAh = sb + s * STAGE_B;
        uint32_t sAl = sAh + TILE_B;
        uint32_t sBh = sAh + 2 * TILE_B;
        uint32_t sBl = sAh + 3 * TILE_B;

#pragma unroll
        for (int ks = 0; ks < 4; ks++) {
            int kl = ks * 16;
            uint32_t ah4[2][4], al4[2][4];
#pragma unroll
            for (int mt = 0; mt < 2; mt++) {
                uint32_t aoff = (uint32_t)((wm * 32 + mt * 16 + l7 + s8) * SPB + (kl + s16) * 2);
                ldm_x4(ah4[mt], sAh + aoff);
                ldm_x4(al4[mt], sAl + aoff);
            }
            uint32_t bh4[2][4], bl4[2][4];
#pragma unroll
            for (int ntp = 0; ntp < 2; ntp++) {
                uint32_t boff = (uint32_t)((wn * 32 + ntp * 16 + l7 + s16) * SPB + (kl + s8) * 2);
                ldm_x4(bh4[ntp], sBh + boff);
                ldm_x4(bl4[ntp], sBl + boff);
            }
#pragma unroll
            for (int mt = 0; mt < 2; mt++)
#pragma unroll
                for (int ntp = 0; ntp < 2; ntp++) {
                    mma16816(acc[mt][2 * ntp],     ah4[mt], bh4[ntp]);
                    mma16816(acc[mt][2 * ntp],     ah4[mt], bl4[ntp]);
                    mma16816(acc[mt][2 * ntp],     al4[mt], bh4[ntp]);
                    mma16816(acc[mt][2 * ntp + 1], ah4[mt], bh4[ntp] + 2);
                    mma16816(acc[mt][2 * ntp + 1], ah4[mt], bl4[ntp] + 2);
                    mma16816(acc[mt][2 * ntp + 1], al4[mt], bh4[ntp] + 2);
                }
        }
    }

    auto emit = [&](int r, int c, float v) {
        bool in = (r < M && c < N);
        float val = 0.f;
        if (in) {
            val = v + (bias ? bias[c] : 0.f);
            if (act == 1) val = fmaxf(val, 0.f);
            if (C) C[(size_t)r * N + c] = val;
        }
        if (Dh) {
            __nv_bfloat16 h = __float2bfloat16(val);
            Dh[(size_t)r * ldd + c] = h;
            Dl[(size_t)r * ldd + c] = __float2bfloat16(val - __bfloat162float(h));
        }
    };
#pragma unroll
    for (int mt = 0; mt < 2; mt++) {
#pragma unroll
        for (int nt = 0; nt < 4; nt++) {
            int r = m0 + wm * 32 + mt * 16 + lr;
            int c = n0 + wn * 32 + nt * 8 + lc;
            emit(r,     c,     acc[mt][nt][0]);
            emit(r,     c + 1, acc[mt][nt][1]);
            emit(r + 8, c,     acc[mt][nt][2]);
            emit(r + 8, c + 1, acc[mt][nt][3]);
        }
    }
}

// ---------------------------------------------------------------------------
// GAT kernels (R12-measured path; gat_fin of layers 0/1 folded into k_gat_h2).
// ---------------------------------------------------------------------------
__device__ __forceinline__ void gat_h_core(
    float xv, int b, int t,
    const float* __restrict__ W, const float* __restrict__ a_s,
    const float* __restrict__ a_d, float* xsm, float* rs)
{
    xsm[t] = xv;
    g_aggr[b * NODE_D + t] = 0.f;
    if (t == 0) g_den[b] = 0.f;
    __syncthreads();
    float acc = 0.f;
#pragma unroll 8
    for (int d = 0; d < NODE_D; d++) acc = fmaf(xsm[d], __ldg(&W[d * NODE_D + t]), acc);
    g_h[b * NODE_D + t] = acc;
    float ps = acc * __ldg(&a_s[t]);
    float pd = acc * __ldg(&a_d[t]);
#pragma unroll
    for (int off = 16; off; off >>= 1) {
        ps += __shfl_xor_sync(0xFFFFFFFFu, ps, off);
        pd += __shfl_xor_sync(0xFFFFFFFFu, pd, off);
    }
    if ((t & 31) == 0) { rs[t >> 5] = ps; rs[4 + (t >> 5)] = pd; }
    __syncthreads();
    if (t == 0) g_es[b] = rs[0] + rs[1] + rs[2] + rs[3];
    if (t == 1) g_ed[b] = rs[4] + rs[5] + rs[6] + rs[7];
}

__global__ void __launch_bounds__(128) k_gat_h(
    const float* __restrict__ W, const float* __restrict__ a_s,
    const float* __restrict__ a_d)
{
    int b = blockIdx.x, t = threadIdx.x;
    __shared__ float xsm[NODE_D];
    __shared__ float rs[8];
    gat_h_core(g_x[b * NODE_D + t], b, t, W, a_s, a_d, xsm, rs);
}

__global__ void __launch_bounds__(128) k_gat_h2(
    const float* __restrict__ W, const float* __restrict__ a_s,
    const float* __restrict__ a_d, const float* __restrict__ bprev)
{
    int b = blockIdx.x, t = threadIdx.x;
    __shared__ float xsm[NODE_D];
    __shared__ float rs[8];
    float v = g_aggr[b * NODE_D + t] + __ldg(&bprev[t]);
    v = (v > 0.f) ? v : (__expf(v) - 1.f);
    gat_h_core(v, b, t, W, a_s, a_d, xsm, rs);
}

__global__ void k_edge12(const int* __restrict__ ei)
{
    int e = blockIdx.x * blockDim.x + threadIdx.x;
    if (e >= E_EXT) return;
    int s, d;
    if (e < N_EDGES) { s = ei[e]; d = ei[N_EDGES + e]; }
    else { s = e - N_EDGES; d = s; }
    float v = g_es[s] + g_ed[d];
    v = (v > 0.f) ? v : 0.2f * v;
    float ex = __expf(v);
    g_ex[e] = ex;
    atomicAdd(&g_den[d], ex);
}

__global__ void k_edge3(const int* __restrict__ ei)
{
    int gt = blockIdx.x * blockDim.x + threadIdx.x;
    int w = gt >> 5, lane = gt & 31;
    if (w >= E_EXT) return;
    int s, d;
    if (w < N_EDGES) { s = ei[w]; d = ei[N_EDGES + w]; }
    else { s = w - N_EDGES; d = s; }
    float alpha = g_ex[w] / g_den[d];
#pragma unroll
    for (int i = 0; i < 4; i++) {
        int c = lane + 32 * i;
        atomicAdd(&g_aggr[d * NODE_D + c], g_h[s * NODE_D + c] * alpha);
    }
}

__global__ void k_gat_fin(const float* __restrict__ b)
{
    int i = blockIdx.x * blockDim.x + threadIdx.x;
    if (i >= N_NODES * NODE_D) return;
    float v = g_aggr[i] + __ldg(&b[i & (NODE_D - 1)]);
    g_x[i] = (v > 0.f) ? v : (__expf(v) - 1.f);
}

// ---------------------------------------------------------------------------
// Edge-attr MLP: 1 -> 8 -> 16 -> 32 (unchanged)
// ---------------------------------------------------------------------------
__global__ void __launch_bounds__(256) k_ef(
    const float* __restrict__ ea,
    const float* __restrict__ w1, const float* __restrict__ b1,
    const float* __restrict__ w2, const float* __restrict__ b2,
    const float* __restrict__ w3, const float* __restrict__ b3)
{
    __shared__ float w1s[8], b1s[8], w2s[128], b2s[16], w3s[512], b3s[32];
    int t = threadIdx.x;
    if (t < 8)   { w1s[t] = w1[t]; b1s[t] = b1[t]; }
    if (t < 128) w2s[t] = w2[t];
    if (t < 16)  b2s[t] = b2[t];
    if (t < 32)  b3s[t] = b3[t];
    for (int i = t; i < 512; i += blockDim.x) w3s[i] = w3[i];
    __syncthreads();
    int e = blockIdx.x * blockDim.x + t;
    if (e >= N_EDGES) return;
    float a = ea[e];
    float t8[8];
#pragma unroll
    for (int j = 0; j < 8; j++) t8[j] = fmaxf(fmaf(a, w1s[j], b1s[j]), 0.f);
    float t16[16];
#pragma unroll
    for (int c = 0; c < 16; c++) {
        float acc = b2s[c];
#pragma unroll
        for (int j = 0; j < 8; j++) acc = fmaf(t8[j], w2s[j * 16 + c], acc);
        t16[c] = fmaxf(acc, 0.f);
    }
#pragma unroll
    for (int c = 0; c < 32; c++) {
        float acc = b3s[c];
#pragma unroll
        for (int j = 0; j < 16; j++) acc = fmaf(t16[j], w3s[j * 32 + c], acc);
        g_ef2[e * EDGE_D + c] = acc;
    }
}

// ---------------------------------------------------------------------------
// Final fused edge classifier (unchanged).
// ---------------------------------------------------------------------------
__global__ void __launch_bounds__(256) k_final(
    const int* __restrict__ ei,
    const float* __restrict__ dp_w, const float* __restrict__ dp_b,
    const float* __restrict__ ec_w1, const float* __restrict__ ec_b1,
    const float* __restrict__ ec_w2, const float* __restrict__ ec_b2,
    float* __restrict__ out)
{
    __shared__ float dpw_s[288 * 32];
    __shared__ float ecw1_s[32 * 16];
    __shared__ float dpb_s[32];
    __shared__ float ecb1_s[16];
    __shared__ float ecw2_s[16];
    __shared__ float vec_s[8][292];
    __shared__ float o32_s[8][32];

    int tid = threadIdx.x;
    for (int i = tid; i < 288 * 32; i += 256) dpw_s[i] = dp_w[i];
    for (int i = tid; i < 512; i += 256) ecw1_s[i] = ec_w1[i];
    if (tid < 32) dpb_s[tid] = dp_b[tid];
    if (tid < 16) { ecb1_s[tid] = ec_b1[tid]; ecw2_s[tid] = ec_w2[tid]; }
    __syncthreads();

    float b2 = __ldg(ec_b2);
    int warp = tid >> 5, lane = tid & 31;
    int gw = blockIdx.x * 8 + warp;
    int nw = gridDim.x * 8;

    for (int e = gw; e < N_EDGES; e += nw) {
        int s = ei[e], d = ei[N_EDGES + e];
        const float* xsp = g_x + s * NODE_D;
        const float* xdp = g_x + d * NODE_D;
#pragma unroll
        for (int i = 0; i < 4; i++) {
            vec_s[warp][lane + 32 * i]       = xsp[lane + 32 * i];
            vec_s[warp][128 + lane + 32 * i] = xdp[lane + 32 * i];
        }
        vec_s[warp][256 + lane] = g_ef2[e * EDGE_D + lane];
        __syncwarp();

        float acc = dpb_s[lane];
#pragma unroll 4
        for (int i = 0; i < 288; i++) acc = fmaf(vec_s[warp][i], dpw_s[i * 32 + lane], acc);
        o32_s[warp][lane] = acc;
        __syncwarp();

        float hh = 0.f;
        if (lane < 16) {
            hh = ecb1_s[lane];
#pragma unroll 4
            for (int j = 0; j < 32; j++) hh = fmaf(o32_s[warp][j], ecw1_s[j * 16 + lane], hh);
            hh = fmaxf(hh, 0.f) * ecw2_s[lane];
        }
#pragma unroll
        for (int off = 8; off; off >>= 1) hh += __shfl_xor_sync(0xFFFFFFFFu, hh, off);
        if (lane == 0) out[e] = 1.f / (1.f + __expf(-(hh + b2)));
        __syncwarp();
    }
}

// ---------------------------------------------------------------------------
extern "C" void kernel_launch(void* const* d_in, const int* in_sizes, int n_in,
                              void* d_out, int out_size)
{
    (void)in_sizes; (void)n_in; (void)out_size;
    const float* node_feats = (const float*)d_in[0];
    const float* edge_attr  = (const float*)d_in[1];
    const float* nv_cw      = (const float*)d_in[2];
    const float* nv_cb      = (const float*)d_in[3];
    const float* nv_cw2     = (const float*)d_in[4];
    const float* nv_hw      = (const float*)d_in[5];
    const float* ne_w1      = (const float*)d_in[6];
    const float* ne_b1      = (const float*)d_in[7];
    const float* ne_w2      = (const float*)d_in[8];
    const float* ne_b2      = (const float*)d_in[9];
    const float* ee_w1      = (const float*)d_in[10];
    const float* ee_b1      = (const float*)d_in[11];
    const float* ee_w2      = (const float*)d_in[12];
    const float* ee_b2      = (const float*)d_in[13];
    const float* ee_w3      = (const float*)d_in[14];
    const float* ee_b3      = (const float*)d_in[15];
    const float* gat_w      = (const float*)d_in[16];
    const float* gat_as     = (const float*)d_in[17];
    const float* gat_ad     = (const float*)d_in[18];
    const float* gat_b      = (const float*)d_in[19];
    const float* dp_w       = (const float*)d_in[20];
    const float* dp_b       = (const float*)d_in[21];
    const float* ec_w1      = (const float*)d_in[22];
    const float* ec_b1      = (const float*)d_in[23];
    const float* ec_w2      = (const float*)d_in[24];
    const float* ec_b2      = (const float*)d_in[25];
    const int*   edge_index = (const int*)d_in[26];
    float* out = (float*)d_out;

    float* p_x;
    __nv_bfloat16 *p_Ah, *p_Al, *p_Bh, *p_Bl;
    __nv_bfloat16 *p_Ah2, *p_Al2, *p_Bh2, *p_Bl2;
    __nv_bfloat16 *p_Ah3, *p_Al3, *p_Bh3, *p_Bl3;
    cudaGetSymbolAddress((void**)&p_x, g_x);
    cudaGetSymbolAddress((void**)&p_Ah, g_Ah);
    cudaGetSymbolAddress((void**)&p_Al, g_Al);
    cudaGetSymbolAddress((void**)&p_Bh, g_Bh);
    cudaGetSymbolAddress((void**)&p_Bl, g_Bl);
    cudaGetSymbolAddress((void**)&p_Ah2, g_Ah2);
    cudaGetSymbolAddress((void**)&p_Al2, g_Al2);
    cudaGetSymbolAddress((void**)&p_Bh2, g_Bh2);
    cudaGetSymbolAddress((void**)&p_Bl2, g_Bl2);
    cudaGetSymbolAddress((void**)&p_Ah3, g_Ah3);
    cudaGetSymbolAddress((void**)&p_Al3, g_Al3);
    cudaGetSymbolAddress((void**)&p_Bh3, g_Bh3);
    cudaGetSymbolAddress((void**)&p_Bl3, g_Bl3);

    static int s_init = 0;
    static cudaStream_t s2;
    static cudaEvent_t ev1, ev2;
    if (!s_init) {
        cudaFuncSetAttribute(k_mma, cudaFuncAttributeMaxDynamicSharedMemorySize, MMA_SMEM_TOTAL);
        cudaFuncSetAttribute(k_nv, cudaFuncAttributeMaxDynamicSharedMemorySize, NV_SMEM);
        cudaStreamCreateWithFlags(&s2, cudaStreamNonBlocking);
        cudaEventCreateWithFlags(&ev1, cudaEventDisableTiming);
        cudaEventCreateWithFlags(&ev2, cudaEventDisableTiming);
        s_init = 1;
    }

    // fork: B conversions + edge MLP run concurrently with NetVLAD
    cudaEventRecord(ev1, 0);
    cudaStreamWaitEvent(s2, ev1, 0);
    {
        dim3 g(VLAD_DIM / 32, N_PAD / 32);
        k_cvt_trans<<<g, 256, 0, s2>>>(nv_hw, H0D, VLAD_DIM, H0D, p_Bh, p_Bl, VLAD_DIM);
    }
    {
        dim3 g(K2PAD / 32, N2PAD / 32);
        k_cvt_trans<<<g, 256, 0, s2>>>(ne_w1, H1D, H0D, H1D, p_Bh2, p_Bl2, K2PAD);
    }
    {
        dim3 g(K3PAD / 32, N3PAD / 32);
        k_cvt_trans<<<g, 256, 0, s2>>>(ne_w2, NODE_D, H1D, NODE_D, p_Bh3, p_Bl3, K3PAD);
    }
    k_ef<<<(N_EDGES + 255) / 256, 256, 0, s2>>>(edge_attr, ee_w1, ee_b1, ee_w2, ee_b2,
                                                ee_w3, ee_b3);
    cudaEventRecord(ev2, s2);

    // main stream: NetVLAD (512 threads)
    k_prep_cw<<<64, 256>>>(nv_cw);
    k_nv<<<N_NODES, NV_T, NV_SMEM>>>(node_feats, nv_cb, nv_cw2);

    // join before G1
    cudaStreamWaitEvent(0, ev2, 0);

    // G1 HMMA: h0 = vlad @ hw -> split-bf16 A operand of G2
    {
        dim3 g(N_PAD / 128, M_PAD / 128);
        k_mma<<<g, MMA_T, MMA_SMEM_TOTAL>>>(p_Ah, p_Al, p_Bh, p_Bl, VLAD_DIM,
                                            nullptr, N_NODES, H0D, nullptr, 0,
                                            p_Ah2, p_Al2, K2PAD);
    }
    // G2 HMMA: h1 = relu(h0 @ ne_w1 + b1) -> split-bf16 A operand of G3
    {
        dim3 g(N2PAD / 128, M_PAD / 128);
        k_mma<<<g, MMA_T, MMA_SMEM_TOTAL>>>(p_Ah2, p_Al2, p_Bh2, p_Bl2, K2PAD,
                                            nullptr, N_NODES, H1D, ne_b1, 1,
                                            p_Ah3, p_Al3, K3PAD);
    }
    // G3 HMMA: x = h1 @ ne_w2 + b2
    {
        dim3 g(1, M_PAD / 128);
        k_mma<<<g, MMA_T, MMA_SMEM_TOTAL>>>(p_Ah3, p_Al3, p_Bh3, p_Bl3, K3PAD,
                                            p_x, N_NODES, NODE_D, ne_b2, 0,
                                            nullptr, nullptr, 0);
    }

    // 3 GAT layers; elu+bias of layers 0/1 folded into the next k_gat_h2
    for (int l = 0; l < DEPTH; l++) {
        if (l == 0)
            k_gat_h<<<N_NODES, 128>>>(gat_w, gat_as, gat_ad);
        else
            k_gat_h2<<<N_NODES, 128>>>(gat_w + l * NODE_D * NODE_D,
                                       gat_as + l * NODE_D, gat_ad + l * NODE_D,
                                       gat_b + (l - 1) * NODE_D);
        k_edge12<<<(E_EXT + 255) / 256, 256>>>(edge_index);
        k_edge3<<<((E_EXT * 32) + 255) / 256, 256>>>(edge_index);
    }
    k_gat_fin<<<(N_NODES * NODE_D + 255) / 256, 256>>>(gat_b + 2 * NODE_D);

    // fused edge classifier -> out
    k_final<<<256, 256>>>(edge_index, dp_w, dp_b, ec_w1, ec_b1, ec_w2, ec_b2, out);
}